// round 3
// baseline (speedup 1.0000x reference)
#include <cuda_runtime.h>
#include <cstdint>

// ---------------------------------------------------------------------------
// R-NEM cell, fully fused fp32 SIMT pipeline.
//   K=8, FC=256, LAST=128, B=2048, M=1024, H=512
//   rows1 = B*K = 16384, rows2 = B*K*(K-1) = 114688
// ---------------------------------------------------------------------------

#define FCN   256
#define LASTN 128
#define HDIM  512
#define MDIM  1024
#define NR1   16384
#define NR2   114688
#define BKT   16

// scratch (device globals; allocation in kernel_launch is forbidden)
__device__ float g_s1[NR1 * FCN];      // 16 MB
__device__ float g_core[NR2 * FCN];    // 117 MB
__device__ float g_eff[NR1 * FCN];     // 16 MB

// ---------------------------------------------------------------------------
// Kernel 1: s1 = relu(LN(state @ enc_w + enc_b))      [16384 x 256], K=512
// tile: 128 rows x 256 cols, 512 threads (32x16), 8x8 per thread
// ---------------------------------------------------------------------------
__global__ __launch_bounds__(512, 1) void k_enc(
    const float* __restrict__ state, const float* __restrict__ W,
    const float* __restrict__ bias, const float* __restrict__ gam,
    const float* __restrict__ bet)
{
    __shared__ float As[BKT][132];
    __shared__ float Bs[BKT][FCN];
    const int x = threadIdx.x, y = threadIdx.y;
    const int tid = y * 32 + x;
    const int R0 = blockIdx.x * 128;
    const int lk = tid & 15, lr = tid >> 4;

    float acc[8][8];
#pragma unroll
    for (int r = 0; r < 8; r++)
#pragma unroll
        for (int c = 0; c < 8; c++) acc[r][c] = 0.f;

    for (int kt = 0; kt < HDIM; kt += BKT) {
#pragma unroll
        for (int p = 0; p < 4; p++)
            As[lk][lr + 32 * p] = state[(size_t)(R0 + lr + 32 * p) * HDIM + kt + lk];
#pragma unroll
        for (int p = 0; p < 2; p++) {
            int idx = tid + 512 * p;
            int kk = idx >> 6, n4 = idx & 63;
            *(float4*)&Bs[kk][n4 * 4] =
                *(const float4*)&W[(size_t)(kt + kk) * FCN + n4 * 4];
        }
        __syncthreads();
#pragma unroll
        for (int kk = 0; kk < BKT; kk++) {
            float a[8];
            float4 a0 = *(const float4*)&As[kk][y * 8];
            float4 a1 = *(const float4*)&As[kk][y * 8 + 4];
            a[0]=a0.x; a[1]=a0.y; a[2]=a0.z; a[3]=a0.w;
            a[4]=a1.x; a[5]=a1.y; a[6]=a1.z; a[7]=a1.w;
            float b[8];
#pragma unroll
            for (int c = 0; c < 8; c++) b[c] = Bs[kk][x + 32 * c];
#pragma unroll
            for (int r = 0; r < 8; r++)
#pragma unroll
                for (int c = 0; c < 8; c++) acc[r][c] += a[r] * b[c];
        }
        __syncthreads();
    }

    float bi[8], ga[8], be[8];
#pragma unroll
    for (int c = 0; c < 8; c++) {
        int col = x + 32 * c;
        bi[c] = bias[col]; ga[c] = gam[col]; be[c] = bet[col];
    }
#pragma unroll
    for (int r = 0; r < 8; r++) {
        int row = R0 + y * 8 + r;
        float v[8], s = 0.f, s2 = 0.f;
#pragma unroll
        for (int c = 0; c < 8; c++) { v[c] = acc[r][c] + bi[c]; s += v[c]; s2 += v[c] * v[c]; }
#pragma unroll
        for (int o = 16; o; o >>= 1) {
            s  += __shfl_xor_sync(0xffffffffu, s,  o);
            s2 += __shfl_xor_sync(0xffffffffu, s2, o);
        }
        float mu = s * (1.f / FCN);
        float var = s2 * (1.f / FCN) - mu * mu;
        float rs = rsqrtf(var + 1e-5f);
#pragma unroll
        for (int c = 0; c < 8; c++) {
            float o2 = (v[c] - mu) * rs * ga[c] + be[c];
            g_s1[(size_t)row * FCN + x + 32 * c] = fmaxf(o2, 0.f);
        }
    }
}

// ---------------------------------------------------------------------------
// Kernel 2: core = relu(LN(concat(s1[p], s1[q]) @ core_w + b))  [114688x256], K=512
// A never materialized: virtual row v -> p = v/7 (focus), q = peer row.
// ---------------------------------------------------------------------------
__global__ __launch_bounds__(512, 1) void k_core(
    const float* __restrict__ W, const float* __restrict__ bias,
    const float* __restrict__ gam, const float* __restrict__ bet)
{
    __shared__ float As[BKT][132];
    __shared__ float Bs[BKT][FCN];
    const int x = threadIdx.x, y = threadIdx.y;
    const int tid = y * 32 + x;
    const int R0 = blockIdx.x * 128;
    const int lk = tid & 15, lr = tid >> 4;

    int prow[4], qrow[4];
#pragma unroll
    for (int p = 0; p < 4; p++) {
        int v = R0 + lr + 32 * p;
        int pr = v / 7;
        int jj = v - pr * 7;
        int i = pr & 7;
        int j = jj + (jj >= i ? 1 : 0);
        prow[p] = pr;
        qrow[p] = (pr & ~7) + j;
    }

    float acc[8][8];
#pragma unroll
    for (int r = 0; r < 8; r++)
#pragma unroll
        for (int c = 0; c < 8; c++) acc[r][c] = 0.f;

    for (int kt = 0; kt < 2 * FCN; kt += BKT) {
        const bool first = kt < FCN;
        const int kc = first ? (kt + lk) : (kt + lk - FCN);
#pragma unroll
        for (int p = 0; p < 4; p++) {
            int src = first ? prow[p] : qrow[p];
            As[lk][lr + 32 * p] = g_s1[(size_t)src * FCN + kc];
        }
#pragma unroll
        for (int p = 0; p < 2; p++) {
            int idx = tid + 512 * p;
            int kk = idx >> 6, n4 = idx & 63;
            *(float4*)&Bs[kk][n4 * 4] =
                *(const float4*)&W[(size_t)(kt + kk) * FCN + n4 * 4];
        }
        __syncthreads();
#pragma unroll
        for (int kk = 0; kk < BKT; kk++) {
            float a[8];
            float4 a0 = *(const float4*)&As[kk][y * 8];
            float4 a1 = *(const float4*)&As[kk][y * 8 + 4];
            a[0]=a0.x; a[1]=a0.y; a[2]=a0.z; a[3]=a0.w;
            a[4]=a1.x; a[5]=a1.y; a[6]=a1.z; a[7]=a1.w;
            float b[8];
#pragma unroll
            for (int c = 0; c < 8; c++) b[c] = Bs[kk][x + 32 * c];
#pragma unroll
            for (int r = 0; r < 8; r++)
#pragma unroll
                for (int c = 0; c < 8; c++) acc[r][c] += a[r] * b[c];
        }
        __syncthreads();
    }

    float bi[8], ga[8], be[8];
#pragma unroll
    for (int c = 0; c < 8; c++) {
        int col = x + 32 * c;
        bi[c] = bias[col]; ga[c] = gam[col]; be[c] = bet[col];
    }
#pragma unroll
    for (int r = 0; r < 8; r++) {
        int row = R0 + y * 8 + r;
        float v[8], s = 0.f, s2 = 0.f;
#pragma unroll
        for (int c = 0; c < 8; c++) { v[c] = acc[r][c] + bi[c]; s += v[c]; s2 += v[c] * v[c]; }
#pragma unroll
        for (int o = 16; o; o >>= 1) {
            s  += __shfl_xor_sync(0xffffffffu, s,  o);
            s2 += __shfl_xor_sync(0xffffffffu, s2, o);
        }
        float mu = s * (1.f / FCN);
        float var = s2 * (1.f / FCN) - mu * mu;
        float rs = rsqrtf(var + 1e-5f);
#pragma unroll
        for (int c = 0; c < 8; c++) {
            float o2 = (v[c] - mu) * rs * ga[c] + be[c];
            g_core[(size_t)row * FCN + x + 32 * c] = fmaxf(o2, 0.f);
        }
    }
}

// ---------------------------------------------------------------------------
// Kernel 3: fused ctx + attention + effect reduction.
//   ctx  = relu(LN(core @ ctx_w + b))       (never materialized)
//   att  = sigmoid(tanh(LN(core @ att1_w + b)) @ att2_w + att2_b)
//   eff[v/7] += att * ctx                   (7 rows per group, in-block)
// tile: 56 virtual rows (= 8 effect groups), 448 threads (32x14), 4x(8+4)/thread
// ---------------------------------------------------------------------------
__global__ __launch_bounds__(448, 1) void k_eff(
    const float* __restrict__ ctxW, const float* __restrict__ ctx_b,
    const float* __restrict__ ctx_g, const float* __restrict__ ctx_bb,
    const float* __restrict__ a1W,  const float* __restrict__ a1_b,
    const float* __restrict__ att_g, const float* __restrict__ att_bb,
    const float* __restrict__ a2W,  const float* __restrict__ a2_b)
{
    __shared__ float As[BKT][60];
    __shared__ float Bc[BKT][FCN];
    __shared__ float Ba[BKT][LASTN];
    __shared__ float s_eff[8][FCN];
    const int x = threadIdx.x, y = threadIdx.y;
    const int tid = y * 32 + x;
    const int R0 = blockIdx.x * 56;
    const int lk = tid & 15, lr = tid >> 4;

    for (int idx = tid; idx < 8 * FCN; idx += 448) ((float*)s_eff)[idx] = 0.f;

    float ac[4][8], aa[4][4];
#pragma unroll
    for (int r = 0; r < 4; r++) {
#pragma unroll
        for (int c = 0; c < 8; c++) ac[r][c] = 0.f;
#pragma unroll
        for (int c = 0; c < 4; c++) aa[r][c] = 0.f;
    }

    for (int kt = 0; kt < FCN; kt += BKT) {
#pragma unroll
        for (int p = 0; p < 2; p++)
            As[lk][lr + 28 * p] = g_core[(size_t)(R0 + lr + 28 * p) * FCN + kt + lk];
        for (int idx = tid; idx < BKT * FCN / 4; idx += 448) {
            int kk = idx >> 6, n4 = idx & 63;
            *(float4*)&Bc[kk][n4 * 4] =
                *(const float4*)&ctxW[(size_t)(kt + kk) * FCN + n4 * 4];
        }
        for (int idx = tid; idx < BKT * LASTN / 4; idx += 448) {
            int kk = idx >> 5, n4 = idx & 31;
            *(float4*)&Ba[kk][n4 * 4] =
                *(const float4*)&a1W[(size_t)(kt + kk) * LASTN + n4 * 4];
        }
        __syncthreads();
#pragma unroll
        for (int kk = 0; kk < BKT; kk++) {
            float4 av = *(const float4*)&As[kk][y * 4];
            float a[4] = {av.x, av.y, av.z, av.w};
            float bc[8], ba[4];
#pragma unroll
            for (int c = 0; c < 8; c++) bc[c] = Bc[kk][x + 32 * c];
#pragma unroll
            for (int c = 0; c < 4; c++) ba[c] = Ba[kk][x + 32 * c];
#pragma unroll
            for (int r = 0; r < 4; r++) {
#pragma unroll
                for (int c = 0; c < 8; c++) ac[r][c] += a[r] * bc[c];
#pragma unroll
                for (int c = 0; c < 4; c++) aa[r][c] += a[r] * ba[c];
            }
        }
        __syncthreads();
    }

    float cb[8], cg[8], cbb[8];
#pragma unroll
    for (int c = 0; c < 8; c++) {
        int col = x + 32 * c;
        cb[c] = ctx_b[col]; cg[c] = ctx_g[col]; cbb[c] = ctx_bb[col];
    }
    float ab[4], ag[4], abb[4], aw[4];
#pragma unroll
    for (int c = 0; c < 4; c++) {
        int col = x + 32 * c;
        ab[c] = a1_b[col]; ag[c] = att_g[col]; abb[c] = att_bb[col]; aw[c] = a2W[col];
    }
    const float a2b = a2_b[0];

#pragma unroll
    for (int r = 0; r < 4; r++) {
        int lrow = y * 4 + r;
        // ctx LN + relu
        float v[8], s = 0.f, s2 = 0.f;
#pragma unroll
        for (int c = 0; c < 8; c++) { v[c] = ac[r][c] + cb[c]; s += v[c]; s2 += v[c] * v[c]; }
#pragma unroll
        for (int o = 16; o; o >>= 1) {
            s  += __shfl_xor_sync(0xffffffffu, s,  o);
            s2 += __shfl_xor_sync(0xffffffffu, s2, o);
        }
        float mu = s * (1.f / FCN);
        float rs = rsqrtf(s2 * (1.f / FCN) - mu * mu + 1e-5f);
        float cv[8];
#pragma unroll
        for (int c = 0; c < 8; c++)
            cv[c] = fmaxf((v[c] - mu) * rs * cg[c] + cbb[c], 0.f);

        // attention LN (over 128) + tanh + dot(att2_w) + sigmoid
        float w[4], t = 0.f, t2 = 0.f;
#pragma unroll
        for (int c = 0; c < 4; c++) { w[c] = aa[r][c] + ab[c]; t += w[c]; t2 += w[c] * w[c]; }
#pragma unroll
        for (int o = 16; o; o >>= 1) {
            t  += __shfl_xor_sync(0xffffffffu, t,  o);
            t2 += __shfl_xor_sync(0xffffffffu, t2, o);
        }
        float mua = t * (1.f / LASTN);
        float rsa = rsqrtf(t2 * (1.f / LASTN) - mua * mua + 1e-5f);
        float dot = 0.f;
#pragma unroll
        for (int c = 0; c < 4; c++) {
            float h = tanhf((w[c] - mua) * rsa * ag[c] + abb[c]);
            dot += h * aw[c];
        }
#pragma unroll
        for (int o = 16; o; o >>= 1) dot += __shfl_xor_sync(0xffffffffu, dot, o);
        float att = 1.f / (1.f + expf(-(dot + a2b)));

        int g = lrow / 7;   // 56-row tile = 8 whole groups of 7
#pragma unroll
        for (int c = 0; c < 8; c++)
            atomicAdd(&s_eff[g][x + 32 * c], att * cv[c]);
    }
    __syncthreads();
    for (int idx = tid; idx < 8 * FCN; idx += 448) {
        int gg = idx >> 8, col = idx & 255;
        g_eff[(size_t)(blockIdx.x * 8 + gg) * FCN + col] = s_eff[gg][col];
    }
}

// ---------------------------------------------------------------------------
// Kernel 4: new_state = concat(s1, effect, x) @ out_w + out_b   [16384x256], K=1536
// A gathered from three sources per k-segment; writes both output copies.
// ---------------------------------------------------------------------------
__global__ __launch_bounds__(512, 1) void k_out(
    const float* __restrict__ xin, const float* __restrict__ W,
    const float* __restrict__ bias, float* __restrict__ out, int dup)
{
    __shared__ float As[BKT][132];
    __shared__ float Bs[BKT][FCN];
    const int x = threadIdx.x, y = threadIdx.y;
    const int tid = y * 32 + x;
    const int R0 = blockIdx.x * 128;
    const int lk = tid & 15, lr = tid >> 4;

    float acc[8][8];
#pragma unroll
    for (int r = 0; r < 8; r++)
#pragma unroll
        for (int c = 0; c < 8; c++) acc[r][c] = 0.f;

    for (int kt = 0; kt < 2 * FCN + MDIM; kt += BKT) {
        const int kc = kt + lk;
#pragma unroll
        for (int p = 0; p < 4; p++) {
            int row = R0 + lr + 32 * p;
            float vv;
            if (kc < FCN)          vv = g_s1[(size_t)row * FCN + kc];
            else if (kc < 2 * FCN) vv = g_eff[(size_t)row * FCN + kc - FCN];
            else                   vv = xin[(size_t)row * MDIM + kc - 2 * FCN];
            As[lk][lr + 32 * p] = vv;
        }
#pragma unroll
        for (int p = 0; p < 2; p++) {
            int idx = tid + 512 * p;
            int kk = idx >> 6, n4 = idx & 63;
            *(float4*)&Bs[kk][n4 * 4] =
                *(const float4*)&W[(size_t)(kt + kk) * FCN + n4 * 4];
        }
        __syncthreads();
#pragma unroll
        for (int kk = 0; kk < BKT; kk++) {
            float a[8];
            float4 a0 = *(const float4*)&As[kk][y * 8];
            float4 a1 = *(const float4*)&As[kk][y * 8 + 4];
            a[0]=a0.x; a[1]=a0.y; a[2]=a0.z; a[3]=a0.w;
            a[4]=a1.x; a[5]=a1.y; a[6]=a1.z; a[7]=a1.w;
            float b[8];
#pragma unroll
            for (int c = 0; c < 8; c++) b[c] = Bs[kk][x + 32 * c];
#pragma unroll
            for (int r = 0; r < 8; r++)
#pragma unroll
                for (int c = 0; c < 8; c++) acc[r][c] += a[r] * b[c];
        }
        __syncthreads();
    }

    float bi[8];
#pragma unroll
    for (int c = 0; c < 8; c++) bi[c] = bias[x + 32 * c];
#pragma unroll
    for (int r = 0; r < 8; r++) {
        int row = R0 + y * 8 + r;
#pragma unroll
        for (int c = 0; c < 8; c++) {
            float o2 = acc[r][c] + bi[c];
            size_t off = (size_t)row * FCN + x + 32 * c;
            out[off] = o2;
            if (dup) out[(size_t)NR1 * FCN + off] = o2;
        }
    }
}

// ---------------------------------------------------------------------------
extern "C" void kernel_launch(void* const* d_in, const int* in_sizes, int n_in,
                              void* d_out, int out_size) {
    const float* x      = (const float*)d_in[0];
    const float* state  = (const float*)d_in[1];
    const float* enc_w  = (const float*)d_in[2];
    const float* enc_b  = (const float*)d_in[3];
    const float* enc_g  = (const float*)d_in[4];
    const float* enc_bb = (const float*)d_in[5];
    const float* core_w = (const float*)d_in[6];
    const float* core_b = (const float*)d_in[7];
    const float* core_g = (const float*)d_in[8];
    const float* core_bb= (const float*)d_in[9];
    const float* ctx_w  = (const float*)d_in[10];
    const float* ctx_b  = (const float*)d_in[11];
    const float* ctx_g  = (const float*)d_in[12];
    const float* ctx_bb = (const float*)d_in[13];
    const float* att1_w = (const float*)d_in[14];
    const float* att1_b = (const float*)d_in[15];
    const float* att_g  = (const float*)d_in[16];
    const float* att_bb = (const float*)d_in[17];
    const float* att2_w = (const float*)d_in[18];
    const float* att2_b = (const float*)d_in[19];
    const float* out_w  = (const float*)d_in[20];
    const float* out_b  = (const float*)d_in[21];
    float* out = (float*)d_out;
    int dup = (out_size >= 2 * NR1 * FCN) ? 1 : 0;

    k_enc <<<NR1 / 128, dim3(32, 16)>>>(state, enc_w, enc_b, enc_g, enc_bb);
    k_core<<<NR2 / 128, dim3(32, 16)>>>(core_w, core_b, core_g, core_bb);
    k_eff <<<NR2 / 56,  dim3(32, 14)>>>(ctx_w, ctx_b, ctx_g, ctx_bb,
                                        att1_w, att1_b, att_g, att_bb,
                                        att2_w, att2_b);
    k_out <<<NR1 / 128, dim3(32, 16)>>>(x, out_w, out_b, out, dup);
}

// round 4
// speedup vs baseline: 2.8048x; 2.8048x over previous
#include <cuda_runtime.h>
#include <cstdint>
#include <math.h>

// ---------------------------------------------------------------------------
// R-NEM cell, tf32 tensor-core pipeline with core-GEMM factorization.
//   K=8, FC=256, LAST=128, B=2048, M=1024, H=512
//   rows1 = 16384, rows2 = 114688
// Factorization: core_pre[v] = U[p] + V[q] + core_b, where [U|V] = s1 @ core_w
// ---------------------------------------------------------------------------

#define FCN   256
#define LASTN 128
#define HDIM  512
#define MDIM  1024
#define NR1   16384
#define NR2   114688

__device__ float g_s1[NR1 * FCN];        // 16 MB
__device__ float g_uv[NR1 * 2 * FCN];    // 32 MB : [U | V]
__device__ float g_eff[NR1 * FCN];       // 16 MB

// -------------------------------- helpers ---------------------------------
__device__ __forceinline__ float to_tf32(float x) {
    unsigned u; asm("cvt.rna.tf32.f32 %0, %1;" : "=r"(u) : "f"(x));
    return __uint_as_float(u);
}

__device__ __forceinline__ void mma8(float* c, const unsigned* a, const unsigned* b) {
    asm volatile(
        "mma.sync.aligned.m16n8k8.row.col.f32.tf32.tf32.f32 "
        "{%0,%1,%2,%3}, {%4,%5,%6,%7}, {%8,%9}, {%0,%1,%2,%3};"
        : "+f"(c[0]), "+f"(c[1]), "+f"(c[2]), "+f"(c[3])
        : "r"(a[0]), "r"(a[1]), "r"(a[2]), "r"(a[3]), "r"(b[0]), "r"(b[1]));
}

// ---------------------------------------------------------------------------
// Kernel 1: s1 = relu(LN(state @ enc_w + enc_b))    M=16384 K=512 N=256
// block 128x256, BK=32, 16 warps (4 row x 4 col), warp 32x64
// ---------------------------------------------------------------------------
__global__ __launch_bounds__(512, 1) void k_enc(
    const float* __restrict__ state, const float* __restrict__ W,
    const float* __restrict__ bias, const float* __restrict__ gam,
    const float* __restrict__ bet)
{
    extern __shared__ float sm[];
    float*  sA  = sm;                        // [128][36]
    float*  sB  = sm + 128 * 36;             // [32][260]
    float2* red = (float2*)(sB + 32 * 260);  // [4][128]

    const int tid = threadIdx.x;
    const int wid = tid >> 5, lane = tid & 31;
    const int g = lane >> 2, t = lane & 3;
    const int wm = wid & 3, wn = wid >> 2;
    const int R0 = blockIdx.x * 128;

    float c[2][8][4];
#pragma unroll
    for (int mt = 0; mt < 2; mt++)
#pragma unroll
        for (int nt = 0; nt < 8; nt++)
#pragma unroll
            for (int e = 0; e < 4; e++) c[mt][nt][e] = 0.f;

    for (int kt = 0; kt < HDIM; kt += 32) {
#pragma unroll
        for (int p = 0; p < 2; p++) {
            int idx = tid + 512 * p;
            int row = idx >> 3, f4 = (idx & 7) * 4;
            float4 v = *(const float4*)&state[(size_t)(R0 + row) * HDIM + kt + f4];
            float* d = &sA[row * 36 + f4];
            d[0] = to_tf32(v.x); d[1] = to_tf32(v.y);
            d[2] = to_tf32(v.z); d[3] = to_tf32(v.w);
        }
#pragma unroll
        for (int p = 0; p < 4; p++) {
            int idx = tid + 512 * p;
            int kk = idx >> 6, n4 = (idx & 63) * 4;
            float4 v = *(const float4*)&W[(size_t)(kt + kk) * FCN + n4];
            float* d = &sB[kk * 260 + n4];
            d[0] = to_tf32(v.x); d[1] = to_tf32(v.y);
            d[2] = to_tf32(v.z); d[3] = to_tf32(v.w);
        }
        __syncthreads();
#pragma unroll
        for (int ks = 0; ks < 32; ks += 8) {
            unsigned a[2][4], b[8][2];
#pragma unroll
            for (int mt = 0; mt < 2; mt++) {
                int r = wm * 32 + mt * 16 + g;
                a[mt][0] = __float_as_uint(sA[r * 36 + ks + t]);
                a[mt][1] = __float_as_uint(sA[(r + 8) * 36 + ks + t]);
                a[mt][2] = __float_as_uint(sA[r * 36 + ks + t + 4]);
                a[mt][3] = __float_as_uint(sA[(r + 8) * 36 + ks + t + 4]);
            }
#pragma unroll
            for (int nt = 0; nt < 8; nt++) {
                int n = wn * 64 + nt * 8 + g;
                b[nt][0] = __float_as_uint(sB[(ks + t) * 260 + n]);
                b[nt][1] = __float_as_uint(sB[(ks + t + 4) * 260 + n]);
            }
#pragma unroll
            for (int mt = 0; mt < 2; mt++)
#pragma unroll
                for (int nt = 0; nt < 8; nt++) mma8(c[mt][nt], a[mt], b[nt]);
        }
        __syncthreads();
    }

    // bias + LN stats
#pragma unroll
    for (int nt = 0; nt < 8; nt++) {
        int col = wn * 64 + nt * 8 + 2 * t;
        float b0 = __ldg(&bias[col]), b1 = __ldg(&bias[col + 1]);
#pragma unroll
        for (int mt = 0; mt < 2; mt++) {
            c[mt][nt][0] += b0; c[mt][nt][1] += b1;
            c[mt][nt][2] += b0; c[mt][nt][3] += b1;
        }
    }
#pragma unroll
    for (int mt = 0; mt < 2; mt++) {
        float s0 = 0, q0 = 0, s1v = 0, q1 = 0;
#pragma unroll
        for (int nt = 0; nt < 8; nt++) {
            s0 += c[mt][nt][0] + c[mt][nt][1];
            q0 += c[mt][nt][0] * c[mt][nt][0] + c[mt][nt][1] * c[mt][nt][1];
            s1v += c[mt][nt][2] + c[mt][nt][3];
            q1 += c[mt][nt][2] * c[mt][nt][2] + c[mt][nt][3] * c[mt][nt][3];
        }
#pragma unroll
        for (int o = 1; o <= 2; o <<= 1) {
            s0 += __shfl_xor_sync(~0u, s0, o); q0 += __shfl_xor_sync(~0u, q0, o);
            s1v += __shfl_xor_sync(~0u, s1v, o); q1 += __shfl_xor_sync(~0u, q1, o);
        }
        if (t == 0) {
            red[wn * 128 + wm * 32 + mt * 16 + g]     = make_float2(s0, q0);
            red[wn * 128 + wm * 32 + mt * 16 + g + 8] = make_float2(s1v, q1);
        }
    }
    __syncthreads();
#pragma unroll
    for (int mt = 0; mt < 2; mt++)
#pragma unroll
        for (int h = 0; h < 2; h++) {
            int row = wm * 32 + mt * 16 + g + 8 * h;
            float s = 0, q = 0;
#pragma unroll
            for (int w2 = 0; w2 < 4; w2++) {
                float2 r2 = red[w2 * 128 + row]; s += r2.x; q += r2.y;
            }
            float mu = s * (1.f / FCN);
            float rs = rsqrtf(q * (1.f / FCN) - mu * mu + 1e-5f);
#pragma unroll
            for (int nt = 0; nt < 8; nt++) {
                int col = wn * 64 + nt * 8 + 2 * t;
                float o0 = fmaxf((c[mt][nt][2 * h]     - mu) * rs * __ldg(&gam[col])     + __ldg(&bet[col]),     0.f);
                float o1 = fmaxf((c[mt][nt][2 * h + 1] - mu) * rs * __ldg(&gam[col + 1]) + __ldg(&bet[col + 1]), 0.f);
                *(float2*)&g_s1[(size_t)(R0 + row) * FCN + col] = make_float2(o0, o1);
            }
        }
}

// ---------------------------------------------------------------------------
// Kernel 2: [U|V] = s1 @ [Wtop|Wbot]     M=16384 K=256 N=512 (no bias/LN)
// block 64x512, 16 warps (2 row x 8 col), warp 32x64
// ---------------------------------------------------------------------------
__global__ __launch_bounds__(512, 1) void k_uv(const float* __restrict__ core_w)
{
    extern __shared__ float sm[];
    float* sA = sm;              // [64][36]
    float* sB = sm + 64 * 36;    // [32][516]

    const int tid = threadIdx.x;
    const int wid = tid >> 5, lane = tid & 31;
    const int g = lane >> 2, t = lane & 3;
    const int wm = wid & 1, wn = wid >> 1;
    const int R0 = blockIdx.x * 64;

    float c[2][8][4];
#pragma unroll
    for (int mt = 0; mt < 2; mt++)
#pragma unroll
        for (int nt = 0; nt < 8; nt++)
#pragma unroll
            for (int e = 0; e < 4; e++) c[mt][nt][e] = 0.f;

    for (int kt = 0; kt < FCN; kt += 32) {
        {
            int row = tid >> 3, f4 = (tid & 7) * 4;
            float4 v = *(const float4*)&g_s1[(size_t)(R0 + row) * FCN + kt + f4];
            float* d = &sA[row * 36 + f4];
            d[0] = to_tf32(v.x); d[1] = to_tf32(v.y);
            d[2] = to_tf32(v.z); d[3] = to_tf32(v.w);
        }
#pragma unroll
        for (int p = 0; p < 8; p++) {
            int idx = tid + 512 * p;
            int kk = idx >> 7, col = (idx & 127) * 4;
            const float* src = (col < FCN)
                ? &core_w[(size_t)(kt + kk) * FCN + col]
                : &core_w[(size_t)(FCN + kt + kk) * FCN + (col - FCN)];
            float4 v = *(const float4*)src;
            float* d = &sB[kk * 516 + col];
            d[0] = to_tf32(v.x); d[1] = to_tf32(v.y);
            d[2] = to_tf32(v.z); d[3] = to_tf32(v.w);
        }
        __syncthreads();
#pragma unroll
        for (int ks = 0; ks < 32; ks += 8) {
            unsigned a[2][4], b[8][2];
#pragma unroll
            for (int mt = 0; mt < 2; mt++) {
                int r = wm * 32 + mt * 16 + g;
                a[mt][0] = __float_as_uint(sA[r * 36 + ks + t]);
                a[mt][1] = __float_as_uint(sA[(r + 8) * 36 + ks + t]);
                a[mt][2] = __float_as_uint(sA[r * 36 + ks + t + 4]);
                a[mt][3] = __float_as_uint(sA[(r + 8) * 36 + ks + t + 4]);
            }
#pragma unroll
            for (int nt = 0; nt < 8; nt++) {
                int n = wn * 64 + nt * 8 + g;
                b[nt][0] = __float_as_uint(sB[(ks + t) * 516 + n]);
                b[nt][1] = __float_as_uint(sB[(ks + t + 4) * 516 + n]);
            }
#pragma unroll
            for (int mt = 0; mt < 2; mt++)
#pragma unroll
                for (int nt = 0; nt < 8; nt++) mma8(c[mt][nt], a[mt], b[nt]);
        }
        __syncthreads();
    }

#pragma unroll
    for (int mt = 0; mt < 2; mt++)
#pragma unroll
        for (int h = 0; h < 2; h++) {
            int row = R0 + wm * 32 + mt * 16 + g + 8 * h;
#pragma unroll
            for (int nt = 0; nt < 8; nt++) {
                int col = wn * 64 + nt * 8 + 2 * t;
                *(float2*)&g_uv[(size_t)row * 512 + col] =
                    make_float2(c[mt][nt][2 * h], c[mt][nt][2 * h + 1]);
            }
        }
}

// ---------------------------------------------------------------------------
// Kernel 3: build core rows on-the-fly, ctx+att GEMMs, effect reduction.
// block = 112 pair-rows (16 complete groups of 7), 448 threads, 14 warps
// warp grid: 7 row-warps (16 rows) x 2 col-warps
// ---------------------------------------------------------------------------
__global__ __launch_bounds__(448, 1) void k_eff(
    const float* __restrict__ core_b, const float* __restrict__ core_g,
    const float* __restrict__ core_bb,
    const float* __restrict__ ctxW, const float* __restrict__ ctx_b,
    const float* __restrict__ ctx_g, const float* __restrict__ ctx_bb,
    const float* __restrict__ a1W,  const float* __restrict__ a1_b,
    const float* __restrict__ att_g, const float* __restrict__ att_bb,
    const float* __restrict__ a2W,  const float* __restrict__ a2_b)
{
    extern __shared__ float sm[];
    float*  sA   = sm;                          // [112][260]  core rows (tf32)
    float*  sB   = sA + 112 * 260;              // [32][260]   B staging
    float*  sEff = sB + 32 * 260;               // [16][257]
    float2* sRed = (float2*)(sEff + 16 * 257);  // [2][112]
    float*  sDot = (float*)(sRed + 2 * 112);    // [2][112]
    float*  sAtt = sDot + 2 * 112;              // [112]

    const int tid = threadIdx.x;
    const int wid = tid >> 5, lane = tid & 31;
    const int g = lane >> 2, t = lane & 3;
    const int wm = wid % 7, wn = wid / 7;
    const int R0 = blockIdx.x * 112;

    for (int idx = tid; idx < 16 * 257; idx += 448) sEff[idx] = 0.f;

    // ---- phase a: core rows = relu(LN(U[p]+V[q]+core_b)) into sA ----
    {
        float cb[8], cg[8], cbb[8];
#pragma unroll
        for (int e = 0; e < 8; e++) {
            int col = lane + 32 * e;
            cb[e] = core_b[col]; cg[e] = core_g[col]; cbb[e] = core_bb[col];
        }
#pragma unroll
        for (int rr = 0; rr < 8; rr++) {
            int lrow = wid * 8 + rr;
            int v = R0 + lrow;
            int p = v / 7;
            int jj = v - p * 7;
            int i = p & 7;
            int j = jj + (jj >= i ? 1 : 0);
            int q = (p & ~7) + j;
            float val[8], s = 0.f, s2 = 0.f;
#pragma unroll
            for (int e = 0; e < 8; e++) {
                int col = lane + 32 * e;
                val[e] = g_uv[(size_t)p * 512 + col] + g_uv[(size_t)q * 512 + 256 + col] + cb[e];
                s += val[e]; s2 += val[e] * val[e];
            }
#pragma unroll
            for (int o = 16; o; o >>= 1) {
                s  += __shfl_xor_sync(~0u, s,  o);
                s2 += __shfl_xor_sync(~0u, s2, o);
            }
            float mu = s * (1.f / FCN);
            float rs = rsqrtf(s2 * (1.f / FCN) - mu * mu + 1e-5f);
#pragma unroll
            for (int e = 0; e < 8; e++) {
                float o2 = fmaxf((val[e] - mu) * rs * cg[e] + cbb[e], 0.f);
                sA[lrow * 260 + lane + 32 * e] = to_tf32(o2);
            }
        }
    }

    // ---- pass 1: attention  (N=128, col-warp owns 64) ----
    {
        float ca[8][4];
#pragma unroll
        for (int nt = 0; nt < 8; nt++)
#pragma unroll
            for (int e = 0; e < 4; e++) ca[nt][e] = 0.f;

        for (int kt = 0; kt < FCN; kt += 32) {
            for (int idx = tid; idx < 32 * 32; idx += 448) {
                int kk = idx >> 5, n4 = (idx & 31) * 4;
                float4 v = *(const float4*)&a1W[(size_t)(kt + kk) * LASTN + n4];
                float* d = &sB[kk * 132 + n4];
                d[0] = to_tf32(v.x); d[1] = to_tf32(v.y);
                d[2] = to_tf32(v.z); d[3] = to_tf32(v.w);
            }
            __syncthreads();
#pragma unroll
            for (int ks = 0; ks < 32; ks += 8) {
                unsigned a[4], b[8][2];
                int r = wm * 16 + g;
                a[0] = __float_as_uint(sA[r * 260 + kt + ks + t]);
                a[1] = __float_as_uint(sA[(r + 8) * 260 + kt + ks + t]);
                a[2] = __float_as_uint(sA[r * 260 + kt + ks + t + 4]);
                a[3] = __float_as_uint(sA[(r + 8) * 260 + kt + ks + t + 4]);
#pragma unroll
                for (int nt = 0; nt < 8; nt++) {
                    int n = wn * 64 + nt * 8 + g;
                    b[nt][0] = __float_as_uint(sB[(ks + t) * 132 + n]);
                    b[nt][1] = __float_as_uint(sB[(ks + t + 4) * 132 + n]);
                }
#pragma unroll
                for (int nt = 0; nt < 8; nt++) mma8(ca[nt], a, b[nt]);
            }
            __syncthreads();
        }
        // epilogue: LN(128) -> tanh -> dot(att2_w) -> sigmoid
#pragma unroll
        for (int nt = 0; nt < 8; nt++) {
            int col = wn * 64 + nt * 8 + 2 * t;
            float b0 = __ldg(&a1_b[col]), b1 = __ldg(&a1_b[col + 1]);
            ca[nt][0] += b0; ca[nt][1] += b1; ca[nt][2] += b0; ca[nt][3] += b1;
        }
        float s0 = 0, q0 = 0, s1v = 0, q1 = 0;
#pragma unroll
        for (int nt = 0; nt < 8; nt++) {
            s0 += ca[nt][0] + ca[nt][1];
            q0 += ca[nt][0] * ca[nt][0] + ca[nt][1] * ca[nt][1];
            s1v += ca[nt][2] + ca[nt][3];
            q1 += ca[nt][2] * ca[nt][2] + ca[nt][3] * ca[nt][3];
        }
#pragma unroll
        for (int o = 1; o <= 2; o <<= 1) {
            s0 += __shfl_xor_sync(~0u, s0, o); q0 += __shfl_xor_sync(~0u, q0, o);
            s1v += __shfl_xor_sync(~0u, s1v, o); q1 += __shfl_xor_sync(~0u, q1, o);
        }
        if (t == 0) {
            sRed[wn * 112 + wm * 16 + g]     = make_float2(s0, q0);
            sRed[wn * 112 + wm * 16 + g + 8] = make_float2(s1v, q1);
        }
        __syncthreads();
        float d0 = 0.f, d1 = 0.f;
        {
            int r0 = wm * 16 + g, r1 = r0 + 8;
            float2 p0 = sRed[r0], p0b = sRed[112 + r0];
            float2 p1 = sRed[r1], p1b = sRed[112 + r1];
            float su0 = p0.x + p0b.x, sq0 = p0.y + p0b.y;
            float su1 = p1.x + p1b.x, sq1 = p1.y + p1b.y;
            float mu0 = su0 * (1.f / LASTN);
            float rs0 = rsqrtf(sq0 * (1.f / LASTN) - mu0 * mu0 + 1e-5f);
            float mu1 = su1 * (1.f / LASTN);
            float rs1 = rsqrtf(sq1 * (1.f / LASTN) - mu1 * mu1 + 1e-5f);
#pragma unroll
            for (int nt = 0; nt < 8; nt++) {
                int col = wn * 64 + nt * 8 + 2 * t;
                float gg0 = __ldg(&att_g[col]),  bb0 = __ldg(&att_bb[col]),  w0 = __ldg(&a2W[col]);
                float gg1 = __ldg(&att_g[col+1]), bb1 = __ldg(&att_bb[col+1]), w1 = __ldg(&a2W[col+1]);
                d0 += tanhf((ca[nt][0] - mu0) * rs0 * gg0 + bb0) * w0;
                d0 += tanhf((ca[nt][1] - mu0) * rs0 * gg1 + bb1) * w1;
                d1 += tanhf((ca[nt][2] - mu1) * rs1 * gg0 + bb0) * w0;
                d1 += tanhf((ca[nt][3] - mu1) * rs1 * gg1 + bb1) * w1;
            }
        }
#pragma unroll
        for (int o = 1; o <= 2; o <<= 1) {
            d0 += __shfl_xor_sync(~0u, d0, o);
            d1 += __shfl_xor_sync(~0u, d1, o);
        }
        if (t == 0) {
            sDot[wn * 112 + wm * 16 + g]     = d0;
            sDot[wn * 112 + wm * 16 + g + 8] = d1;
        }
        __syncthreads();
        if (wn == 0 && t == 0) {
            float a2b = __ldg(&a2_b[0]);
            int r0 = wm * 16 + g;
            sAtt[r0]     = 1.f / (1.f + expf(-(sDot[r0]     + sDot[112 + r0]     + a2b)));
            sAtt[r0 + 8] = 1.f / (1.f + expf(-(sDot[r0 + 8] + sDot[112 + r0 + 8] + a2b)));
        }
    }

    // ---- pass 2: ctx (N=256, col-warp owns 128) + effect reduction ----
    {
        float cc[16][4];
#pragma unroll
        for (int nt = 0; nt < 16; nt++)
#pragma unroll
            for (int e = 0; e < 4; e++) cc[nt][e] = 0.f;

        for (int kt = 0; kt < FCN; kt += 32) {
            for (int idx = tid; idx < 32 * 64; idx += 448) {
                int kk = idx >> 6, n4 = (idx & 63) * 4;
                float4 v = *(const float4*)&ctxW[(size_t)(kt + kk) * FCN + n4];
                float* d = &sB[kk * 260 + n4];
                d[0] = to_tf32(v.x); d[1] = to_tf32(v.y);
                d[2] = to_tf32(v.z); d[3] = to_tf32(v.w);
            }
            __syncthreads();
#pragma unroll
            for (int ks = 0; ks < 32; ks += 8) {
                unsigned a[4], b[16][2];
                int r = wm * 16 + g;
                a[0] = __float_as_uint(sA[r * 260 + kt + ks + t]);
                a[1] = __float_as_uint(sA[(r + 8) * 260 + kt + ks + t]);
                a[2] = __float_as_uint(sA[r * 260 + kt + ks + t + 4]);
                a[3] = __float_as_uint(sA[(r + 8) * 260 + kt + ks + t + 4]);
#pragma unroll
                for (int nt = 0; nt < 16; nt++) {
                    int n = wn * 128 + nt * 8 + g;
                    b[nt][0] = __float_as_uint(sB[(ks + t) * 260 + n]);
                    b[nt][1] = __float_as_uint(sB[(ks + t + 4) * 260 + n]);
                }
#pragma unroll
                for (int nt = 0; nt < 16; nt++) mma8(cc[nt], a, b[nt]);
            }
            __syncthreads();
        }
        // epilogue: LN + relu, scale by att, accumulate effect per group
#pragma unroll
        for (int nt = 0; nt < 16; nt++) {
            int col = wn * 128 + nt * 8 + 2 * t;
            float b0 = __ldg(&ctx_b[col]), b1 = __ldg(&ctx_b[col + 1]);
            cc[nt][0] += b0; cc[nt][1] += b1; cc[nt][2] += b0; cc[nt][3] += b1;
        }
        float s0 = 0, q0 = 0, s1v = 0, q1 = 0;
#pragma unroll
        for (int nt = 0; nt < 16; nt++) {
            s0 += cc[nt][0] + cc[nt][1];
            q0 += cc[nt][0] * cc[nt][0] + cc[nt][1] * cc[nt][1];
            s1v += cc[nt][2] + cc[nt][3];
            q1 += cc[nt][2] * cc[nt][2] + cc[nt][3] * cc[nt][3];
        }
#pragma unroll
        for (int o = 1; o <= 2; o <<= 1) {
            s0 += __shfl_xor_sync(~0u, s0, o); q0 += __shfl_xor_sync(~0u, q0, o);
            s1v += __shfl_xor_sync(~0u, s1v, o); q1 += __shfl_xor_sync(~0u, q1, o);
        }
        if (t == 0) {
            sRed[wn * 112 + wm * 16 + g]     = make_float2(s0, q0);
            sRed[wn * 112 + wm * 16 + g + 8] = make_float2(s1v, q1);
        }
        __syncthreads();
        {
            int r0 = wm * 16 + g, r1 = r0 + 8;
            float2 p0 = sRed[r0], p0b = sRed[112 + r0];
            float2 p1 = sRed[r1], p1b = sRed[112 + r1];
            float mu0 = (p0.x + p0b.x) * (1.f / FCN);
            float rs0 = rsqrtf((p0.y + p0b.y) * (1.f / FCN) - mu0 * mu0 + 1e-5f);
            float mu1 = (p1.x + p1b.x) * (1.f / FCN);
            float rs1 = rsqrtf((p1.y + p1b.y) * (1.f / FCN) - mu1 * mu1 + 1e-5f);
            float at0 = sAtt[r0], at1 = sAtt[r1];
            int gl0 = (R0 + r0) / 7 - blockIdx.x * 16;
            int gl1 = (R0 + r1) / 7 - blockIdx.x * 16;
#pragma unroll
            for (int nt = 0; nt < 16; nt++) {
                int col = wn * 128 + nt * 8 + 2 * t;
                float gg0 = __ldg(&ctx_g[col]),  bb0 = __ldg(&ctx_bb[col]);
                float gg1 = __ldg(&ctx_g[col+1]), bb1 = __ldg(&ctx_bb[col+1]);
                float v00 = fmaxf((cc[nt][0] - mu0) * rs0 * gg0 + bb0, 0.f) * at0;
                float v01 = fmaxf((cc[nt][1] - mu0) * rs0 * gg1 + bb1, 0.f) * at0;
                float v10 = fmaxf((cc[nt][2] - mu1) * rs1 * gg0 + bb0, 0.f) * at1;
                float v11 = fmaxf((cc[nt][3] - mu1) * rs1 * gg1 + bb1, 0.f) * at1;
                atomicAdd(&sEff[gl0 * 257 + col],     v00);
                atomicAdd(&sEff[gl0 * 257 + col + 1], v01);
                atomicAdd(&sEff[gl1 * 257 + col],     v10);
                atomicAdd(&sEff[gl1 * 257 + col + 1], v11);
            }
        }
    }
    __syncthreads();
    for (int idx = tid; idx < 16 * FCN; idx += 448) {
        int gg = idx >> 8, col = idx & 255;
        g_eff[(size_t)(blockIdx.x * 16 + gg) * FCN + col] = sEff[gg * 257 + col];
    }
}

// ---------------------------------------------------------------------------
// Kernel 4: new_state = concat(s1, effect, x) @ out_w + out_b
// M=16384 K=1536 N=256, block 128x256, 16 warps (4x4), warp 32x64
// ---------------------------------------------------------------------------
__global__ __launch_bounds__(512, 1) void k_out(
    const float* __restrict__ xin, const float* __restrict__ W,
    const float* __restrict__ bias, float* __restrict__ out, int dup)
{
    extern __shared__ float sm[];
    float* sA = sm;              // [128][36]
    float* sB = sm + 128 * 36;   // [32][260]

    const int tid = threadIdx.x;
    const int wid = tid >> 5, lane = tid & 31;
    const int g = lane >> 2, t = lane & 3;
    const int wm = wid & 3, wn = wid >> 2;
    const int R0 = blockIdx.x * 128;

    float c[2][8][4];
#pragma unroll
    for (int mt = 0; mt < 2; mt++)
#pragma unroll
        for (int nt = 0; nt < 8; nt++)
#pragma unroll
            for (int e = 0; e < 4; e++) c[mt][nt][e] = 0.f;

    for (int kt = 0; kt < 2 * FCN + MDIM; kt += 32) {
#pragma unroll
        for (int p = 0; p < 2; p++) {
            int idx = tid + 512 * p;
            int row = idx >> 3, f4 = (idx & 7) * 4;
            const float* src;
            if (kt < FCN)          src = &g_s1 [(size_t)(R0 + row) * FCN  + kt + f4];
            else if (kt < 2 * FCN) src = &g_eff[(size_t)(R0 + row) * FCN  + kt - FCN + f4];
            else                   src = &xin  [(size_t)(R0 + row) * MDIM + kt - 2 * FCN + f4];
            float4 v = *(const float4*)src;
            float* d = &sA[row * 36 + f4];
            d[0] = to_tf32(v.x); d[1] = to_tf32(v.y);
            d[2] = to_tf32(v.z); d[3] = to_tf32(v.w);
        }
#pragma unroll
        for (int p = 0; p < 4; p++) {
            int idx = tid + 512 * p;
            int kk = idx >> 6, n4 = (idx & 63) * 4;
            float4 v = *(const float4*)&W[(size_t)(kt + kk) * FCN + n4];
            float* d = &sB[kk * 260 + n4];
            d[0] = to_tf32(v.x); d[1] = to_tf32(v.y);
            d[2] = to_tf32(v.z); d[3] = to_tf32(v.w);
        }
        __syncthreads();
#pragma unroll
        for (int ks = 0; ks < 32; ks += 8) {
            unsigned a[2][4], b[8][2];
#pragma unroll
            for (int mt = 0; mt < 2; mt++) {
                int r = wm * 32 + mt * 16 + g;
                a[mt][0] = __float_as_uint(sA[r * 36 + ks + t]);
                a[mt][1] = __float_as_uint(sA[(r + 8) * 36 + ks + t]);
                a[mt][2] = __float_as_uint(sA[r * 36 + ks + t + 4]);
                a[mt][3] = __float_as_uint(sA[(r + 8) * 36 + ks + t + 4]);
            }
#pragma unroll
            for (int nt = 0; nt < 8; nt++) {
                int n = wn * 64 + nt * 8 + g;
                b[nt][0] = __float_as_uint(sB[(ks + t) * 260 + n]);
                b[nt][1] = __float_as_uint(sB[(ks + t + 4) * 260 + n]);
            }
#pragma unroll
            for (int mt = 0; mt < 2; mt++)
#pragma unroll
                for (int nt = 0; nt < 8; nt++) mma8(c[mt][nt], a[mt], b[nt]);
        }
        __syncthreads();
    }

#pragma unroll
    for (int mt = 0; mt < 2; mt++)
#pragma unroll
        for (int h = 0; h < 2; h++) {
            int row = R0 + wm * 32 + mt * 16 + g + 8 * h;
#pragma unroll
            for (int nt = 0; nt < 8; nt++) {
                int col = wn * 64 + nt * 8 + 2 * t;
                float o0 = c[mt][nt][2 * h]     + __ldg(&bias[col]);
                float o1 = c[mt][nt][2 * h + 1] + __ldg(&bias[col + 1]);
                size_t off = (size_t)row * FCN + col;
                *(float2*)&out[off] = make_float2(o0, o1);
                if (dup) *(float2*)&out[(size_t)NR1 * FCN + off] = make_float2(o0, o1);
            }
        }
}

// ---------------------------------------------------------------------------
extern "C" void kernel_launch(void* const* d_in, const int* in_sizes, int n_in,
                              void* d_out, int out_size) {
    const float* x      = (const float*)d_in[0];
    const float* state  = (const float*)d_in[1];
    const float* enc_w  = (const float*)d_in[2];
    const float* enc_b  = (const float*)d_in[3];
    const float* enc_g  = (const float*)d_in[4];
    const float* enc_bb = (const float*)d_in[5];
    const float* core_w = (const float*)d_in[6];
    const float* core_b = (const float*)d_in[7];
    const float* core_g = (const float*)d_in[8];
    const float* core_bb= (const float*)d_in[9];
    const float* ctx_w  = (const float*)d_in[10];
    const float* ctx_b  = (const float*)d_in[11];
    const float* ctx_g  = (const float*)d_in[12];
    const float* ctx_bb = (const float*)d_in[13];
    const float* att1_w = (const float*)d_in[14];
    const float* att1_b = (const float*)d_in[15];
    const float* att_g  = (const float*)d_in[16];
    const float* att_bb = (const float*)d_in[17];
    const float* att2_w = (const float*)d_in[18];
    const float* att2_b = (const float*)d_in[19];
    const float* out_w  = (const float*)d_in[20];
    const float* out_b  = (const float*)d_in[21];
    float* out = (float*)d_out;
    int dup = (out_size >= 2 * NR1 * FCN) ? 1 : 0;

    const int smem_enc = (128 * 36 + 32 * 260) * 4 + 4 * 128 * 8;
    const int smem_uv  = (64 * 36 + 32 * 516) * 4;
    const int smem_eff = (112 * 260 + 32 * 260 + 16 * 257 + 2 * 112 * 2 + 2 * 112 + 112) * 4;
    const int smem_out = (128 * 36 + 32 * 260) * 4;

    cudaFuncSetAttribute(k_enc, cudaFuncAttributeMaxDynamicSharedMemorySize, smem_enc);
    cudaFuncSetAttribute(k_uv,  cudaFuncAttributeMaxDynamicSharedMemorySize, smem_uv);
    cudaFuncSetAttribute(k_eff, cudaFuncAttributeMaxDynamicSharedMemorySize, smem_eff);
    cudaFuncSetAttribute(k_out, cudaFuncAttributeMaxDynamicSharedMemorySize, smem_out);

    k_enc<<<NR1 / 128, 512, smem_enc>>>(state, enc_w, enc_b, enc_g, enc_bb);
    k_uv <<<NR1 / 64,  512, smem_uv >>>(core_w);
    k_eff<<<NR2 / 112, 448, smem_eff>>>(core_b, core_g, core_bb,
                                        ctx_w, ctx_b, ctx_g, ctx_bb,
                                        att1_w, att1_b, att_g, att_bb,
                                        att2_w, att2_b);
    k_out<<<NR1 / 128, 512, smem_out>>>(x, out_w, out_b, out, dup);
}

// round 5
// speedup vs baseline: 3.3931x; 1.2097x over previous
#include <cuda_runtime.h>
#include <cstdint>
#include <math.h>

// ---------------------------------------------------------------------------
// R-NEM cell, tf32 tensor-core pipeline, cp.async double-buffered mainloops.
//   K=8, FC=256, LAST=128, B=2048, M=1024, H=512
//   rows1 = 16384, rows2 = 114688
// core_pre[v] = U[p] + V[q] + core_b, [U|V] = s1 @ core_w (packed k-major)
// ---------------------------------------------------------------------------

#define FCN   256
#define LASTN 128
#define HDIM  512
#define MDIM  1024
#define NR1   16384
#define NR2   114688
#define KOUT  (2 * FCN + MDIM)

__device__ float g_s1[NR1 * FCN];        // tf32-rounded
__device__ float g_uv[NR1 * 2 * FCN];    // fp32
__device__ float g_eff[NR1 * FCN];       // tf32-rounded

// pre-converted (tf32) weights
__device__ float g_wenc[HDIM * FCN];
__device__ float g_wuv[FCN * 2 * FCN];   // packed: [k][512] = [Wtop | Wbot]
__device__ float g_wctx[FCN * FCN];
__device__ float g_watt[FCN * LASTN];
__device__ float g_wout[KOUT * FCN];

// -------------------------------- helpers ---------------------------------
__device__ __forceinline__ float to_tf32(float x) {
    unsigned u; asm("cvt.rna.tf32.f32 %0, %1;" : "=r"(u) : "f"(x));
    return __uint_as_float(u);
}
__device__ __forceinline__ void mma8(float* c, const unsigned* a, const unsigned* b) {
    asm volatile(
        "mma.sync.aligned.m16n8k8.row.col.f32.tf32.tf32.f32 "
        "{%0,%1,%2,%3}, {%4,%5,%6,%7}, {%8,%9}, {%0,%1,%2,%3};"
        : "+f"(c[0]), "+f"(c[1]), "+f"(c[2]), "+f"(c[3])
        : "r"(a[0]), "r"(a[1]), "r"(a[2]), "r"(a[3]), "r"(b[0]), "r"(b[1]));
}
__device__ __forceinline__ void cpa16(float* dst, const float* src) {
    unsigned d = (unsigned)__cvta_generic_to_shared(dst);
    asm volatile("cp.async.cg.shared.global [%0], [%1], 16;" :: "r"(d), "l"(src));
}
__device__ __forceinline__ void cp_commit() { asm volatile("cp.async.commit_group;"); }
__device__ __forceinline__ void cp_wait0()  { asm volatile("cp.async.wait_group 0;"); }

// ---------------------------------------------------------------------------
// Kernel 0: convert/pack weights to tf32
// ---------------------------------------------------------------------------
__global__ void k_cvtw(const float* __restrict__ enc_w, const float* __restrict__ core_w,
                       const float* __restrict__ ctx_w, const float* __restrict__ att1_w,
                       const float* __restrict__ out_w)
{
    int i = blockIdx.x * blockDim.x + threadIdx.x;
    int n = gridDim.x * blockDim.x;
    for (int idx = i; idx < HDIM * FCN; idx += n) g_wenc[idx] = to_tf32(enc_w[idx]);
    for (int idx = i; idx < FCN * 2 * FCN; idx += n) {
        int k = idx >> 9, c = idx & 511;
        float v = (c < FCN) ? core_w[k * FCN + c] : core_w[(FCN + k) * FCN + (c - FCN)];
        g_wuv[idx] = to_tf32(v);
    }
    for (int idx = i; idx < FCN * FCN; idx += n) g_wctx[idx] = to_tf32(ctx_w[idx]);
    for (int idx = i; idx < FCN * LASTN; idx += n) g_watt[idx] = to_tf32(att1_w[idx]);
    for (int idx = i; idx < KOUT * FCN; idx += n) g_wout[idx] = to_tf32(out_w[idx]);
}

// ---------------------------------------------------------------------------
// Kernel 1: s1 = relu(LN(state @ enc_w + enc_b))    M=16384 K=512 N=256
// block 128x256, 16 warps (4x4), warp 32x64, pipelined
// ---------------------------------------------------------------------------
__global__ __launch_bounds__(512, 1) void k_enc(
    const float* __restrict__ state, const float* __restrict__ bias,
    const float* __restrict__ gam, const float* __restrict__ bet)
{
    extern __shared__ float sm[];
    float*  sA  = sm;                            // 2 x [128][36]
    float*  sB  = sm + 2 * 128 * 36;             // 2 x [32][260]
    float2* red = (float2*)(sB + 2 * 32 * 260);  // [4][128]

    const int tid = threadIdx.x;
    const int wid = tid >> 5, lane = tid & 31;
    const int g = lane >> 2, t = lane & 3;
    const int wm = wid & 3, wn = wid >> 2;
    const int R0 = blockIdx.x * 128;

    const int ar0 = (tid) >> 3,        af0 = ((tid) & 7) * 4;
    const int ar1 = (tid + 512) >> 3,  af1 = ((tid + 512) & 7) * 4;

    float c[2][8][4];
#pragma unroll
    for (int mt = 0; mt < 2; mt++)
#pragma unroll
        for (int nt = 0; nt < 8; nt++)
#pragma unroll
            for (int e = 0; e < 4; e++) c[mt][nt][e] = 0.f;

    float4 a0, a1;
    // prologue: tile 0
    a0 = *(const float4*)&state[(size_t)(R0 + ar0) * HDIM + af0];
    a1 = *(const float4*)&state[(size_t)(R0 + ar1) * HDIM + af1];
    {
        float* d0 = &sA[ar0 * 36 + af0];
        d0[0]=to_tf32(a0.x); d0[1]=to_tf32(a0.y); d0[2]=to_tf32(a0.z); d0[3]=to_tf32(a0.w);
        float* d1 = &sA[ar1 * 36 + af1];
        d1[0]=to_tf32(a1.x); d1[1]=to_tf32(a1.y); d1[2]=to_tf32(a1.z); d1[3]=to_tf32(a1.w);
    }
#pragma unroll
    for (int p = 0; p < 4; p++) {
        int idx = tid + 512 * p;
        int kk = idx >> 6, n4 = (idx & 63) * 4;
        cpa16(&sB[kk * 260 + n4], &g_wenc[(size_t)kk * FCN + n4]);
    }
    cp_commit(); cp_wait0(); __syncthreads();

    const int T = HDIM / 32;
    for (int kt = 0; kt < T; kt++) {
        const int bt = kt & 1, bn = bt ^ 1;
        float* cA = sA + bt * 128 * 36;
        float* cB = sB + bt * 32 * 260;
        if (kt + 1 < T) {
            float* nB = sB + bn * 32 * 260;
#pragma unroll
            for (int p = 0; p < 4; p++) {
                int idx = tid + 512 * p;
                int kk = idx >> 6, n4 = (idx & 63) * 4;
                cpa16(&nB[kk * 260 + n4], &g_wenc[(size_t)((kt + 1) * 32 + kk) * FCN + n4]);
            }
            cp_commit();
            a0 = *(const float4*)&state[(size_t)(R0 + ar0) * HDIM + (kt + 1) * 32 + af0];
            a1 = *(const float4*)&state[(size_t)(R0 + ar1) * HDIM + (kt + 1) * 32 + af1];
        }
#pragma unroll
        for (int ks = 0; ks < 32; ks += 8) {
            unsigned a[2][4], b[8][2];
#pragma unroll
            for (int mt = 0; mt < 2; mt++) {
                int r = wm * 32 + mt * 16 + g;
                a[mt][0] = __float_as_uint(cA[r * 36 + ks + t]);
                a[mt][1] = __float_as_uint(cA[(r + 8) * 36 + ks + t]);
                a[mt][2] = __float_as_uint(cA[r * 36 + ks + t + 4]);
                a[mt][3] = __float_as_uint(cA[(r + 8) * 36 + ks + t + 4]);
            }
#pragma unroll
            for (int nt = 0; nt < 8; nt++) {
                int n = wn * 64 + nt * 8 + g;
                b[nt][0] = __float_as_uint(cB[(ks + t) * 260 + n]);
                b[nt][1] = __float_as_uint(cB[(ks + t + 4) * 260 + n]);
            }
#pragma unroll
            for (int mt = 0; mt < 2; mt++)
#pragma unroll
                for (int nt = 0; nt < 8; nt++) mma8(c[mt][nt], a[mt], b[nt]);
        }
        if (kt + 1 < T) {
            float* nA = sA + bn * 128 * 36;
            float* d0 = &nA[ar0 * 36 + af0];
            d0[0]=to_tf32(a0.x); d0[1]=to_tf32(a0.y); d0[2]=to_tf32(a0.z); d0[3]=to_tf32(a0.w);
            float* d1 = &nA[ar1 * 36 + af1];
            d1[0]=to_tf32(a1.x); d1[1]=to_tf32(a1.y); d1[2]=to_tf32(a1.z); d1[3]=to_tf32(a1.w);
        }
        cp_wait0(); __syncthreads();
    }

    // epilogue: bias + LN + relu (tf32-rounded store)
#pragma unroll
    for (int nt = 0; nt < 8; nt++) {
        int col = wn * 64 + nt * 8 + 2 * t;
        float b0 = __ldg(&bias[col]), b1 = __ldg(&bias[col + 1]);
#pragma unroll
        for (int mt = 0; mt < 2; mt++) {
            c[mt][nt][0] += b0; c[mt][nt][1] += b1;
            c[mt][nt][2] += b0; c[mt][nt][3] += b1;
        }
    }
#pragma unroll
    for (int mt = 0; mt < 2; mt++) {
        float s0 = 0, q0 = 0, s1v = 0, q1 = 0;
#pragma unroll
        for (int nt = 0; nt < 8; nt++) {
            s0 += c[mt][nt][0] + c[mt][nt][1];
            q0 += c[mt][nt][0] * c[mt][nt][0] + c[mt][nt][1] * c[mt][nt][1];
            s1v += c[mt][nt][2] + c[mt][nt][3];
            q1 += c[mt][nt][2] * c[mt][nt][2] + c[mt][nt][3] * c[mt][nt][3];
        }
#pragma unroll
        for (int o = 1; o <= 2; o <<= 1) {
            s0 += __shfl_xor_sync(~0u, s0, o); q0 += __shfl_xor_sync(~0u, q0, o);
            s1v += __shfl_xor_sync(~0u, s1v, o); q1 += __shfl_xor_sync(~0u, q1, o);
        }
        if (t == 0) {
            red[wn * 128 + wm * 32 + mt * 16 + g]     = make_float2(s0, q0);
            red[wn * 128 + wm * 32 + mt * 16 + g + 8] = make_float2(s1v, q1);
        }
    }
    __syncthreads();
#pragma unroll
    for (int mt = 0; mt < 2; mt++)
#pragma unroll
        for (int h = 0; h < 2; h++) {
            int row = wm * 32 + mt * 16 + g + 8 * h;
            float s = 0, q = 0;
#pragma unroll
            for (int w2 = 0; w2 < 4; w2++) {
                float2 r2 = red[w2 * 128 + row]; s += r2.x; q += r2.y;
            }
            float mu = s * (1.f / FCN);
            float rs = rsqrtf(q * (1.f / FCN) - mu * mu + 1e-5f);
#pragma unroll
            for (int nt = 0; nt < 8; nt++) {
                int col = wn * 64 + nt * 8 + 2 * t;
                float o0 = fmaxf((c[mt][nt][2 * h]     - mu) * rs * __ldg(&gam[col])     + __ldg(&bet[col]),     0.f);
                float o1 = fmaxf((c[mt][nt][2 * h + 1] - mu) * rs * __ldg(&gam[col + 1]) + __ldg(&bet[col + 1]), 0.f);
                *(float2*)&g_s1[(size_t)(R0 + row) * FCN + col] =
                    make_float2(to_tf32(o0), to_tf32(o1));
            }
        }
}

// ---------------------------------------------------------------------------
// Kernel 2: [U|V] = s1 @ packed(core_w)   M=16384 K=256 N=512
// block 64x512, 16 warps (2x8), warp 32x64, pipelined
// ---------------------------------------------------------------------------
__global__ __launch_bounds__(512, 1) void k_uv()
{
    extern __shared__ float sm[];
    float* sA = sm;                   // 2 x [64][36]
    float* sB = sm + 2 * 64 * 36;     // 2 x [32][516]

    const int tid = threadIdx.x;
    const int wid = tid >> 5, lane = tid & 31;
    const int g = lane >> 2, t = lane & 3;
    const int wm = wid & 1, wn = wid >> 1;
    const int R0 = blockIdx.x * 64;
    const int ar = tid >> 3, af = (tid & 7) * 4;

    float c[2][8][4];
#pragma unroll
    for (int mt = 0; mt < 2; mt++)
#pragma unroll
        for (int nt = 0; nt < 8; nt++)
#pragma unroll
            for (int e = 0; e < 4; e++) c[mt][nt][e] = 0.f;

    float4 a0;
    a0 = *(const float4*)&g_s1[(size_t)(R0 + ar) * FCN + af];
    *(float4*)&sA[ar * 36 + af] = a0;   // already tf32-rounded
#pragma unroll
    for (int p = 0; p < 8; p++) {
        int idx = tid + 512 * p;
        int kk = idx >> 7, n4 = (idx & 127) * 4;
        cpa16(&sB[kk * 516 + n4], &g_wuv[(size_t)kk * 512 + n4]);
    }
    cp_commit(); cp_wait0(); __syncthreads();

    const int T = FCN / 32;
    for (int kt = 0; kt < T; kt++) {
        const int bt = kt & 1, bn = bt ^ 1;
        float* cA = sA + bt * 64 * 36;
        float* cB = sB + bt * 32 * 516;
        if (kt + 1 < T) {
            float* nB = sB + bn * 32 * 516;
#pragma unroll
            for (int p = 0; p < 8; p++) {
                int idx = tid + 512 * p;
                int kk = idx >> 7, n4 = (idx & 127) * 4;
                cpa16(&nB[kk * 516 + n4], &g_wuv[(size_t)((kt + 1) * 32 + kk) * 512 + n4]);
            }
            cp_commit();
            a0 = *(const float4*)&g_s1[(size_t)(R0 + ar) * FCN + (kt + 1) * 32 + af];
        }
#pragma unroll
        for (int ks = 0; ks < 32; ks += 8) {
            unsigned a[2][4], b[8][2];
#pragma unroll
            for (int mt = 0; mt < 2; mt++) {
                int r = wm * 32 + mt * 16 + g;
                a[mt][0] = __float_as_uint(cA[r * 36 + ks + t]);
                a[mt][1] = __float_as_uint(cA[(r + 8) * 36 + ks + t]);
                a[mt][2] = __float_as_uint(cA[r * 36 + ks + t + 4]);
                a[mt][3] = __float_as_uint(cA[(r + 8) * 36 + ks + t + 4]);
            }
#pragma unroll
            for (int nt = 0; nt < 8; nt++) {
                int n = wn * 64 + nt * 8 + g;
                b[nt][0] = __float_as_uint(cB[(ks + t) * 516 + n]);
                b[nt][1] = __float_as_uint(cB[(ks + t + 4) * 516 + n]);
            }
#pragma unroll
            for (int mt = 0; mt < 2; mt++)
#pragma unroll
                for (int nt = 0; nt < 8; nt++) mma8(c[mt][nt], a[mt], b[nt]);
        }
        if (kt + 1 < T)
            *(float4*)&sA[bn * 64 * 36 + ar * 36 + af] = a0;
        cp_wait0(); __syncthreads();
    }

#pragma unroll
    for (int mt = 0; mt < 2; mt++)
#pragma unroll
        for (int h = 0; h < 2; h++) {
            int row = R0 + wm * 32 + mt * 16 + g + 8 * h;
#pragma unroll
            for (int nt = 0; nt < 8; nt++) {
                int col = wn * 64 + nt * 8 + 2 * t;
                *(float2*)&g_uv[(size_t)row * 512 + col] =
                    make_float2(c[mt][nt][2 * h], c[mt][nt][2 * h + 1]);
            }
        }
}

// ---------------------------------------------------------------------------
// Kernel 3: build core rows, ctx+att GEMMs, effect reduction. Pipelined B.
// block = 112 pair-rows, 448 threads, warps 7 row x 2 col
// ---------------------------------------------------------------------------
__global__ __launch_bounds__(448, 1) void k_eff(
    const float* __restrict__ core_b, const float* __restrict__ core_g,
    const float* __restrict__ core_bb,
    const float* __restrict__ ctx_b,
    const float* __restrict__ ctx_g, const float* __restrict__ ctx_bb,
    const float* __restrict__ a1_b,
    const float* __restrict__ att_g, const float* __restrict__ att_bb,
    const float* __restrict__ a2W,  const float* __restrict__ a2_b)
{
    extern __shared__ float sm[];
    float*  sA   = sm;                          // [112][260]  core rows (tf32)
    float*  sB   = sA + 112 * 260;              // 2 x [32][260]
    float*  sEff = sB + 2 * 32 * 260;           // [16][257]
    float2* sRed = (float2*)(sEff + 16 * 257);  // [2][112]
    float*  sDot = (float*)(sRed + 2 * 112);    // [2][112]
    float*  sAtt = sDot + 2 * 112;              // [112]

    const int tid = threadIdx.x;
    const int wid = tid >> 5, lane = tid & 31;
    const int g = lane >> 2, t = lane & 3;
    const int wm = wid % 7, wn = wid / 7;
    const int R0 = blockIdx.x * 112;

    // prefetch att1 weight tile 0 while building core rows
    for (int idx = tid; idx < 32 * 32; idx += 448) {
        int kk = idx >> 5, n4 = (idx & 31) * 4;
        cpa16(&sB[kk * 132 + n4], &g_watt[(size_t)kk * LASTN + n4]);
    }
    cp_commit();

    for (int idx = tid; idx < 16 * 257; idx += 448) sEff[idx] = 0.f;

    // ---- phase a: core rows = relu(LN(U[p]+V[q]+core_b)) into sA ----
    {
        float cb[8], cg[8], cbb[8];
#pragma unroll
        for (int e = 0; e < 8; e++) {
            int col = lane + 32 * e;
            cb[e] = core_b[col]; cg[e] = core_g[col]; cbb[e] = core_bb[col];
        }
#pragma unroll
        for (int rr = 0; rr < 8; rr++) {
            int lrow = wid * 8 + rr;
            int v = R0 + lrow;
            int p = v / 7;
            int jj = v - p * 7;
            int i = p & 7;
            int j = jj + (jj >= i ? 1 : 0);
            int q = (p & ~7) + j;
            float val[8], s = 0.f, s2 = 0.f;
#pragma unroll
            for (int e = 0; e < 8; e++) {
                int col = lane + 32 * e;
                val[e] = g_uv[(size_t)p * 512 + col] + g_uv[(size_t)q * 512 + 256 + col] + cb[e];
                s += val[e]; s2 += val[e] * val[e];
            }
#pragma unroll
            for (int o = 16; o; o >>= 1) {
                s  += __shfl_xor_sync(~0u, s,  o);
                s2 += __shfl_xor_sync(~0u, s2, o);
            }
            float mu = s * (1.f / FCN);
            float rs = rsqrtf(s2 * (1.f / FCN) - mu * mu + 1e-5f);
#pragma unroll
            for (int e = 0; e < 8; e++) {
                float o2 = fmaxf((val[e] - mu) * rs * cg[e] + cbb[e], 0.f);
                sA[lrow * 260 + lane + 32 * e] = to_tf32(o2);
            }
        }
    }
    cp_wait0(); __syncthreads();

    // ---- pass 1: attention  (N=128, col-warp owns 64) ----
    {
        float ca[8][4];
#pragma unroll
        for (int nt = 0; nt < 8; nt++)
#pragma unroll
            for (int e = 0; e < 4; e++) ca[nt][e] = 0.f;

        const int T = FCN / 32;
        for (int kt = 0; kt < T; kt++) {
            const int bt = kt & 1, bn = bt ^ 1;
            float* cB = sB + bt * 32 * 260;
            if (kt + 1 < T) {
                float* nB = sB + bn * 32 * 260;
                for (int idx = tid; idx < 32 * 32; idx += 448) {
                    int kk = idx >> 5, n4 = (idx & 31) * 4;
                    cpa16(&nB[kk * 132 + n4],
                          &g_watt[(size_t)((kt + 1) * 32 + kk) * LASTN + n4]);
                }
                cp_commit();
            } else {
                // prefetch ctx weight tile 0 into the other buffer
                float* nB = sB + bn * 32 * 260;
                for (int idx = tid; idx < 32 * 64; idx += 448) {
                    int kk = idx >> 6, n4 = (idx & 63) * 4;
                    cpa16(&nB[kk * 260 + n4], &g_wctx[(size_t)kk * FCN + n4]);
                }
                cp_commit();
            }
#pragma unroll
            for (int ks = 0; ks < 32; ks += 8) {
                unsigned a[4], b[8][2];
                int r = wm * 16 + g;
                a[0] = __float_as_uint(sA[r * 260 + kt * 32 + ks + t]);
                a[1] = __float_as_uint(sA[(r + 8) * 260 + kt * 32 + ks + t]);
                a[2] = __float_as_uint(sA[r * 260 + kt * 32 + ks + t + 4]);
                a[3] = __float_as_uint(sA[(r + 8) * 260 + kt * 32 + ks + t + 4]);
#pragma unroll
                for (int nt = 0; nt < 8; nt++) {
                    int n = wn * 64 + nt * 8 + g;
                    b[nt][0] = __float_as_uint(cB[(ks + t) * 132 + n]);
                    b[nt][1] = __float_as_uint(cB[(ks + t + 4) * 132 + n]);
                }
#pragma unroll
                for (int nt = 0; nt < 8; nt++) mma8(ca[nt], a, b[nt]);
            }
            cp_wait0(); __syncthreads();
        }
        // epilogue: LN(128) -> tanh -> dot(att2_w) -> sigmoid
#pragma unroll
        for (int nt = 0; nt < 8; nt++) {
            int col = wn * 64 + nt * 8 + 2 * t;
            float b0 = __ldg(&a1_b[col]), b1 = __ldg(&a1_b[col + 1]);
            ca[nt][0] += b0; ca[nt][1] += b1; ca[nt][2] += b0; ca[nt][3] += b1;
        }
        float s0 = 0, q0 = 0, s1v = 0, q1 = 0;
#pragma unroll
        for (int nt = 0; nt < 8; nt++) {
            s0 += ca[nt][0] + ca[nt][1];
            q0 += ca[nt][0] * ca[nt][0] + ca[nt][1] * ca[nt][1];
            s1v += ca[nt][2] + ca[nt][3];
            q1 += ca[nt][2] * ca[nt][2] + ca[nt][3] * ca[nt][3];
        }
#pragma unroll
        for (int o = 1; o <= 2; o <<= 1) {
            s0 += __shfl_xor_sync(~0u, s0, o); q0 += __shfl_xor_sync(~0u, q0, o);
            s1v += __shfl_xor_sync(~0u, s1v, o); q1 += __shfl_xor_sync(~0u, q1, o);
        }
        if (t == 0) {
            sRed[wn * 112 + wm * 16 + g]     = make_float2(s0, q0);
            sRed[wn * 112 + wm * 16 + g + 8] = make_float2(s1v, q1);
        }
        __syncthreads();
        float d0 = 0.f, d1 = 0.f;
        {
            int r0 = wm * 16 + g, r1 = r0 + 8;
            float2 p0 = sRed[r0], p0b = sRed[112 + r0];
            float2 p1 = sRed[r1], p1b = sRed[112 + r1];
            float su0 = p0.x + p0b.x, sq0 = p0.y + p0b.y;
            float su1 = p1.x + p1b.x, sq1 = p1.y + p1b.y;
            float mu0 = su0 * (1.f / LASTN);
            float rs0 = rsqrtf(sq0 * (1.f / LASTN) - mu0 * mu0 + 1e-5f);
            float mu1 = su1 * (1.f / LASTN);
            float rs1 = rsqrtf(sq1 * (1.f / LASTN) - mu1 * mu1 + 1e-5f);
#pragma unroll
            for (int nt = 0; nt < 8; nt++) {
                int col = wn * 64 + nt * 8 + 2 * t;
                float gg0 = __ldg(&att_g[col]),  bb0 = __ldg(&att_bb[col]),  w0 = __ldg(&a2W[col]);
                float gg1 = __ldg(&att_g[col+1]), bb1 = __ldg(&att_bb[col+1]), w1 = __ldg(&a2W[col+1]);
                d0 += tanhf((ca[nt][0] - mu0) * rs0 * gg0 + bb0) * w0;
                d0 += tanhf((ca[nt][1] - mu0) * rs0 * gg1 + bb1) * w1;
                d1 += tanhf((ca[nt][2] - mu1) * rs1 * gg0 + bb0) * w0;
                d1 += tanhf((ca[nt][3] - mu1) * rs1 * gg1 + bb1) * w1;
            }
        }
#pragma unroll
        for (int o = 1; o <= 2; o <<= 1) {
            d0 += __shfl_xor_sync(~0u, d0, o);
            d1 += __shfl_xor_sync(~0u, d1, o);
        }
        if (t == 0) {
            sDot[wn * 112 + wm * 16 + g]     = d0;
            sDot[wn * 112 + wm * 16 + g + 8] = d1;
        }
        __syncthreads();
        if (wn == 0 && t == 0) {
            float a2b = __ldg(&a2_b[0]);
            int r0 = wm * 16 + g;
            sAtt[r0]     = 1.f / (1.f + expf(-(sDot[r0]     + sDot[112 + r0]     + a2b)));
            sAtt[r0 + 8] = 1.f / (1.f + expf(-(sDot[r0 + 8] + sDot[112 + r0 + 8] + a2b)));
        }
        __syncthreads();
    }

    // ---- pass 2: ctx (N=256, col-warp owns 128) + effect reduction ----
    // pass1's last iteration prefetched ctx tile 0 into buffer (T&1)^1... = buffer 0? 
    // pass1 T=8, last kt=7, bt=1, bn=0 -> ctx tile0 sits in buffer 0. Good.
    {
        float cc[16][4];
#pragma unroll
        for (int nt = 0; nt < 16; nt++)
#pragma unroll
            for (int e = 0; e < 4; e++) cc[nt][e] = 0.f;

        const int T = FCN / 32;
        for (int kt = 0; kt < T; kt++) {
            const int bt = kt & 1, bn = bt ^ 1;
            float* cB = sB + bt * 32 * 260;
            if (kt + 1 < T) {
                float* nB = sB + bn * 32 * 260;
                for (int idx = tid; idx < 32 * 64; idx += 448) {
                    int kk = idx >> 6, n4 = (idx & 63) * 4;
                    cpa16(&nB[kk * 260 + n4],
                          &g_wctx[(size_t)((kt + 1) * 32 + kk) * FCN + n4]);
                }
                cp_commit();
            }
#pragma unroll
            for (int ks = 0; ks < 32; ks += 8) {
                unsigned a[4], b[16][2];
                int r = wm * 16 + g;
                a[0] = __float_as_uint(sA[r * 260 + kt * 32 + ks + t]);
                a[1] = __float_as_uint(sA[(r + 8) * 260 + kt * 32 + ks + t]);
                a[2] = __float_as_uint(sA[r * 260 + kt * 32 + ks + t + 4]);
                a[3] = __float_as_uint(sA[(r + 8) * 260 + kt * 32 + ks + t + 4]);
#pragma unroll
                for (int nt = 0; nt < 16; nt++) {
                    int n = wn * 128 + nt * 8 + g;
                    b[nt][0] = __float_as_uint(cB[(ks + t) * 260 + n]);
                    b[nt][1] = __float_as_uint(cB[(ks + t + 4) * 260 + n]);
                }
#pragma unroll
                for (int nt = 0; nt < 16; nt++) mma8(cc[nt], a, b[nt]);
            }
            cp_wait0(); __syncthreads();
        }
        // epilogue: LN + relu, scale by att, accumulate effect per group
#pragma unroll
        for (int nt = 0; nt < 16; nt++) {
            int col = wn * 128 + nt * 8 + 2 * t;
            float b0 = __ldg(&ctx_b[col]), b1 = __ldg(&ctx_b[col + 1]);
            cc[nt][0] += b0; cc[nt][1] += b1; cc[nt][2] += b0; cc[nt][3] += b1;
        }
        float s0 = 0, q0 = 0, s1v = 0, q1 = 0;
#pragma unroll
        for (int nt = 0; nt < 16; nt++) {
            s0 += cc[nt][0] + cc[nt][1];
            q0 += cc[nt][0] * cc[nt][0] + cc[nt][1] * cc[nt][1];
            s1v += cc[nt][2] + cc[nt][3];
            q1 += cc[nt][2] * cc[nt][2] + cc[nt][3] * cc[nt][3];
        }
#pragma unroll
        for (int o = 1; o <= 2; o <<= 1) {
            s0 += __shfl_xor_sync(~0u, s0, o); q0 += __shfl_xor_sync(~0u, q0, o);
            s1v += __shfl_xor_sync(~0u, s1v, o); q1 += __shfl_xor_sync(~0u, q1, o);
        }
        if (t == 0) {
            sRed[wn * 112 + wm * 16 + g]     = make_float2(s0, q0);
            sRed[wn * 112 + wm * 16 + g + 8] = make_float2(s1v, q1);
        }
        __syncthreads();
        {
            int r0 = wm * 16 + g, r1 = r0 + 8;
            float2 p0 = sRed[r0], p0b = sRed[112 + r0];
            float2 p1 = sRed[r1], p1b = sRed[112 + r1];
            float mu0 = (p0.x + p0b.x) * (1.f / FCN);
            float rs0 = rsqrtf((p0.y + p0b.y) * (1.f / FCN) - mu0 * mu0 + 1e-5f);
            float mu1 = (p1.x + p1b.x) * (1.f / FCN);
            float rs1 = rsqrtf((p1.y + p1b.y) * (1.f / FCN) - mu1 * mu1 + 1e-5f);
            float at0 = sAtt[r0], at1 = sAtt[r1];
            int gl0 = (R0 + r0) / 7 - blockIdx.x * 16;
            int gl1 = (R0 + r1) / 7 - blockIdx.x * 16;
#pragma unroll
            for (int nt = 0; nt < 16; nt++) {
                int col = wn * 128 + nt * 8 + 2 * t;
                float gg0 = __ldg(&ctx_g[col]),  bb0 = __ldg(&ctx_bb[col]);
                float gg1 = __ldg(&ctx_g[col+1]), bb1 = __ldg(&ctx_bb[col+1]);
                float v00 = fmaxf((cc[nt][0] - mu0) * rs0 * gg0 + bb0, 0.f) * at0;
                float v01 = fmaxf((cc[nt][1] - mu0) * rs0 * gg1 + bb1, 0.f) * at0;
                float v10 = fmaxf((cc[nt][2] - mu1) * rs1 * gg0 + bb0, 0.f) * at1;
                float v11 = fmaxf((cc[nt][3] - mu1) * rs1 * gg1 + bb1, 0.f) * at1;
                atomicAdd(&sEff[gl0 * 257 + col],     v00);
                atomicAdd(&sEff[gl0 * 257 + col + 1], v01);
                atomicAdd(&sEff[gl1 * 257 + col],     v10);
                atomicAdd(&sEff[gl1 * 257 + col + 1], v11);
            }
        }
    }
    __syncthreads();
    for (int idx = tid; idx < 16 * FCN; idx += 448) {
        int gg = idx >> 8, col = idx & 255;
        g_eff[(size_t)(blockIdx.x * 16 + gg) * FCN + col] = to_tf32(sEff[gg * 257 + col]);
    }
}

// ---------------------------------------------------------------------------
// Kernel 4: new_state = concat(s1, effect, x) @ out_w + out_b
// M=16384 K=1536 N=256, block 128x256, 16 warps (4x4), pipelined
// ---------------------------------------------------------------------------
__global__ __launch_bounds__(512, 1) void k_out(
    const float* __restrict__ xin, const float* __restrict__ bias,
    float* __restrict__ out, int dup)
{
    extern __shared__ float sm[];
    float* sA = sm;                 // 2 x [128][36]
    float* sB = sm + 2 * 128 * 36;  // 2 x [32][260]

    const int tid = threadIdx.x;
    const int wid = tid >> 5, lane = tid & 31;
    const int g = lane >> 2, t = lane & 3;
    const int wm = wid & 3, wn = wid >> 2;
    const int R0 = blockIdx.x * 128;

    const int ar0 = (tid) >> 3,        af0 = ((tid) & 7) * 4;
    const int ar1 = (tid + 512) >> 3,  af1 = ((tid + 512) & 7) * 4;

    float c[2][8][4];
#pragma unroll
    for (int mt = 0; mt < 2; mt++)
#pragma unroll
        for (int nt = 0; nt < 8; nt++)
#pragma unroll
            for (int e = 0; e < 4; e++) c[mt][nt][e] = 0.f;

    // A loader: sources already tf32-rounded except xin (convert flag)
    auto ldA = [&](int kt, float4& v0, float4& v1, bool& cvt) {
        int base = kt * 32;
        if (base < FCN) {
            v0 = *(const float4*)&g_s1[(size_t)(R0 + ar0) * FCN + base + af0];
            v1 = *(const float4*)&g_s1[(size_t)(R0 + ar1) * FCN + base + af1];
            cvt = false;
        } else if (base < 2 * FCN) {
            v0 = *(const float4*)&g_eff[(size_t)(R0 + ar0) * FCN + base - FCN + af0];
            v1 = *(const float4*)&g_eff[(size_t)(R0 + ar1) * FCN + base - FCN + af1];
            cvt = false;
        } else {
            v0 = *(const float4*)&xin[(size_t)(R0 + ar0) * MDIM + base - 2 * FCN + af0];
            v1 = *(const float4*)&xin[(size_t)(R0 + ar1) * MDIM + base - 2 * FCN + af1];
            cvt = true;
        }
    };
    auto stA = [&](float* buf, float4 v0, float4 v1, bool cvt) {
        float* d0 = &buf[ar0 * 36 + af0];
        float* d1 = &buf[ar1 * 36 + af1];
        if (cvt) {
            d0[0]=to_tf32(v0.x); d0[1]=to_tf32(v0.y); d0[2]=to_tf32(v0.z); d0[3]=to_tf32(v0.w);
            d1[0]=to_tf32(v1.x); d1[1]=to_tf32(v1.y); d1[2]=to_tf32(v1.z); d1[3]=to_tf32(v1.w);
        } else {
            *(float4*)d0 = v0; *(float4*)d1 = v1;
        }
    };

    float4 a0, a1; bool cvt;
    ldA(0, a0, a1, cvt);
    stA(sA, a0, a1, cvt);
#pragma unroll
    for (int p = 0; p < 4; p++) {
        int idx = tid + 512 * p;
        int kk = idx >> 6, n4 = (idx & 63) * 4;
        cpa16(&sB[kk * 260 + n4], &g_wout[(size_t)kk * FCN + n4]);
    }
    cp_commit(); cp_wait0(); __syncthreads();

    const int T = KOUT / 32;
    for (int kt = 0; kt < T; kt++) {
        const int bt = kt & 1, bn = bt ^ 1;
        float* cA = sA + bt * 128 * 36;
        float* cB = sB + bt * 32 * 260;
        if (kt + 1 < T) {
            float* nB = sB + bn * 32 * 260;
#pragma unroll
            for (int p = 0; p < 4; p++) {
                int idx = tid + 512 * p;
                int kk = idx >> 6, n4 = (idx & 63) * 4;
                cpa16(&nB[kk * 260 + n4], &g_wout[(size_t)((kt + 1) * 32 + kk) * FCN + n4]);
            }
            cp_commit();
            ldA(kt + 1, a0, a1, cvt);
        }
#pragma unroll
        for (int ks = 0; ks < 32; ks += 8) {
            unsigned a[2][4], b[8][2];
#pragma unroll
            for (int mt = 0; mt < 2; mt++) {
                int r = wm * 32 + mt * 16 + g;
                a[mt][0] = __float_as_uint(cA[r * 36 + ks + t]);
                a[mt][1] = __float_as_uint(cA[(r + 8) * 36 + ks + t]);
                a[mt][2] = __float_as_uint(cA[r * 36 + ks + t + 4]);
                a[mt][3] = __float_as_uint(cA[(r + 8) * 36 + ks + t + 4]);
            }
#pragma unroll
            for (int nt = 0; nt < 8; nt++) {
                int n = wn * 64 + nt * 8 + g;
                b[nt][0] = __float_as_uint(cB[(ks + t) * 260 + n]);
                b[nt][1] = __float_as_uint(cB[(ks + t + 4) * 260 + n]);
            }
#pragma unroll
            for (int mt = 0; mt < 2; mt++)
#pragma unroll
                for (int nt = 0; nt < 8; nt++) mma8(c[mt][nt], a[mt], b[nt]);
        }
        if (kt + 1 < T)
            stA(sA + bn * 128 * 36, a0, a1, cvt);
        cp_wait0(); __syncthreads();
    }

#pragma unroll
    for (int mt = 0; mt < 2; mt++)
#pragma unroll
        for (int h = 0; h < 2; h++) {
            int row = R0 + wm * 32 + mt * 16 + g + 8 * h;
#pragma unroll
            for (int nt = 0; nt < 8; nt++) {
                int col = wn * 64 + nt * 8 + 2 * t;
                float o0 = c[mt][nt][2 * h]     + __ldg(&bias[col]);
                float o1 = c[mt][nt][2 * h + 1] + __ldg(&bias[col + 1]);
                size_t off = (size_t)row * FCN + col;
                *(float2*)&out[off] = make_float2(o0, o1);
                if (dup) *(float2*)&out[(size_t)NR1 * FCN + off] = make_float2(o0, o1);
            }
        }
}

// ---------------------------------------------------------------------------
extern "C" void kernel_launch(void* const* d_in, const int* in_sizes, int n_in,
                              void* d_out, int out_size) {
    const float* x      = (const float*)d_in[0];
    const float* state  = (const float*)d_in[1];
    const float* enc_w  = (const float*)d_in[2];
    const float* enc_b  = (const float*)d_in[3];
    const float* enc_g  = (const float*)d_in[4];
    const float* enc_bb = (const float*)d_in[5];
    const float* core_w = (const float*)d_in[6];
    const float* core_b = (const float*)d_in[7];
    const float* core_g = (const float*)d_in[8];
    const float* core_bb= (const float*)d_in[9];
    const float* ctx_w  = (const float*)d_in[10];
    const float* ctx_b  = (const float*)d_in[11];
    const float* ctx_g  = (const float*)d_in[12];
    const float* ctx_bb = (const float*)d_in[13];
    const float* att1_w = (const float*)d_in[14];
    const float* att1_b = (const float*)d_in[15];
    const float* att_g  = (const float*)d_in[16];
    const float* att_bb = (const float*)d_in[17];
    const float* att2_w = (const float*)d_in[18];
    const float* att2_b = (const float*)d_in[19];
    const float* out_w  = (const float*)d_in[20];
    const float* out_b  = (const float*)d_in[21];
    float* out = (float*)d_out;
    int dup = (out_size >= 2 * NR1 * FCN) ? 1 : 0;

    const int smem_enc = (2 * 128 * 36 + 2 * 32 * 260) * 4 + 4 * 128 * 8;
    const int smem_uv  = (2 * 64 * 36 + 2 * 32 * 516) * 4;
    const int smem_eff = (112 * 260 + 2 * 32 * 260 + 16 * 257 + 2 * 112 * 2 + 2 * 112 + 112) * 4;
    const int smem_out = (2 * 128 * 36 + 2 * 32 * 260) * 4;

    static int attr_done = 0;
    if (!attr_done) {
        cudaFuncSetAttribute(k_enc, cudaFuncAttributeMaxDynamicSharedMemorySize, smem_enc);
        cudaFuncSetAttribute(k_uv,  cudaFuncAttributeMaxDynamicSharedMemorySize, smem_uv);
        cudaFuncSetAttribute(k_eff, cudaFuncAttributeMaxDynamicSharedMemorySize, smem_eff);
        cudaFuncSetAttribute(k_out, cudaFuncAttributeMaxDynamicSharedMemorySize, smem_out);
        attr_done = 1;
    }

    k_cvtw<<<256, 256>>>(enc_w, core_w, ctx_w, att1_w, out_w);
    k_enc<<<NR1 / 128, 512, smem_enc>>>(state, enc_b, enc_g, enc_bb);
    k_uv <<<NR1 / 64,  512, smem_uv >>>();
    k_eff<<<NR2 / 112, 448, smem_eff>>>(core_b, core_g, core_bb,
                                        ctx_b, ctx_g, ctx_bb,
                                        att1_b, att_g, att_bb,
                                        att2_w, att2_b);
    k_out<<<NR1 / 128, 512, smem_out>>>(x, out_b, out, dup);
}

// round 6
// speedup vs baseline: 4.0256x; 1.1864x over previous
#include <cuda_runtime.h>
#include <cstdint>
#include <math.h>

// ---------------------------------------------------------------------------
// R-NEM cell, tf32 tensor-core pipeline, cp.async double-buffered mainloops.
//   K=8, FC=256, LAST=128, B=2048, M=1024, H=512
//   rows1 = 16384, rows2 = 114688
// core_pre[v] = U[p] + V[q] + core_b, [U|V] = s1 @ core_w (packed k-major)
// R6: conflict-free smem strides (264/520), k_eff rebuilt as 4x4 warp grid
//     (M=32 per warp) on a 128-row padded tile -> 3x less LDS per FLOP.
// ---------------------------------------------------------------------------

#define FCN   256
#define LASTN 128
#define HDIM  512
#define MDIM  1024
#define NR1   16384
#define NR2   114688
#define KOUT  (2 * FCN + MDIM)

__device__ float g_s1[NR1 * FCN];        // tf32-rounded
__device__ float g_uv[NR1 * 2 * FCN];    // fp32
__device__ float g_eff[NR1 * FCN];       // tf32-rounded

// pre-converted (tf32) weights
__device__ float g_wenc[HDIM * FCN];
__device__ float g_wuv[FCN * 2 * FCN];   // packed: [k][512] = [Wtop | Wbot]
__device__ float g_wctx[FCN * FCN];
__device__ float g_watt[FCN * LASTN];
__device__ float g_wout[KOUT * FCN];

// -------------------------------- helpers ---------------------------------
__device__ __forceinline__ float to_tf32(float x) {
    unsigned u; asm("cvt.rna.tf32.f32 %0, %1;" : "=r"(u) : "f"(x));
    return __uint_as_float(u);
}
__device__ __forceinline__ void mma8(float* c, const unsigned* a, const unsigned* b) {
    asm volatile(
        "mma.sync.aligned.m16n8k8.row.col.f32.tf32.tf32.f32 "
        "{%0,%1,%2,%3}, {%4,%5,%6,%7}, {%8,%9}, {%0,%1,%2,%3};"
        : "+f"(c[0]), "+f"(c[1]), "+f"(c[2]), "+f"(c[3])
        : "r"(a[0]), "r"(a[1]), "r"(a[2]), "r"(a[3]), "r"(b[0]), "r"(b[1]));
}
__device__ __forceinline__ void cpa16(float* dst, const float* src) {
    unsigned d = (unsigned)__cvta_generic_to_shared(dst);
    asm volatile("cp.async.cg.shared.global [%0], [%1], 16;" :: "r"(d), "l"(src));
}
__device__ __forceinline__ void cp_commit() { asm volatile("cp.async.commit_group;"); }
__device__ __forceinline__ void cp_wait0()  { asm volatile("cp.async.wait_group 0;"); }

#define LDB 264   // B tile stride: bank = 8t+g, conflict-free
#define LDB2 520  // 512-wide B tile stride
#define LDBA 136  // 128-wide B tile stride
#define LDSA 264  // k_eff A tile stride

// ---------------------------------------------------------------------------
// Kernel 0: convert/pack weights to tf32
// ---------------------------------------------------------------------------
__global__ void k_cvtw(const float* __restrict__ enc_w, const float* __restrict__ core_w,
                       const float* __restrict__ ctx_w, const float* __restrict__ att1_w,
                       const float* __restrict__ out_w)
{
    int i = blockIdx.x * blockDim.x + threadIdx.x;
    int n = gridDim.x * blockDim.x;
    for (int idx = i; idx < HDIM * FCN; idx += n) g_wenc[idx] = to_tf32(enc_w[idx]);
    for (int idx = i; idx < FCN * 2 * FCN; idx += n) {
        int k = idx >> 9, c = idx & 511;
        float v = (c < FCN) ? core_w[k * FCN + c] : core_w[(FCN + k) * FCN + (c - FCN)];
        g_wuv[idx] = to_tf32(v);
    }
    for (int idx = i; idx < FCN * FCN; idx += n) g_wctx[idx] = to_tf32(ctx_w[idx]);
    for (int idx = i; idx < FCN * LASTN; idx += n) g_watt[idx] = to_tf32(att1_w[idx]);
    for (int idx = i; idx < KOUT * FCN; idx += n) g_wout[idx] = to_tf32(out_w[idx]);
}

// ---------------------------------------------------------------------------
// Kernel 1: s1 = relu(LN(state @ enc_w + enc_b))    M=16384 K=512 N=256
// ---------------------------------------------------------------------------
__global__ __launch_bounds__(512, 1) void k_enc(
    const float* __restrict__ state, const float* __restrict__ bias,
    const float* __restrict__ gam, const float* __restrict__ bet)
{
    extern __shared__ float sm[];
    float*  sA  = sm;                            // 2 x [128][36]
    float*  sB  = sm + 2 * 128 * 36;             // 2 x [32][LDB]
    float2* red = (float2*)(sB + 2 * 32 * LDB);  // [4][128]

    const int tid = threadIdx.x;
    const int wid = tid >> 5, lane = tid & 31;
    const int g = lane >> 2, t = lane & 3;
    const int wm = wid & 3, wn = wid >> 2;
    const int R0 = blockIdx.x * 128;

    const int ar0 = (tid) >> 3,        af0 = ((tid) & 7) * 4;
    const int ar1 = (tid + 512) >> 3,  af1 = ((tid + 512) & 7) * 4;

    float c[2][8][4];
#pragma unroll
    for (int mt = 0; mt < 2; mt++)
#pragma unroll
        for (int nt = 0; nt < 8; nt++)
#pragma unroll
            for (int e = 0; e < 4; e++) c[mt][nt][e] = 0.f;

    float4 a0, a1;
    a0 = *(const float4*)&state[(size_t)(R0 + ar0) * HDIM + af0];
    a1 = *(const float4*)&state[(size_t)(R0 + ar1) * HDIM + af1];
    {
        float* d0 = &sA[ar0 * 36 + af0];
        d0[0]=to_tf32(a0.x); d0[1]=to_tf32(a0.y); d0[2]=to_tf32(a0.z); d0[3]=to_tf32(a0.w);
        float* d1 = &sA[ar1 * 36 + af1];
        d1[0]=to_tf32(a1.x); d1[1]=to_tf32(a1.y); d1[2]=to_tf32(a1.z); d1[3]=to_tf32(a1.w);
    }
#pragma unroll
    for (int p = 0; p < 4; p++) {
        int idx = tid + 512 * p;
        int kk = idx >> 6, n4 = (idx & 63) * 4;
        cpa16(&sB[kk * LDB + n4], &g_wenc[(size_t)kk * FCN + n4]);
    }
    cp_commit(); cp_wait0(); __syncthreads();

    const int T = HDIM / 32;
    for (int kt = 0; kt < T; kt++) {
        const int bt = kt & 1, bn = bt ^ 1;
        float* cA = sA + bt * 128 * 36;
        float* cB = sB + bt * 32 * LDB;
        if (kt + 1 < T) {
            float* nB = sB + bn * 32 * LDB;
#pragma unroll
            for (int p = 0; p < 4; p++) {
                int idx = tid + 512 * p;
                int kk = idx >> 6, n4 = (idx & 63) * 4;
                cpa16(&nB[kk * LDB + n4], &g_wenc[(size_t)((kt + 1) * 32 + kk) * FCN + n4]);
            }
            cp_commit();
            a0 = *(const float4*)&state[(size_t)(R0 + ar0) * HDIM + (kt + 1) * 32 + af0];
            a1 = *(const float4*)&state[(size_t)(R0 + ar1) * HDIM + (kt + 1) * 32 + af1];
        }
#pragma unroll
        for (int ks = 0; ks < 32; ks += 8) {
            unsigned a[2][4], b[8][2];
#pragma unroll
            for (int mt = 0; mt < 2; mt++) {
                int r = wm * 32 + mt * 16 + g;
                a[mt][0] = __float_as_uint(cA[r * 36 + ks + t]);
                a[mt][1] = __float_as_uint(cA[(r + 8) * 36 + ks + t]);
                a[mt][2] = __float_as_uint(cA[r * 36 + ks + t + 4]);
                a[mt][3] = __float_as_uint(cA[(r + 8) * 36 + ks + t + 4]);
            }
#pragma unroll
            for (int nt = 0; nt < 8; nt++) {
                int n = wn * 64 + nt * 8 + g;
                b[nt][0] = __float_as_uint(cB[(ks + t) * LDB + n]);
                b[nt][1] = __float_as_uint(cB[(ks + t + 4) * LDB + n]);
            }
#pragma unroll
            for (int mt = 0; mt < 2; mt++)
#pragma unroll
                for (int nt = 0; nt < 8; nt++) mma8(c[mt][nt], a[mt], b[nt]);
        }
        if (kt + 1 < T) {
            float* nA = sA + bn * 128 * 36;
            float* d0 = &nA[ar0 * 36 + af0];
            d0[0]=to_tf32(a0.x); d0[1]=to_tf32(a0.y); d0[2]=to_tf32(a0.z); d0[3]=to_tf32(a0.w);
            float* d1 = &nA[ar1 * 36 + af1];
            d1[0]=to_tf32(a1.x); d1[1]=to_tf32(a1.y); d1[2]=to_tf32(a1.z); d1[3]=to_tf32(a1.w);
        }
        cp_wait0(); __syncthreads();
    }

#pragma unroll
    for (int nt = 0; nt < 8; nt++) {
        int col = wn * 64 + nt * 8 + 2 * t;
        float b0 = __ldg(&bias[col]), b1 = __ldg(&bias[col + 1]);
#pragma unroll
        for (int mt = 0; mt < 2; mt++) {
            c[mt][nt][0] += b0; c[mt][nt][1] += b1;
            c[mt][nt][2] += b0; c[mt][nt][3] += b1;
        }
    }
#pragma unroll
    for (int mt = 0; mt < 2; mt++) {
        float s0 = 0, q0 = 0, s1v = 0, q1 = 0;
#pragma unroll
        for (int nt = 0; nt < 8; nt++) {
            s0 += c[mt][nt][0] + c[mt][nt][1];
            q0 += c[mt][nt][0] * c[mt][nt][0] + c[mt][nt][1] * c[mt][nt][1];
            s1v += c[mt][nt][2] + c[mt][nt][3];
            q1 += c[mt][nt][2] * c[mt][nt][2] + c[mt][nt][3] * c[mt][nt][3];
        }
#pragma unroll
        for (int o = 1; o <= 2; o <<= 1) {
            s0 += __shfl_xor_sync(~0u, s0, o); q0 += __shfl_xor_sync(~0u, q0, o);
            s1v += __shfl_xor_sync(~0u, s1v, o); q1 += __shfl_xor_sync(~0u, q1, o);
        }
        if (t == 0) {
            red[wn * 128 + wm * 32 + mt * 16 + g]     = make_float2(s0, q0);
            red[wn * 128 + wm * 32 + mt * 16 + g + 8] = make_float2(s1v, q1);
        }
    }
    __syncthreads();
#pragma unroll
    for (int mt = 0; mt < 2; mt++)
#pragma unroll
        for (int h = 0; h < 2; h++) {
            int row = wm * 32 + mt * 16 + g + 8 * h;
            float s = 0, q = 0;
#pragma unroll
            for (int w2 = 0; w2 < 4; w2++) {
                float2 r2 = red[w2 * 128 + row]; s += r2.x; q += r2.y;
            }
            float mu = s * (1.f / FCN);
            float rs = rsqrtf(q * (1.f / FCN) - mu * mu + 1e-5f);
#pragma unroll
            for (int nt = 0; nt < 8; nt++) {
                int col = wn * 64 + nt * 8 + 2 * t;
                float o0 = fmaxf((c[mt][nt][2 * h]     - mu) * rs * __ldg(&gam[col])     + __ldg(&bet[col]),     0.f);
                float o1 = fmaxf((c[mt][nt][2 * h + 1] - mu) * rs * __ldg(&gam[col + 1]) + __ldg(&bet[col + 1]), 0.f);
                *(float2*)&g_s1[(size_t)(R0 + row) * FCN + col] =
                    make_float2(to_tf32(o0), to_tf32(o1));
            }
        }
}

// ---------------------------------------------------------------------------
// Kernel 2: [U|V] = s1 @ packed(core_w)   M=16384 K=256 N=512
// ---------------------------------------------------------------------------
__global__ __launch_bounds__(512, 1) void k_uv()
{
    extern __shared__ float sm[];
    float* sA = sm;                   // 2 x [64][36]
    float* sB = sm + 2 * 64 * 36;     // 2 x [32][LDB2]

    const int tid = threadIdx.x;
    const int wid = tid >> 5, lane = tid & 31;
    const int g = lane >> 2, t = lane & 3;
    const int wm = wid & 1, wn = wid >> 1;
    const int R0 = blockIdx.x * 64;
    const int ar = tid >> 3, af = (tid & 7) * 4;

    float c[2][8][4];
#pragma unroll
    for (int mt = 0; mt < 2; mt++)
#pragma unroll
        for (int nt = 0; nt < 8; nt++)
#pragma unroll
            for (int e = 0; e < 4; e++) c[mt][nt][e] = 0.f;

    float4 a0;
    a0 = *(const float4*)&g_s1[(size_t)(R0 + ar) * FCN + af];
    *(float4*)&sA[ar * 36 + af] = a0;
#pragma unroll
    for (int p = 0; p < 8; p++) {
        int idx = tid + 512 * p;
        int kk = idx >> 7, n4 = (idx & 127) * 4;
        cpa16(&sB[kk * LDB2 + n4], &g_wuv[(size_t)kk * 512 + n4]);
    }
    cp_commit(); cp_wait0(); __syncthreads();

    const int T = FCN / 32;
    for (int kt = 0; kt < T; kt++) {
        const int bt = kt & 1, bn = bt ^ 1;
        float* cA = sA + bt * 64 * 36;
        float* cB = sB + bt * 32 * LDB2;
        if (kt + 1 < T) {
            float* nB = sB + bn * 32 * LDB2;
#pragma unroll
            for (int p = 0; p < 8; p++) {
                int idx = tid + 512 * p;
                int kk = idx >> 7, n4 = (idx & 127) * 4;
                cpa16(&nB[kk * LDB2 + n4], &g_wuv[(size_t)((kt + 1) * 32 + kk) * 512 + n4]);
            }
            cp_commit();
            a0 = *(const float4*)&g_s1[(size_t)(R0 + ar) * FCN + (kt + 1) * 32 + af];
        }
#pragma unroll
        for (int ks = 0; ks < 32; ks += 8) {
            unsigned a[2][4], b[8][2];
#pragma unroll
            for (int mt = 0; mt < 2; mt++) {
                int r = wm * 32 + mt * 16 + g;
                a[mt][0] = __float_as_uint(cA[r * 36 + ks + t]);
                a[mt][1] = __float_as_uint(cA[(r + 8) * 36 + ks + t]);
                a[mt][2] = __float_as_uint(cA[r * 36 + ks + t + 4]);
                a[mt][3] = __float_as_uint(cA[(r + 8) * 36 + ks + t + 4]);
            }
#pragma unroll
            for (int nt = 0; nt < 8; nt++) {
                int n = wn * 64 + nt * 8 + g;
                b[nt][0] = __float_as_uint(cB[(ks + t) * LDB2 + n]);
                b[nt][1] = __float_as_uint(cB[(ks + t + 4) * LDB2 + n]);
            }
#pragma unroll
            for (int mt = 0; mt < 2; mt++)
#pragma unroll
                for (int nt = 0; nt < 8; nt++) mma8(c[mt][nt], a[mt], b[nt]);
        }
        if (kt + 1 < T)
            *(float4*)&sA[bn * 64 * 36 + ar * 36 + af] = a0;
        cp_wait0(); __syncthreads();
    }

#pragma unroll
    for (int mt = 0; mt < 2; mt++)
#pragma unroll
        for (int h = 0; h < 2; h++) {
            int row = R0 + wm * 32 + mt * 16 + g + 8 * h;
#pragma unroll
            for (int nt = 0; nt < 8; nt++) {
                int col = wn * 64 + nt * 8 + 2 * t;
                *(float2*)&g_uv[(size_t)row * 512 + col] =
                    make_float2(c[mt][nt][2 * h], c[mt][nt][2 * h + 1]);
            }
        }
}

// ---------------------------------------------------------------------------
// Kernel 3: build core rows, att + ctx GEMMs, effect reduction.
// 512 threads, 16 warps as 4 row-warps (32 rows) x 4 col-warps.
// Block tile: 128 rows (112 real = 16 groups of 7, rows 112-127 zero pad).
// ---------------------------------------------------------------------------
__global__ __launch_bounds__(512, 1) void k_eff(
    const float* __restrict__ core_b, const float* __restrict__ core_g,
    const float* __restrict__ core_bb,
    const float* __restrict__ ctx_b,
    const float* __restrict__ ctx_g, const float* __restrict__ ctx_bb,
    const float* __restrict__ a1_b,
    const float* __restrict__ att_g, const float* __restrict__ att_bb,
    const float* __restrict__ a2W,  const float* __restrict__ a2_b)
{
    extern __shared__ float sm[];
    float*  sA   = sm;                          // [128][LDSA] core rows (tf32)
    float*  sB   = sA + 128 * LDSA;             // 2 x [32][LDB]
    float*  sEff = sB + 2 * 32 * LDB;           // [16][257]
    float2* sRed = (float2*)(sEff + 16 * 257);  // [4][128]
    float*  sDot = (float*)(sRed + 4 * 128);    // [4][128]
    float*  sAtt = sDot + 4 * 128;              // [128]

    const int tid = threadIdx.x;
    const int wid = tid >> 5, lane = tid & 31;
    const int g = lane >> 2, t = lane & 3;
    const int wm = wid & 3, wn = wid >> 2;
    const int R0 = blockIdx.x * 112;

    // prefetch att1 weight tile 0 while building core rows
#pragma unroll
    for (int p = 0; p < 2; p++) {
        int idx = tid + 512 * p;
        int kk = idx >> 5, n4 = (idx & 31) * 4;
        cpa16(&sB[kk * LDBA + n4], &g_watt[(size_t)kk * LASTN + n4]);
    }
    cp_commit();

    for (int idx = tid; idx < 16 * 257; idx += 512) sEff[idx] = 0.f;
    // zero pad rows 112..127
    for (int r = 112 + wid; r < 128; r += 16)
        for (int cc = lane; cc < LDSA; cc += 32) sA[r * LDSA + cc] = 0.f;

    // ---- phase a: core rows = relu(LN(U[p]+V[q]+core_b)) into sA (rows 0..111)
    {
        float cb[8], cg[8], cbb[8];
#pragma unroll
        for (int e = 0; e < 8; e++) {
            int col = lane + 32 * e;
            cb[e] = core_b[col]; cg[e] = core_g[col]; cbb[e] = core_bb[col];
        }
#pragma unroll
        for (int rr = 0; rr < 7; rr++) {
            int lrow = wid * 7 + rr;
            int v = R0 + lrow;
            int p = v / 7;
            int jj = v - p * 7;
            int i = p & 7;
            int j = jj + (jj >= i ? 1 : 0);
            int q = (p & ~7) + j;
            float val[8], s = 0.f, s2 = 0.f;
#pragma unroll
            for (int e = 0; e < 8; e++) {
                int col = lane + 32 * e;
                val[e] = g_uv[(size_t)p * 512 + col] + g_uv[(size_t)q * 512 + 256 + col] + cb[e];
                s += val[e]; s2 += val[e] * val[e];
            }
#pragma unroll
            for (int o = 16; o; o >>= 1) {
                s  += __shfl_xor_sync(~0u, s,  o);
                s2 += __shfl_xor_sync(~0u, s2, o);
            }
            float mu = s * (1.f / FCN);
            float rs = rsqrtf(s2 * (1.f / FCN) - mu * mu + 1e-5f);
#pragma unroll
            for (int e = 0; e < 8; e++) {
                float o2 = fmaxf((val[e] - mu) * rs * cg[e] + cbb[e], 0.f);
                sA[lrow * LDSA + lane + 32 * e] = to_tf32(o2);
            }
        }
    }
    cp_wait0(); __syncthreads();

    // ---- pass 1: attention  (N=128, col-warp owns 32; M=32 per row-warp) ----
    {
        float ca[2][4][4];
#pragma unroll
        for (int mt = 0; mt < 2; mt++)
#pragma unroll
            for (int nt = 0; nt < 4; nt++)
#pragma unroll
                for (int e = 0; e < 4; e++) ca[mt][nt][e] = 0.f;

        const int T = FCN / 32;
        for (int kt = 0; kt < T; kt++) {
            const int bt = kt & 1, bn = bt ^ 1;
            float* cB = sB + bt * 32 * LDB;
            if (kt + 1 < T) {
                float* nB = sB + bn * 32 * LDB;
#pragma unroll
                for (int p = 0; p < 2; p++) {
                    int idx = tid + 512 * p;
                    int kk = idx >> 5, n4 = (idx & 31) * 4;
                    cpa16(&nB[kk * LDBA + n4],
                          &g_watt[(size_t)((kt + 1) * 32 + kk) * LASTN + n4]);
                }
                cp_commit();
            } else {
                // prefetch ctx weight tile 0 into the other buffer (buffer 0)
                float* nB = sB + bn * 32 * LDB;
#pragma unroll
                for (int p = 0; p < 4; p++) {
                    int idx = tid + 512 * p;
                    int kk = idx >> 6, n4 = (idx & 63) * 4;
                    cpa16(&nB[kk * LDB + n4], &g_wctx[(size_t)kk * FCN + n4]);
                }
                cp_commit();
            }
#pragma unroll
            for (int ks = 0; ks < 32; ks += 8) {
                unsigned a[2][4], b[4][2];
#pragma unroll
                for (int mt = 0; mt < 2; mt++) {
                    int r = wm * 32 + mt * 16 + g;
                    a[mt][0] = __float_as_uint(sA[r * LDSA + kt * 32 + ks + t]);
                    a[mt][1] = __float_as_uint(sA[(r + 8) * LDSA + kt * 32 + ks + t]);
                    a[mt][2] = __float_as_uint(sA[r * LDSA + kt * 32 + ks + t + 4]);
                    a[mt][3] = __float_as_uint(sA[(r + 8) * LDSA + kt * 32 + ks + t + 4]);
                }
#pragma unroll
                for (int nt = 0; nt < 4; nt++) {
                    int n = wn * 32 + nt * 8 + g;
                    b[nt][0] = __float_as_uint(cB[(ks + t) * LDBA + n]);
                    b[nt][1] = __float_as_uint(cB[(ks + t + 4) * LDBA + n]);
                }
#pragma unroll
                for (int mt = 0; mt < 2; mt++)
#pragma unroll
                    for (int nt = 0; nt < 4; nt++) mma8(ca[mt][nt], a[mt], b[nt]);
            }
            cp_wait0(); __syncthreads();
        }
        // epilogue: bias, LN(128) stats
#pragma unroll
        for (int nt = 0; nt < 4; nt++) {
            int col = wn * 32 + nt * 8 + 2 * t;
            float b0 = __ldg(&a1_b[col]), b1 = __ldg(&a1_b[col + 1]);
#pragma unroll
            for (int mt = 0; mt < 2; mt++) {
                ca[mt][nt][0] += b0; ca[mt][nt][1] += b1;
                ca[mt][nt][2] += b0; ca[mt][nt][3] += b1;
            }
        }
#pragma unroll
        for (int mt = 0; mt < 2; mt++) {
            float s0 = 0, q0 = 0, s1v = 0, q1 = 0;
#pragma unroll
            for (int nt = 0; nt < 4; nt++) {
                s0 += ca[mt][nt][0] + ca[mt][nt][1];
                q0 += ca[mt][nt][0] * ca[mt][nt][0] + ca[mt][nt][1] * ca[mt][nt][1];
                s1v += ca[mt][nt][2] + ca[mt][nt][3];
                q1 += ca[mt][nt][2] * ca[mt][nt][2] + ca[mt][nt][3] * ca[mt][nt][3];
            }
#pragma unroll
            for (int o = 1; o <= 2; o <<= 1) {
                s0 += __shfl_xor_sync(~0u, s0, o); q0 += __shfl_xor_sync(~0u, q0, o);
                s1v += __shfl_xor_sync(~0u, s1v, o); q1 += __shfl_xor_sync(~0u, q1, o);
            }
            if (t == 0) {
                sRed[wn * 128 + wm * 32 + mt * 16 + g]     = make_float2(s0, q0);
                sRed[wn * 128 + wm * 32 + mt * 16 + g + 8] = make_float2(s1v, q1);
            }
        }
        __syncthreads();
        // tanh-dot per row
#pragma unroll
        for (int mt = 0; mt < 2; mt++)
#pragma unroll
            for (int h = 0; h < 2; h++) {
                int row = wm * 32 + mt * 16 + g + 8 * h;
                float s = 0, q = 0;
#pragma unroll
                for (int w2 = 0; w2 < 4; w2++) {
                    float2 r2 = sRed[w2 * 128 + row]; s += r2.x; q += r2.y;
                }
                float mu = s * (1.f / LASTN);
                float rs = rsqrtf(q * (1.f / LASTN) - mu * mu + 1e-5f);
                float d = 0.f;
#pragma unroll
                for (int nt = 0; nt < 4; nt++) {
                    int col = wn * 32 + nt * 8 + 2 * t;
                    float gg0 = __ldg(&att_g[col]),   bb0 = __ldg(&att_bb[col]),   w0 = __ldg(&a2W[col]);
                    float gg1 = __ldg(&att_g[col+1]), bb1 = __ldg(&att_bb[col+1]), w1 = __ldg(&a2W[col+1]);
                    d += tanhf((ca[mt][nt][2*h]   - mu) * rs * gg0 + bb0) * w0;
                    d += tanhf((ca[mt][nt][2*h+1] - mu) * rs * gg1 + bb1) * w1;
                }
#pragma unroll
                for (int o = 1; o <= 2; o <<= 1) d += __shfl_xor_sync(~0u, d, o);
                if (t == 0) sDot[wn * 128 + row] = d;
            }
        __syncthreads();
        if (wid < 4) {
            int row = wid * 32 + lane;
            float a2b = __ldg(&a2_b[0]);
            float d = sDot[row] + sDot[128 + row] + sDot[256 + row] + sDot[384 + row];
            sAtt[row] = 1.f / (1.f + expf(-(d + a2b)));
        }
        __syncthreads();
    }

    // ---- pass 2: ctx (N=256, col-warp owns 64; M=32) + effect reduction ----
    // ctx tile 0 was prefetched into buffer 0 during pass-1 tail.
    {
        float cc[2][8][4];
#pragma unroll
        for (int mt = 0; mt < 2; mt++)
#pragma unroll
            for (int nt = 0; nt < 8; nt++)
#pragma unroll
                for (int e = 0; e < 4; e++) cc[mt][nt][e] = 0.f;

        const int T = FCN / 32;
        for (int kt = 0; kt < T; kt++) {
            const int bt = kt & 1, bn = bt ^ 1;
            float* cB = sB + bt * 32 * LDB;
            if (kt + 1 < T) {
                float* nB = sB + bn * 32 * LDB;
#pragma unroll
                for (int p = 0; p < 4; p++) {
                    int idx = tid + 512 * p;
                    int kk = idx >> 6, n4 = (idx & 63) * 4;
                    cpa16(&nB[kk * LDB + n4],
                          &g_wctx[(size_t)((kt + 1) * 32 + kk) * FCN + n4]);
                }
                cp_commit();
            }
#pragma unroll
            for (int ks = 0; ks < 32; ks += 8) {
                unsigned a[2][4], b[8][2];
#pragma unroll
                for (int mt = 0; mt < 2; mt++) {
                    int r = wm * 32 + mt * 16 + g;
                    a[mt][0] = __float_as_uint(sA[r * LDSA + kt * 32 + ks + t]);
                    a[mt][1] = __float_as_uint(sA[(r + 8) * LDSA + kt * 32 + ks + t]);
                    a[mt][2] = __float_as_uint(sA[r * LDSA + kt * 32 + ks + t + 4]);
                    a[mt][3] = __float_as_uint(sA[(r + 8) * LDSA + kt * 32 + ks + t + 4]);
                }
#pragma unroll
                for (int nt = 0; nt < 8; nt++) {
                    int n = wn * 64 + nt * 8 + g;
                    b[nt][0] = __float_as_uint(cB[(ks + t) * LDB + n]);
                    b[nt][1] = __float_as_uint(cB[(ks + t + 4) * LDB + n]);
                }
#pragma unroll
                for (int mt = 0; mt < 2; mt++)
#pragma unroll
                    for (int nt = 0; nt < 8; nt++) mma8(cc[mt][nt], a[mt], b[nt]);
            }
            cp_wait0(); __syncthreads();
        }
        // epilogue: bias + LN stats
#pragma unroll
        for (int nt = 0; nt < 8; nt++) {
            int col = wn * 64 + nt * 8 + 2 * t;
            float b0 = __ldg(&ctx_b[col]), b1 = __ldg(&ctx_b[col + 1]);
#pragma unroll
            for (int mt = 0; mt < 2; mt++) {
                cc[mt][nt][0] += b0; cc[mt][nt][1] += b1;
                cc[mt][nt][2] += b0; cc[mt][nt][3] += b1;
            }
        }
#pragma unroll
        for (int mt = 0; mt < 2; mt++) {
            float s0 = 0, q0 = 0, s1v = 0, q1 = 0;
#pragma unroll
            for (int nt = 0; nt < 8; nt++) {
                s0 += cc[mt][nt][0] + cc[mt][nt][1];
                q0 += cc[mt][nt][0] * cc[mt][nt][0] + cc[mt][nt][1] * cc[mt][nt][1];
                s1v += cc[mt][nt][2] + cc[mt][nt][3];
                q1 += cc[mt][nt][2] * cc[mt][nt][2] + cc[mt][nt][3] * cc[mt][nt][3];
            }
#pragma unroll
            for (int o = 1; o <= 2; o <<= 1) {
                s0 += __shfl_xor_sync(~0u, s0, o); q0 += __shfl_xor_sync(~0u, q0, o);
                s1v += __shfl_xor_sync(~0u, s1v, o); q1 += __shfl_xor_sync(~0u, q1, o);
            }
            if (t == 0) {
                sRed[wn * 128 + wm * 32 + mt * 16 + g]     = make_float2(s0, q0);
                sRed[wn * 128 + wm * 32 + mt * 16 + g + 8] = make_float2(s1v, q1);
            }
        }
        __syncthreads();
        // LN + relu + att-scale + effect accumulate
#pragma unroll
        for (int mt = 0; mt < 2; mt++)
#pragma unroll
            for (int h = 0; h < 2; h++) {
                int row = wm * 32 + mt * 16 + g + 8 * h;
                if (row >= 112) continue;
                float s = 0, q = 0;
#pragma unroll
                for (int w2 = 0; w2 < 4; w2++) {
                    float2 r2 = sRed[w2 * 128 + row]; s += r2.x; q += r2.y;
                }
                float mu = s * (1.f / FCN);
                float rs = rsqrtf(q * (1.f / FCN) - mu * mu + 1e-5f);
                float at = sAtt[row];
                int gl = row / 7;
#pragma unroll
                for (int nt = 0; nt < 8; nt++) {
                    int col = wn * 64 + nt * 8 + 2 * t;
                    float gg0 = __ldg(&ctx_g[col]),   bb0 = __ldg(&ctx_bb[col]);
                    float gg1 = __ldg(&ctx_g[col+1]), bb1 = __ldg(&ctx_bb[col+1]);
                    float v0 = fmaxf((cc[mt][nt][2*h]   - mu) * rs * gg0 + bb0, 0.f) * at;
                    float v1 = fmaxf((cc[mt][nt][2*h+1] - mu) * rs * gg1 + bb1, 0.f) * at;
                    atomicAdd(&sEff[gl * 257 + col],     v0);
                    atomicAdd(&sEff[gl * 257 + col + 1], v1);
                }
            }
    }
    __syncthreads();
    for (int idx = tid; idx < 16 * FCN; idx += 512) {
        int gg = idx >> 8, col = idx & 255;
        g_eff[(size_t)(blockIdx.x * 16 + gg) * FCN + col] = to_tf32(sEff[gg * 257 + col]);
    }
}

// ---------------------------------------------------------------------------
// Kernel 4: new_state = concat(s1, effect, x) @ out_w + out_b
// ---------------------------------------------------------------------------
__global__ __launch_bounds__(512, 1) void k_out(
    const float* __restrict__ xin, const float* __restrict__ bias,
    float* __restrict__ out, int dup)
{
    extern __shared__ float sm[];
    float* sA = sm;                 // 2 x [128][36]
    float* sB = sm + 2 * 128 * 36;  // 2 x [32][LDB]

    const int tid = threadIdx.x;
    const int wid = tid >> 5, lane = tid & 31;
    const int g = lane >> 2, t = lane & 3;
    const int wm = wid & 3, wn = wid >> 2;
    const int R0 = blockIdx.x * 128;

    const int ar0 = (tid) >> 3,        af0 = ((tid) & 7) * 4;
    const int ar1 = (tid + 512) >> 3,  af1 = ((tid + 512) & 7) * 4;

    float c[2][8][4];
#pragma unroll
    for (int mt = 0; mt < 2; mt++)
#pragma unroll
        for (int nt = 0; nt < 8; nt++)
#pragma unroll
            for (int e = 0; e < 4; e++) c[mt][nt][e] = 0.f;

    auto ldA = [&](int kt, float4& v0, float4& v1, bool& cvt) {
        int base = kt * 32;
        if (base < FCN) {
            v0 = *(const float4*)&g_s1[(size_t)(R0 + ar0) * FCN + base + af0];
            v1 = *(const float4*)&g_s1[(size_t)(R0 + ar1) * FCN + base + af1];
            cvt = false;
        } else if (base < 2 * FCN) {
            v0 = *(const float4*)&g_eff[(size_t)(R0 + ar0) * FCN + base - FCN + af0];
            v1 = *(const float4*)&g_eff[(size_t)(R0 + ar1) * FCN + base - FCN + af1];
            cvt = false;
        } else {
            v0 = *(const float4*)&xin[(size_t)(R0 + ar0) * MDIM + base - 2 * FCN + af0];
            v1 = *(const float4*)&xin[(size_t)(R0 + ar1) * MDIM + base - 2 * FCN + af1];
            cvt = true;
        }
    };
    auto stA = [&](float* buf, float4 v0, float4 v1, bool cvt) {
        float* d0 = &buf[ar0 * 36 + af0];
        float* d1 = &buf[ar1 * 36 + af1];
        if (cvt) {
            d0[0]=to_tf32(v0.x); d0[1]=to_tf32(v0.y); d0[2]=to_tf32(v0.z); d0[3]=to_tf32(v0.w);
            d1[0]=to_tf32(v1.x); d1[1]=to_tf32(v1.y); d1[2]=to_tf32(v1.z); d1[3]=to_tf32(v1.w);
        } else {
            *(float4*)d0 = v0; *(float4*)d1 = v1;
        }
    };

    float4 a0, a1; bool cvt;
    ldA(0, a0, a1, cvt);
    stA(sA, a0, a1, cvt);
#pragma unroll
    for (int p = 0; p < 4; p++) {
        int idx = tid + 512 * p;
        int kk = idx >> 6, n4 = (idx & 63) * 4;
        cpa16(&sB[kk * LDB + n4], &g_wout[(size_t)kk * FCN + n4]);
    }
    cp_commit(); cp_wait0(); __syncthreads();

    const int T = KOUT / 32;
    for (int kt = 0; kt < T; kt++) {
        const int bt = kt & 1, bn = bt ^ 1;
        float* cA = sA + bt * 128 * 36;
        float* cB = sB + bt * 32 * LDB;
        if (kt + 1 < T) {
            float* nB = sB + bn * 32 * LDB;
#pragma unroll
            for (int p = 0; p < 4; p++) {
                int idx = tid + 512 * p;
                int kk = idx >> 6, n4 = (idx & 63) * 4;
                cpa16(&nB[kk * LDB + n4], &g_wout[(size_t)((kt + 1) * 32 + kk) * FCN + n4]);
            }
            cp_commit();
            ldA(kt + 1, a0, a1, cvt);
        }
#pragma unroll
        for (int ks = 0; ks < 32; ks += 8) {
            unsigned a[2][4], b[8][2];
#pragma unroll
            for (int mt = 0; mt < 2; mt++) {
                int r = wm * 32 + mt * 16 + g;
                a[mt][0] = __float_as_uint(cA[r * 36 + ks + t]);
                a[mt][1] = __float_as_uint(cA[(r + 8) * 36 + ks + t]);
                a[mt][2] = __float_as_uint(cA[r * 36 + ks + t + 4]);
                a[mt][3] = __float_as_uint(cA[(r + 8) * 36 + ks + t + 4]);
            }
#pragma unroll
            for (int nt = 0; nt < 8; nt++) {
                int n = wn * 64 + nt * 8 + g;
                b[nt][0] = __float_as_uint(cB[(ks + t) * LDB + n]);
                b[nt][1] = __float_as_uint(cB[(ks + t + 4) * LDB + n]);
            }
#pragma unroll
            for (int mt = 0; mt < 2; mt++)
#pragma unroll
                for (int nt = 0; nt < 8; nt++) mma8(c[mt][nt], a[mt], b[nt]);
        }
        if (kt + 1 < T)
            stA(sA + bn * 128 * 36, a0, a1, cvt);
        cp_wait0(); __syncthreads();
    }

#pragma unroll
    for (int mt = 0; mt < 2; mt++)
#pragma unroll
        for (int h = 0; h < 2; h++) {
            int row = R0 + wm * 32 + mt * 16 + g + 8 * h;
#pragma unroll
            for (int nt = 0; nt < 8; nt++) {
                int col = wn * 64 + nt * 8 + 2 * t;
                float o0 = c[mt][nt][2 * h]     + __ldg(&bias[col]);
                float o1 = c[mt][nt][2 * h + 1] + __ldg(&bias[col + 1]);
                size_t off = (size_t)row * FCN + col;
                *(float2*)&out[off] = make_float2(o0, o1);
                if (dup) *(float2*)&out[(size_t)NR1 * FCN + off] = make_float2(o0, o1);
            }
        }
}

// ---------------------------------------------------------------------------
extern "C" void kernel_launch(void* const* d_in, const int* in_sizes, int n_in,
                              void* d_out, int out_size) {
    const float* x      = (const float*)d_in[0];
    const float* state  = (const float*)d_in[1];
    const float* enc_w  = (const float*)d_in[2];
    const float* enc_b  = (const float*)d_in[3];
    const float* enc_g  = (const float*)d_in[4];
    const float* enc_bb = (const float*)d_in[5];
    const float* core_w = (const float*)d_in[6];
    const float* core_b = (const float*)d_in[7];
    const float* core_g = (const float*)d_in[8];
    const float* core_bb= (const float*)d_in[9];
    const float* ctx_w  = (const float*)d_in[10];
    const float* ctx_b  = (const float*)d_in[11];
    const float* ctx_g  = (const float*)d_in[12];
    const float* ctx_bb = (const float*)d_in[13];
    const float* att1_w = (const float*)d_in[14];
    const float* att1_b = (const float*)d_in[15];
    const float* att_g  = (const float*)d_in[16];
    const float* att_bb = (const float*)d_in[17];
    const float* att2_w = (const float*)d_in[18];
    const float* att2_b = (const float*)d_in[19];
    const float* out_w  = (const float*)d_in[20];
    const float* out_b  = (const float*)d_in[21];
    float* out = (float*)d_out;
    int dup = (out_size >= 2 * NR1 * FCN) ? 1 : 0;

    const int smem_enc = (2 * 128 * 36 + 2 * 32 * LDB) * 4 + 4 * 128 * 8;
    const int smem_uv  = (2 * 64 * 36 + 2 * 32 * LDB2) * 4;
    const int smem_eff = (128 * LDSA + 2 * 32 * LDB + 16 * 257) * 4
                       + 4 * 128 * 8 + 4 * 128 * 4 + 128 * 4;
    const int smem_out = (2 * 128 * 36 + 2 * 32 * LDB) * 4;

    static int attr_done = 0;
    if (!attr_done) {
        cudaFuncSetAttribute(k_enc, cudaFuncAttributeMaxDynamicSharedMemorySize, smem_enc);
        cudaFuncSetAttribute(k_uv,  cudaFuncAttributeMaxDynamicSharedMemorySize, smem_uv);
        cudaFuncSetAttribute(k_eff, cudaFuncAttributeMaxDynamicSharedMemorySize, smem_eff);
        cudaFuncSetAttribute(k_out, cudaFuncAttributeMaxDynamicSharedMemorySize, smem_out);
        attr_done = 1;
    }

    k_cvtw<<<256, 256>>>(enc_w, core_w, ctx_w, att1_w, out_w);
    k_enc<<<NR1 / 128, 512, smem_enc>>>(state, enc_b, enc_g, enc_bb);
    k_uv <<<NR1 / 64,  512, smem_uv >>>();
    k_eff<<<NR2 / 112, 512, smem_eff>>>(core_b, core_g, core_bb,
                                        ctx_b, ctx_g, ctx_bb,
                                        att1_b, att_g, att_bb,
                                        att2_w, att2_b);
    k_out<<<NR1 / 128, 512, smem_out>>>(x, out_b, out, dup);
}

// round 7
// speedup vs baseline: 4.8165x; 1.1965x over previous
#include <cuda_runtime.h>
#include <cuda_fp16.h>
#include <cstdint>
#include <math.h>

// ---------------------------------------------------------------------------
// R-NEM cell. tf32 pipeline for enc/uv/out; fp16 m16n8k16 fragments for k_eff
// (ctx+att GEMMs) with pre-packed per-lane fragment layouts.
//   K=8, FC=256, LAST=128, B=2048, M=1024, H=512
// core_pre[v] = U[p] + V[q] + core_b, [U|V] = s1 @ core_w (packed k-major)
// ---------------------------------------------------------------------------

#define FCN   256
#define LASTN 128
#define HDIM  512
#define MDIM  1024
#define NR1   16384
#define NR2   114688
#define KOUT  (2 * FCN + MDIM)

__device__ float g_s1[NR1 * FCN];        // tf32-rounded
__device__ float g_uv[NR1 * 2 * FCN];    // fp32
__device__ float g_eff[NR1 * FCN];       // tf32-rounded

// tf32 weights
__device__ float g_wenc[HDIM * FCN];
__device__ float g_wuv[FCN * 2 * FCN];   // packed: [k][512] = [Wtop | Wbot]
__device__ float g_wout[KOUT * FCN];

// fp16 fragment-packed weights for k_eff:
//   slot idx = (kt16 * (N/8) + n8) * 32 + lane ; uint2 = {b0, b1} frag regs
__device__ __align__(16) uint2 g_wattp[(FCN / 16) * (LASTN / 8) * 32]; // 8192
__device__ __align__(16) uint2 g_wctxp[(FCN / 16) * (FCN / 8) * 32];   // 16384

// -------------------------------- helpers ---------------------------------
__device__ __forceinline__ float to_tf32(float x) {
    unsigned u; asm("cvt.rna.tf32.f32 %0, %1;" : "=r"(u) : "f"(x));
    return __uint_as_float(u);
}
__device__ __forceinline__ void mma8(float* c, const unsigned* a, const unsigned* b) {
    asm volatile(
        "mma.sync.aligned.m16n8k8.row.col.f32.tf32.tf32.f32 "
        "{%0,%1,%2,%3}, {%4,%5,%6,%7}, {%8,%9}, {%0,%1,%2,%3};"
        : "+f"(c[0]), "+f"(c[1]), "+f"(c[2]), "+f"(c[3])
        : "r"(a[0]), "r"(a[1]), "r"(a[2]), "r"(a[3]), "r"(b[0]), "r"(b[1]));
}
__device__ __forceinline__ void mma16(float* c, const unsigned* a, const unsigned* b) {
    asm volatile(
        "mma.sync.aligned.m16n8k16.row.col.f32.f16.f16.f32 "
        "{%0,%1,%2,%3}, {%4,%5,%6,%7}, {%8,%9}, {%0,%1,%2,%3};"
        : "+f"(c[0]), "+f"(c[1]), "+f"(c[2]), "+f"(c[3])
        : "r"(a[0]), "r"(a[1]), "r"(a[2]), "r"(a[3]), "r"(b[0]), "r"(b[1]));
}
__device__ __forceinline__ void cpa16(void* dst, const void* src) {
    unsigned d = (unsigned)__cvta_generic_to_shared(dst);
    asm volatile("cp.async.cg.shared.global [%0], [%1], 16;" :: "r"(d), "l"(src));
}
__device__ __forceinline__ void cp_commit() { asm volatile("cp.async.commit_group;"); }
__device__ __forceinline__ void cp_wait0()  { asm volatile("cp.async.wait_group 0;"); }
__device__ __forceinline__ unsigned packh(float a, float b) {
    __half2 h = __floats2half2_rn(a, b);
    return *(unsigned*)&h;
}

#define LDB 264   // tf32 B tile stride
#define LDB2 520

// ---------------------------------------------------------------------------
// Kernel 0: convert/pack weights
// ---------------------------------------------------------------------------
__global__ void k_cvtw(const float* __restrict__ enc_w, const float* __restrict__ core_w,
                       const float* __restrict__ ctx_w, const float* __restrict__ att1_w,
                       const float* __restrict__ out_w)
{
    int i = blockIdx.x * blockDim.x + threadIdx.x;
    int n = gridDim.x * blockDim.x;
    for (int idx = i; idx < HDIM * FCN; idx += n) g_wenc[idx] = to_tf32(enc_w[idx]);
    for (int idx = i; idx < FCN * 2 * FCN; idx += n) {
        int k = idx >> 9, c = idx & 511;
        float v = (c < FCN) ? core_w[k * FCN + c] : core_w[(FCN + k) * FCN + (c - FCN)];
        g_wuv[idx] = to_tf32(v);
    }
    for (int idx = i; idx < KOUT * FCN; idx += n) g_wout[idx] = to_tf32(out_w[idx]);
    // fp16 fragment pack: att1_w (256x128)
    for (int idx = i; idx < (FCN/16) * (LASTN/8) * 32; idx += n) {
        int kt = idx >> 9;            // / (16*32)
        int n8 = (idx >> 5) & 15;
        int lane = idx & 31;
        int g = lane >> 2, t = lane & 3;
        int nn = n8 * 8 + g, k0 = kt * 16;
        g_wattp[idx] = make_uint2(
            packh(att1_w[(k0 + 2*t)     * LASTN + nn], att1_w[(k0 + 2*t + 1) * LASTN + nn]),
            packh(att1_w[(k0 + 8 + 2*t) * LASTN + nn], att1_w[(k0 + 9 + 2*t) * LASTN + nn]));
    }
    // fp16 fragment pack: ctx_w (256x256)
    for (int idx = i; idx < (FCN/16) * (FCN/8) * 32; idx += n) {
        int kt = idx >> 10;           // / (32*32)
        int n8 = (idx >> 5) & 31;
        int lane = idx & 31;
        int g = lane >> 2, t = lane & 3;
        int nn = n8 * 8 + g, k0 = kt * 16;
        g_wctxp[idx] = make_uint2(
            packh(ctx_w[(k0 + 2*t)     * FCN + nn], ctx_w[(k0 + 2*t + 1) * FCN + nn]),
            packh(ctx_w[(k0 + 8 + 2*t) * FCN + nn], ctx_w[(k0 + 9 + 2*t) * FCN + nn]));
    }
}

// ---------------------------------------------------------------------------
// Kernel 1: s1 = relu(LN(state @ enc_w + enc_b))    (tf32, unchanged)
// ---------------------------------------------------------------------------
__global__ __launch_bounds__(512, 1) void k_enc(
    const float* __restrict__ state, const float* __restrict__ bias,
    const float* __restrict__ gam, const float* __restrict__ bet)
{
    extern __shared__ float sm[];
    float*  sA  = sm;
    float*  sB  = sm + 2 * 128 * 36;
    float2* red = (float2*)(sB + 2 * 32 * LDB);

    const int tid = threadIdx.x;
    const int wid = tid >> 5, lane = tid & 31;
    const int g = lane >> 2, t = lane & 3;
    const int wm = wid & 3, wn = wid >> 2;
    const int R0 = blockIdx.x * 128;
    const int ar0 = (tid) >> 3,        af0 = ((tid) & 7) * 4;
    const int ar1 = (tid + 512) >> 3,  af1 = ((tid + 512) & 7) * 4;

    float c[2][8][4];
#pragma unroll
    for (int mt = 0; mt < 2; mt++)
#pragma unroll
        for (int nt = 0; nt < 8; nt++)
#pragma unroll
            for (int e = 0; e < 4; e++) c[mt][nt][e] = 0.f;

    float4 a0, a1;
    a0 = *(const float4*)&state[(size_t)(R0 + ar0) * HDIM + af0];
    a1 = *(const float4*)&state[(size_t)(R0 + ar1) * HDIM + af1];
    {
        float* d0 = &sA[ar0 * 36 + af0];
        d0[0]=to_tf32(a0.x); d0[1]=to_tf32(a0.y); d0[2]=to_tf32(a0.z); d0[3]=to_tf32(a0.w);
        float* d1 = &sA[ar1 * 36 + af1];
        d1[0]=to_tf32(a1.x); d1[1]=to_tf32(a1.y); d1[2]=to_tf32(a1.z); d1[3]=to_tf32(a1.w);
    }
#pragma unroll
    for (int p = 0; p < 4; p++) {
        int idx = tid + 512 * p;
        int kk = idx >> 6, n4 = (idx & 63) * 4;
        cpa16(&sB[kk * LDB + n4], &g_wenc[(size_t)kk * FCN + n4]);
    }
    cp_commit(); cp_wait0(); __syncthreads();

    const int T = HDIM / 32;
    for (int kt = 0; kt < T; kt++) {
        const int bt = kt & 1, bn = bt ^ 1;
        float* cA = sA + bt * 128 * 36;
        float* cB = sB + bt * 32 * LDB;
        if (kt + 1 < T) {
            float* nB = sB + bn * 32 * LDB;
#pragma unroll
            for (int p = 0; p < 4; p++) {
                int idx = tid + 512 * p;
                int kk = idx >> 6, n4 = (idx & 63) * 4;
                cpa16(&nB[kk * LDB + n4], &g_wenc[(size_t)((kt + 1) * 32 + kk) * FCN + n4]);
            }
            cp_commit();
            a0 = *(const float4*)&state[(size_t)(R0 + ar0) * HDIM + (kt + 1) * 32 + af0];
            a1 = *(const float4*)&state[(size_t)(R0 + ar1) * HDIM + (kt + 1) * 32 + af1];
        }
#pragma unroll
        for (int ks = 0; ks < 32; ks += 8) {
            unsigned a[2][4], b[8][2];
#pragma unroll
            for (int mt = 0; mt < 2; mt++) {
                int r = wm * 32 + mt * 16 + g;
                a[mt][0] = __float_as_uint(cA[r * 36 + ks + t]);
                a[mt][1] = __float_as_uint(cA[(r + 8) * 36 + ks + t]);
                a[mt][2] = __float_as_uint(cA[r * 36 + ks + t + 4]);
                a[mt][3] = __float_as_uint(cA[(r + 8) * 36 + ks + t + 4]);
            }
#pragma unroll
            for (int nt = 0; nt < 8; nt++) {
                int n = wn * 64 + nt * 8 + g;
                b[nt][0] = __float_as_uint(cB[(ks + t) * LDB + n]);
                b[nt][1] = __float_as_uint(cB[(ks + t + 4) * LDB + n]);
            }
#pragma unroll
            for (int mt = 0; mt < 2; mt++)
#pragma unroll
                for (int nt = 0; nt < 8; nt++) mma8(c[mt][nt], a[mt], b[nt]);
        }
        if (kt + 1 < T) {
            float* nA = sA + bn * 128 * 36;
            float* d0 = &nA[ar0 * 36 + af0];
            d0[0]=to_tf32(a0.x); d0[1]=to_tf32(a0.y); d0[2]=to_tf32(a0.z); d0[3]=to_tf32(a0.w);
            float* d1 = &nA[ar1 * 36 + af1];
            d1[0]=to_tf32(a1.x); d1[1]=to_tf32(a1.y); d1[2]=to_tf32(a1.z); d1[3]=to_tf32(a1.w);
        }
        cp_wait0(); __syncthreads();
    }

#pragma unroll
    for (int nt = 0; nt < 8; nt++) {
        int col = wn * 64 + nt * 8 + 2 * t;
        float b0 = __ldg(&bias[col]), b1 = __ldg(&bias[col + 1]);
#pragma unroll
        for (int mt = 0; mt < 2; mt++) {
            c[mt][nt][0] += b0; c[mt][nt][1] += b1;
            c[mt][nt][2] += b0; c[mt][nt][3] += b1;
        }
    }
#pragma unroll
    for (int mt = 0; mt < 2; mt++) {
        float s0 = 0, q0 = 0, s1v = 0, q1 = 0;
#pragma unroll
        for (int nt = 0; nt < 8; nt++) {
            s0 += c[mt][nt][0] + c[mt][nt][1];
            q0 += c[mt][nt][0] * c[mt][nt][0] + c[mt][nt][1] * c[mt][nt][1];
            s1v += c[mt][nt][2] + c[mt][nt][3];
            q1 += c[mt][nt][2] * c[mt][nt][2] + c[mt][nt][3] * c[mt][nt][3];
        }
#pragma unroll
        for (int o = 1; o <= 2; o <<= 1) {
            s0 += __shfl_xor_sync(~0u, s0, o); q0 += __shfl_xor_sync(~0u, q0, o);
            s1v += __shfl_xor_sync(~0u, s1v, o); q1 += __shfl_xor_sync(~0u, q1, o);
        }
        if (t == 0) {
            red[wn * 128 + wm * 32 + mt * 16 + g]     = make_float2(s0, q0);
            red[wn * 128 + wm * 32 + mt * 16 + g + 8] = make_float2(s1v, q1);
        }
    }
    __syncthreads();
#pragma unroll
    for (int mt = 0; mt < 2; mt++)
#pragma unroll
        for (int h = 0; h < 2; h++) {
            int row = wm * 32 + mt * 16 + g + 8 * h;
            float s = 0, q = 0;
#pragma unroll
            for (int w2 = 0; w2 < 4; w2++) {
                float2 r2 = red[w2 * 128 + row]; s += r2.x; q += r2.y;
            }
            float mu = s * (1.f / FCN);
            float rs = rsqrtf(q * (1.f / FCN) - mu * mu + 1e-5f);
#pragma unroll
            for (int nt = 0; nt < 8; nt++) {
                int col = wn * 64 + nt * 8 + 2 * t;
                float o0 = fmaxf((c[mt][nt][2 * h]     - mu) * rs * __ldg(&gam[col])     + __ldg(&bet[col]),     0.f);
                float o1 = fmaxf((c[mt][nt][2 * h + 1] - mu) * rs * __ldg(&gam[col + 1]) + __ldg(&bet[col + 1]), 0.f);
                *(float2*)&g_s1[(size_t)(R0 + row) * FCN + col] =
                    make_float2(to_tf32(o0), to_tf32(o1));
            }
        }
}

// ---------------------------------------------------------------------------
// Kernel 2: [U|V] = s1 @ packed(core_w)   (tf32, unchanged)
// ---------------------------------------------------------------------------
__global__ __launch_bounds__(512, 1) void k_uv()
{
    extern __shared__ float sm[];
    float* sA = sm;
    float* sB = sm + 2 * 64 * 36;

    const int tid = threadIdx.x;
    const int wid = tid >> 5, lane = tid & 31;
    const int g = lane >> 2, t = lane & 3;
    const int wm = wid & 1, wn = wid >> 1;
    const int R0 = blockIdx.x * 64;
    const int ar = tid >> 3, af = (tid & 7) * 4;

    float c[2][8][4];
#pragma unroll
    for (int mt = 0; mt < 2; mt++)
#pragma unroll
        for (int nt = 0; nt < 8; nt++)
#pragma unroll
            for (int e = 0; e < 4; e++) c[mt][nt][e] = 0.f;

    float4 a0;
    a0 = *(const float4*)&g_s1[(size_t)(R0 + ar) * FCN + af];
    *(float4*)&sA[ar * 36 + af] = a0;
#pragma unroll
    for (int p = 0; p < 8; p++) {
        int idx = tid + 512 * p;
        int kk = idx >> 7, n4 = (idx & 127) * 4;
        cpa16(&sB[kk * LDB2 + n4], &g_wuv[(size_t)kk * 512 + n4]);
    }
    cp_commit(); cp_wait0(); __syncthreads();

    const int T = FCN / 32;
    for (int kt = 0; kt < T; kt++) {
        const int bt = kt & 1, bn = bt ^ 1;
        float* cA = sA + bt * 64 * 36;
        float* cB = sB + bt * 32 * LDB2;
        if (kt + 1 < T) {
            float* nB = sB + bn * 32 * LDB2;
#pragma unroll
            for (int p = 0; p < 8; p++) {
                int idx = tid + 512 * p;
                int kk = idx >> 7, n4 = (idx & 127) * 4;
                cpa16(&nB[kk * LDB2 + n4], &g_wuv[(size_t)((kt + 1) * 32 + kk) * 512 + n4]);
            }
            cp_commit();
            a0 = *(const float4*)&g_s1[(size_t)(R0 + ar) * FCN + (kt + 1) * 32 + af];
        }
#pragma unroll
        for (int ks = 0; ks < 32; ks += 8) {
            unsigned a[2][4], b[8][2];
#pragma unroll
            for (int mt = 0; mt < 2; mt++) {
                int r = wm * 32 + mt * 16 + g;
                a[mt][0] = __float_as_uint(cA[r * 36 + ks + t]);
                a[mt][1] = __float_as_uint(cA[(r + 8) * 36 + ks + t]);
                a[mt][2] = __float_as_uint(cA[r * 36 + ks + t + 4]);
                a[mt][3] = __float_as_uint(cA[(r + 8) * 36 + ks + t + 4]);
            }
#pragma unroll
            for (int nt = 0; nt < 8; nt++) {
                int n = wn * 64 + nt * 8 + g;
                b[nt][0] = __float_as_uint(cB[(ks + t) * LDB2 + n]);
                b[nt][1] = __float_as_uint(cB[(ks + t + 4) * LDB2 + n]);
            }
#pragma unroll
            for (int mt = 0; mt < 2; mt++)
#pragma unroll
                for (int nt = 0; nt < 8; nt++) mma8(c[mt][nt], a[mt], b[nt]);
        }
        if (kt + 1 < T)
            *(float4*)&sA[bn * 64 * 36 + ar * 36 + af] = a0;
        cp_wait0(); __syncthreads();
    }

#pragma unroll
    for (int mt = 0; mt < 2; mt++)
#pragma unroll
        for (int h = 0; h < 2; h++) {
            int row = R0 + wm * 32 + mt * 16 + g + 8 * h;
#pragma unroll
            for (int nt = 0; nt < 8; nt++) {
                int col = wn * 64 + nt * 8 + 2 * t;
                *(float2*)&g_uv[(size_t)row * 512 + col] =
                    make_float2(c[mt][nt][2 * h], c[mt][nt][2 * h + 1]);
            }
        }
}

// ---------------------------------------------------------------------------
// Kernel 3 (fp16): build packed core rows, att + ctx GEMMs, effect reduction.
// 512 threads, 16 warps (4 row x 4 col). Tile 128 rows (112 real).
// Packed A: [mt16(8)][kt16(16)] blocks of 528B; slot = lane*16B = a0..a3.
// Packed B (global, k_cvtw): [kt16][n8][lane] uint2 = b0,b1.
// ---------------------------------------------------------------------------
__global__ __launch_bounds__(512, 1) void k_eff(
    const float* __restrict__ core_b, const float* __restrict__ core_g,
    const float* __restrict__ core_bb,
    const float* __restrict__ ctx_b,
    const float* __restrict__ ctx_g, const float* __restrict__ ctx_bb,
    const float* __restrict__ a1_b,
    const float* __restrict__ att_g, const float* __restrict__ att_bb,
    const float* __restrict__ a2W,  const float* __restrict__ a2_b)
{
    extern __shared__ float sm[];
    char*   sAp  = (char*)sm;                   // 8*16*528 = 67584 B
    float*  sB   = sm + 67584 / 4;              // 2 x 2048 floats (8KB each)
    float*  sEff = sB + 2 * 2048;               // [16][257]
    float2* sRed = (float2*)(sEff + 16 * 257);  // [4][128]
    float*  sDot = (float*)(sRed + 4 * 128);    // [4][128]
    float*  sAtt = sDot + 4 * 128;              // [128]

    const int tid = threadIdx.x;
    const int wid = tid >> 5, lane = tid & 31;
    const int g = lane >> 2, t = lane & 3;
    const int wm = wid & 3, wn = wid >> 2;
    const int R0 = blockIdx.x * 112;
    const int NKT = FCN / 16;   // 16 k16-tiles

    // prefetch att1 packed tile 0 into buffer 0 (4KB)
    if (tid < 256)
        cpa16((char*)sB + tid * 16, (const char*)g_wattp + tid * 16);
    cp_commit();

    for (int idx = tid; idx < 16 * 257; idx += 512) sEff[idx] = 0.f;
    {   // zero pad slab mt=7 (rows 112..127)
        float* z = (float*)(sAp + 7 * 16 * 528);
        for (int i = tid; i < 16 * 528 / 4; i += 512) z[i] = 0.f;
    }

    // ---- phase a: core rows -> packed fp16 sA. lane owns col pairs 2lane+64e
    {
        const int mt = -1; (void)mt;
#pragma unroll
        for (int rr = 0; rr < 7; rr++) {
            int lrow = wid * 7 + rr;
            int v = R0 + lrow;
            int p = v / 7;
            int jj = v - p * 7;
            int i = p & 7;
            int j = jj + (jj >= i ? 1 : 0);
            int q = (p & ~7) + j;
            float2 val[4];
            float s = 0.f, s2 = 0.f;
#pragma unroll
            for (int e = 0; e < 4; e++) {
                int col = 2 * lane + 64 * e;
                float2 u  = *(const float2*)&g_uv[(size_t)p * 512 + col];
                float2 vq = *(const float2*)&g_uv[(size_t)q * 512 + 256 + col];
                float2 cb = *(const float2*)&core_b[col];
                val[e].x = u.x + vq.x + cb.x;
                val[e].y = u.y + vq.y + cb.y;
                s += val[e].x + val[e].y;
                s2 += val[e].x * val[e].x + val[e].y * val[e].y;
            }
#pragma unroll
            for (int o = 16; o; o >>= 1) {
                s  += __shfl_xor_sync(~0u, s,  o);
                s2 += __shfl_xor_sync(~0u, s2, o);
            }
            float mu = s * (1.f / FCN);
            float rs = rsqrtf(s2 * (1.f / FCN) - mu * mu + 1e-5f);
            int mtile = lrow >> 4, gg = lrow & 7, hm = (lrow >> 3) & 1;
            int tt = lane & 3, hk = (lane >> 2) & 1;
#pragma unroll
            for (int e = 0; e < 4; e++) {
                int col = 2 * lane + 64 * e;
                float2 cg = *(const float2*)&core_g[col];
                float2 cbb = *(const float2*)&core_bb[col];
                float o0 = fmaxf((val[e].x - mu) * rs * cg.x + cbb.x, 0.f);
                float o1 = fmaxf((val[e].y - mu) * rs * cg.y + cbb.y, 0.f);
                int kt = (lane >> 3) + 4 * e;
                unsigned off = (unsigned)((mtile * 16 + kt) * 528
                                          + ((gg << 2) + tt) * 16 + (hk * 2 + hm) * 4);
                *(unsigned*)(sAp + off) = packh(o0, o1);
            }
        }
    }
    cp_wait0(); __syncthreads();

    // ---- pass 1: attention (N=128, warp owns 32 cols = 4 n8-tiles) ----
    {
        float ca[2][4][4];
#pragma unroll
        for (int mt = 0; mt < 2; mt++)
#pragma unroll
            for (int nt = 0; nt < 4; nt++)
#pragma unroll
                for (int e = 0; e < 4; e++) ca[mt][nt][e] = 0.f;

        for (int kt = 0; kt < NKT; kt++) {
            const int bt = kt & 1, bn = bt ^ 1;
            float* cB = sB + bt * 2048;
            if (kt + 1 < NKT) {
                if (tid < 256)
                    cpa16((char*)(sB + bn * 2048) + tid * 16,
                          (const char*)g_wattp + (size_t)(kt + 1) * 4096 + tid * 16);
                cp_commit();
            } else {
                cpa16((char*)(sB + bn * 2048) + tid * 16, (const char*)g_wctxp + tid * 16);
                cp_commit();
            }
            unsigned a[2][4];
#pragma unroll
            for (int mt = 0; mt < 2; mt++) {
                uint4 av = *(uint4*)(sAp + ((wm * 2 + mt) * 16 + kt) * 528 + lane * 16);
                a[mt][0] = av.x; a[mt][1] = av.y; a[mt][2] = av.z; a[mt][3] = av.w;
            }
#pragma unroll
            for (int nt = 0; nt < 4; nt++) {
                uint2 bv = *(uint2*)((char*)cB + ((wn * 4 + nt) * 32 + lane) * 8);
                unsigned b[2] = {bv.x, bv.y};
                mma16(ca[0][nt], a[0], b);
                mma16(ca[1][nt], a[1], b);
            }
            cp_wait0(); __syncthreads();
        }
        // epilogue: bias + LN(128) stats
#pragma unroll
        for (int nt = 0; nt < 4; nt++) {
            int col = wn * 32 + nt * 8 + 2 * t;
            float b0 = __ldg(&a1_b[col]), b1 = __ldg(&a1_b[col + 1]);
#pragma unroll
            for (int mt = 0; mt < 2; mt++) {
                ca[mt][nt][0] += b0; ca[mt][nt][1] += b1;
                ca[mt][nt][2] += b0; ca[mt][nt][3] += b1;
            }
        }
#pragma unroll
        for (int mt = 0; mt < 2; mt++) {
            float s0 = 0, q0 = 0, s1v = 0, q1 = 0;
#pragma unroll
            for (int nt = 0; nt < 4; nt++) {
                s0 += ca[mt][nt][0] + ca[mt][nt][1];
                q0 += ca[mt][nt][0] * ca[mt][nt][0] + ca[mt][nt][1] * ca[mt][nt][1];
                s1v += ca[mt][nt][2] + ca[mt][nt][3];
                q1 += ca[mt][nt][2] * ca[mt][nt][2] + ca[mt][nt][3] * ca[mt][nt][3];
            }
#pragma unroll
            for (int o = 1; o <= 2; o <<= 1) {
                s0 += __shfl_xor_sync(~0u, s0, o); q0 += __shfl_xor_sync(~0u, q0, o);
                s1v += __shfl_xor_sync(~0u, s1v, o); q1 += __shfl_xor_sync(~0u, q1, o);
            }
            if (t == 0) {
                sRed[wn * 128 + wm * 32 + mt * 16 + g]     = make_float2(s0, q0);
                sRed[wn * 128 + wm * 32 + mt * 16 + g + 8] = make_float2(s1v, q1);
            }
        }
        __syncthreads();
#pragma unroll
        for (int mt = 0; mt < 2; mt++)
#pragma unroll
            for (int h = 0; h < 2; h++) {
                int row = wm * 32 + mt * 16 + g + 8 * h;
                float s = 0, q = 0;
#pragma unroll
                for (int w2 = 0; w2 < 4; w2++) {
                    float2 r2 = sRed[w2 * 128 + row]; s += r2.x; q += r2.y;
                }
                float mu = s * (1.f / LASTN);
                float rs = rsqrtf(q * (1.f / LASTN) - mu * mu + 1e-5f);
                float d = 0.f;
#pragma unroll
                for (int nt = 0; nt < 4; nt++) {
                    int col = wn * 32 + nt * 8 + 2 * t;
                    float gg0 = __ldg(&att_g[col]),   bb0 = __ldg(&att_bb[col]),   w0 = __ldg(&a2W[col]);
                    float gg1 = __ldg(&att_g[col+1]), bb1 = __ldg(&att_bb[col+1]), w1 = __ldg(&a2W[col+1]);
                    d += tanhf((ca[mt][nt][2*h]   - mu) * rs * gg0 + bb0) * w0;
                    d += tanhf((ca[mt][nt][2*h+1] - mu) * rs * gg1 + bb1) * w1;
                }
#pragma unroll
                for (int o = 1; o <= 2; o <<= 1) d += __shfl_xor_sync(~0u, d, o);
                if (t == 0) sDot[wn * 128 + row] = d;
            }
        __syncthreads();
        if (wid < 4) {
            int row = wid * 32 + lane;
            float a2b = __ldg(&a2_b[0]);
            float d = sDot[row] + sDot[128 + row] + sDot[256 + row] + sDot[384 + row];
            sAtt[row] = 1.f / (1.f + expf(-(d + a2b)));
        }
        __syncthreads();
    }

    // ---- pass 2: ctx (N=256, warp owns 64 cols = 8 n8-tiles) + effect ----
    {
        float cc[2][8][4];
#pragma unroll
        for (int mt = 0; mt < 2; mt++)
#pragma unroll
            for (int nt = 0; nt < 8; nt++)
#pragma unroll
                for (int e = 0; e < 4; e++) cc[mt][nt][e] = 0.f;

        for (int kt = 0; kt < NKT; kt++) {
            const int bt = kt & 1, bn = bt ^ 1;
            float* cB = sB + bt * 2048;
            if (kt + 1 < NKT) {
                cpa16((char*)(sB + bn * 2048) + tid * 16,
                      (const char*)g_wctxp + (size_t)(kt + 1) * 8192 + tid * 16);
                cp_commit();
            }
            unsigned a[2][4];
#pragma unroll
            for (int mt = 0; mt < 2; mt++) {
                uint4 av = *(uint4*)(sAp + ((wm * 2 + mt) * 16 + kt) * 528 + lane * 16);
                a[mt][0] = av.x; a[mt][1] = av.y; a[mt][2] = av.z; a[mt][3] = av.w;
            }
#pragma unroll
            for (int nt = 0; nt < 8; nt++) {
                uint2 bv = *(uint2*)((char*)cB + ((wn * 8 + nt) * 32 + lane) * 8);
                unsigned b[2] = {bv.x, bv.y};
                mma16(cc[0][nt], a[0], b);
                mma16(cc[1][nt], a[1], b);
            }
            cp_wait0(); __syncthreads();
        }
        // epilogue: bias + LN stats
#pragma unroll
        for (int nt = 0; nt < 8; nt++) {
            int col = wn * 64 + nt * 8 + 2 * t;
            float b0 = __ldg(&ctx_b[col]), b1 = __ldg(&ctx_b[col + 1]);
#pragma unroll
            for (int mt = 0; mt < 2; mt++) {
                cc[mt][nt][0] += b0; cc[mt][nt][1] += b1;
                cc[mt][nt][2] += b0; cc[mt][nt][3] += b1;
            }
        }
#pragma unroll
        for (int mt = 0; mt < 2; mt++) {
            float s0 = 0, q0 = 0, s1v = 0, q1 = 0;
#pragma unroll
            for (int nt = 0; nt < 8; nt++) {
                s0 += cc[mt][nt][0] + cc[mt][nt][1];
                q0 += cc[mt][nt][0] * cc[mt][nt][0] + cc[mt][nt][1] * cc[mt][nt][1];
                s1v += cc[mt][nt][2] + cc[mt][nt][3];
                q1 += cc[mt][nt][2] * cc[mt][nt][2] + cc[mt][nt][3] * cc[mt][nt][3];
            }
#pragma unroll
            for (int o = 1; o <= 2; o <<= 1) {
                s0 += __shfl_xor_sync(~0u, s0, o); q0 += __shfl_xor_sync(~0u, q0, o);
                s1v += __shfl_xor_sync(~0u, s1v, o); q1 += __shfl_xor_sync(~0u, q1, o);
            }
            if (t == 0) {
                sRed[wn * 128 + wm * 32 + mt * 16 + g]     = make_float2(s0, q0);
                sRed[wn * 128 + wm * 32 + mt * 16 + g + 8] = make_float2(s1v, q1);
            }
        }
        __syncthreads();
#pragma unroll
        for (int mt = 0; mt < 2; mt++)
#pragma unroll
            for (int h = 0; h < 2; h++) {
                int row = wm * 32 + mt * 16 + g + 8 * h;
                if (row >= 112) continue;
                float s = 0, q = 0;
#pragma unroll
                for (int w2 = 0; w2 < 4; w2++) {
                    float2 r2 = sRed[w2 * 128 + row]; s += r2.x; q += r2.y;
                }
                float mu = s * (1.f / FCN);
                float rs = rsqrtf(q * (1.f / FCN) - mu * mu + 1e-5f);
                float at = sAtt[row];
                int gl = row / 7;
#pragma unroll
                for (int nt = 0; nt < 8; nt++) {
                    int col = wn * 64 + nt * 8 + 2 * t;
                    float gg0 = __ldg(&ctx_g[col]),   bb0 = __ldg(&ctx_bb[col]);
                    float gg1 = __ldg(&ctx_g[col+1]), bb1 = __ldg(&ctx_bb[col+1]);
                    float v0 = fmaxf((cc[mt][nt][2*h]   - mu) * rs * gg0 + bb0, 0.f) * at;
                    float v1 = fmaxf((cc[mt][nt][2*h+1] - mu) * rs * gg1 + bb1, 0.f) * at;
                    atomicAdd(&sEff[gl * 257 + col],     v0);
                    atomicAdd(&sEff[gl * 257 + col + 1], v1);
                }
            }
    }
    __syncthreads();
    for (int idx = tid; idx < 16 * FCN; idx += 512) {
        int gg = idx >> 8, col = idx & 255;
        g_eff[(size_t)(blockIdx.x * 16 + gg) * FCN + col] = to_tf32(sEff[gg * 257 + col]);
    }
}

// ---------------------------------------------------------------------------
// Kernel 4: new_state = concat(s1, effect, x) @ out_w + out_b  (tf32)
// ---------------------------------------------------------------------------
__global__ __launch_bounds__(512, 1) void k_out(
    const float* __restrict__ xin, const float* __restrict__ bias,
    float* __restrict__ out, int dup)
{
    extern __shared__ float sm[];
    float* sA = sm;
    float* sB = sm + 2 * 128 * 36;

    const int tid = threadIdx.x;
    const int wid = tid >> 5, lane = tid & 31;
    const int g = lane >> 2, t = lane & 3;
    const int wm = wid & 3, wn = wid >> 2;
    const int R0 = blockIdx.x * 128;
    const int ar0 = (tid) >> 3,        af0 = ((tid) & 7) * 4;
    const int ar1 = (tid + 512) >> 3,  af1 = ((tid + 512) & 7) * 4;

    float c[2][8][4];
#pragma unroll
    for (int mt = 0; mt < 2; mt++)
#pragma unroll
        for (int nt = 0; nt < 8; nt++)
#pragma unroll
            for (int e = 0; e < 4; e++) c[mt][nt][e] = 0.f;

    auto ldA = [&](int kt, float4& v0, float4& v1, bool& cvt) {
        int base = kt * 32;
        if (base < FCN) {
            v0 = *(const float4*)&g_s1[(size_t)(R0 + ar0) * FCN + base + af0];
            v1 = *(const float4*)&g_s1[(size_t)(R0 + ar1) * FCN + base + af1];
            cvt = false;
        } else if (base < 2 * FCN) {
            v0 = *(const float4*)&g_eff[(size_t)(R0 + ar0) * FCN + base - FCN + af0];
            v1 = *(const float4*)&g_eff[(size_t)(R0 + ar1) * FCN + base - FCN + af1];
            cvt = false;
        } else {
            v0 = *(const float4*)&xin[(size_t)(R0 + ar0) * MDIM + base - 2 * FCN + af0];
            v1 = *(const float4*)&xin[(size_t)(R0 + ar1) * MDIM + base - 2 * FCN + af1];
            cvt = true;
        }
    };
    auto stA = [&](float* buf, float4 v0, float4 v1, bool cvt) {
        float* d0 = &buf[ar0 * 36 + af0];
        float* d1 = &buf[ar1 * 36 + af1];
        if (cvt) {
            d0[0]=to_tf32(v0.x); d0[1]=to_tf32(v0.y); d0[2]=to_tf32(v0.z); d0[3]=to_tf32(v0.w);
            d1[0]=to_tf32(v1.x); d1[1]=to_tf32(v1.y); d1[2]=to_tf32(v1.z); d1[3]=to_tf32(v1.w);
        } else {
            *(float4*)d0 = v0; *(float4*)d1 = v1;
        }
    };

    float4 a0, a1; bool cvt;
    ldA(0, a0, a1, cvt);
    stA(sA, a0, a1, cvt);
#pragma unroll
    for (int p = 0; p < 4; p++) {
        int idx = tid + 512 * p;
        int kk = idx >> 6, n4 = (idx & 63) * 4;
        cpa16(&sB[kk * LDB + n4], &g_wout[(size_t)kk * FCN + n4]);
    }
    cp_commit(); cp_wait0(); __syncthreads();

    const int T = KOUT / 32;
    for (int kt = 0; kt < T; kt++) {
        const int bt = kt & 1, bn = bt ^ 1;
        float* cA = sA + bt * 128 * 36;
        float* cB = sB + bt * 32 * LDB;
        if (kt + 1 < T) {
            float* nB = sB + bn * 32 * LDB;
#pragma unroll
            for (int p = 0; p < 4; p++) {
                int idx = tid + 512 * p;
                int kk = idx >> 6, n4 = (idx & 63) * 4;
                cpa16(&nB[kk * LDB + n4], &g_wout[(size_t)((kt + 1) * 32 + kk) * FCN + n4]);
            }
            cp_commit();
            ldA(kt + 1, a0, a1, cvt);
        }
#pragma unroll
        for (int ks = 0; ks < 32; ks += 8) {
            unsigned a[2][4], b[8][2];
#pragma unroll
            for (int mt = 0; mt < 2; mt++) {
                int r = wm * 32 + mt * 16 + g;
                a[mt][0] = __float_as_uint(cA[r * 36 + ks + t]);
                a[mt][1] = __float_as_uint(cA[(r + 8) * 36 + ks + t]);
                a[mt][2] = __float_as_uint(cA[r * 36 + ks + t + 4]);
                a[mt][3] = __float_as_uint(cA[(r + 8) * 36 + ks + t + 4]);
            }
#pragma unroll
            for (int nt = 0; nt < 8; nt++) {
                int n = wn * 64 + nt * 8 + g;
                b[nt][0] = __float_as_uint(cB[(ks + t) * LDB + n]);
                b[nt][1] = __float_as_uint(cB[(ks + t + 4) * LDB + n]);
            }
#pragma unroll
            for (int mt = 0; mt < 2; mt++)
#pragma unroll
                for (int nt = 0; nt < 8; nt++) mma8(c[mt][nt], a[mt], b[nt]);
        }
        if (kt + 1 < T)
            stA(sA + bn * 128 * 36, a0, a1, cvt);
        cp_wait0(); __syncthreads();
    }

#pragma unroll
    for (int mt = 0; mt < 2; mt++)
#pragma unroll
        for (int h = 0; h < 2; h++) {
            int row = R0 + wm * 32 + mt * 16 + g + 8 * h;
#pragma unroll
            for (int nt = 0; nt < 8; nt++) {
                int col = wn * 64 + nt * 8 + 2 * t;
                float o0 = c[mt][nt][2 * h]     + __ldg(&bias[col]);
                float o1 = c[mt][nt][2 * h + 1] + __ldg(&bias[col + 1]);
                size_t off = (size_t)row * FCN + col;
                *(float2*)&out[off] = make_float2(o0, o1);
                if (dup) *(float2*)&out[(size_t)NR1 * FCN + off] = make_float2(o0, o1);
            }
        }
}

// ---------------------------------------------------------------------------
extern "C" void kernel_launch(void* const* d_in, const int* in_sizes, int n_in,
                              void* d_out, int out_size) {
    const float* x      = (const float*)d_in[0];
    const float* state  = (const float*)d_in[1];
    const float* enc_w  = (const float*)d_in[2];
    const float* enc_b  = (const float*)d_in[3];
    const float* enc_g  = (const float*)d_in[4];
    const float* enc_bb = (const float*)d_in[5];
    const float* core_w = (const float*)d_in[6];
    const float* core_b = (const float*)d_in[7];
    const float* core_g = (const float*)d_in[8];
    const float* core_bb= (const float*)d_in[9];
    const float* ctx_w  = (const float*)d_in[10];
    const float* ctx_b  = (const float*)d_in[11];
    const float* ctx_g  = (const float*)d_in[12];
    const float* ctx_bb = (const float*)d_in[13];
    const float* att1_w = (const float*)d_in[14];
    const float* att1_b = (const float*)d_in[15];
    const float* att_g  = (const float*)d_in[16];
    const float* att_bb = (const float*)d_in[17];
    const float* att2_w = (const float*)d_in[18];
    const float* att2_b = (const float*)d_in[19];
    const float* out_w  = (const float*)d_in[20];
    const float* out_b  = (const float*)d_in[21];
    float* out = (float*)d_out;
    int dup = (out_size >= 2 * NR1 * FCN) ? 1 : 0;

    const int smem_enc = (2 * 128 * 36 + 2 * 32 * LDB) * 4 + 4 * 128 * 8;
    const int smem_uv  = (2 * 64 * 36 + 2 * 32 * LDB2) * 4;
    const int smem_eff = 67584 + 2 * 2048 * 4 + 16 * 257 * 4
                       + 4 * 128 * 8 + 4 * 128 * 4 + 128 * 4;
    const int smem_out = (2 * 128 * 36 + 2 * 32 * LDB) * 4;

    static int attr_done = 0;
    if (!attr_done) {
        cudaFuncSetAttribute(k_enc, cudaFuncAttributeMaxDynamicSharedMemorySize, smem_enc);
        cudaFuncSetAttribute(k_uv,  cudaFuncAttributeMaxDynamicSharedMemorySize, smem_uv);
        cudaFuncSetAttribute(k_eff, cudaFuncAttributeMaxDynamicSharedMemorySize, smem_eff);
        cudaFuncSetAttribute(k_out, cudaFuncAttributeMaxDynamicSharedMemorySize, smem_out);
        attr_done = 1;
    }

    k_cvtw<<<256, 256>>>(enc_w, core_w, ctx_w, att1_w, out_w);
    k_enc<<<NR1 / 128, 512, smem_enc>>>(state, enc_b, enc_g, enc_bb);
    k_uv <<<NR1 / 64,  512, smem_uv >>>();
    k_eff<<<NR2 / 112, 512, smem_eff>>>(core_b, core_g, core_bb,
                                        ctx_b, ctx_g, ctx_bb,
                                        att1_b, att_g, att_bb,
                                        att2_w, att2_b);
    k_out<<<NR1 / 128, 512, smem_out>>>(x, out_b, out, dup);
}

// round 8
// speedup vs baseline: 4.8686x; 1.0108x over previous
#include <cuda_runtime.h>
#include <cuda_fp16.h>
#include <cstdint>
#include <math.h>

// ---------------------------------------------------------------------------
// R-NEM cell. tf32 pipeline for enc/uv/out; fp16 m16n8k16 for k_eff with
// packed per-lane fragment weights loaded DIRECTLY via LDG (no smem staging,
// no barriers in the GEMM mainloops).
//   K=8, FC=256, LAST=128, B=2048, M=1024, H=512
// core_pre[v] = U[p] + V[q] + core_b, [U|V] = s1 @ core_w (packed k-major)
// ---------------------------------------------------------------------------

#define FCN   256
#define LASTN 128
#define HDIM  512
#define MDIM  1024
#define NR1   16384
#define NR2   114688
#define KOUT  (2 * FCN + MDIM)

__device__ float g_s1[NR1 * FCN];        // tf32-rounded
__device__ float g_uv[NR1 * 2 * FCN];    // fp32
__device__ float g_eff[NR1 * FCN];       // tf32-rounded

// tf32 weights
__device__ float g_wenc[HDIM * FCN];
__device__ float g_wuv[FCN * 2 * FCN];   // packed: [k][512] = [Wtop | Wbot]
__device__ float g_wout[KOUT * FCN];

// fp16 fragment-packed weights for k_eff:
//   slot idx = (kt16 * (N/8) + n8) * 32 + lane ; uint2 = {b0, b1} frag regs
__device__ __align__(16) uint2 g_wattp[(FCN / 16) * (LASTN / 8) * 32]; // 64 KB
__device__ __align__(16) uint2 g_wctxp[(FCN / 16) * (FCN / 8) * 32];   // 128 KB

// -------------------------------- helpers ---------------------------------
__device__ __forceinline__ float to_tf32(float x) {
    unsigned u; asm("cvt.rna.tf32.f32 %0, %1;" : "=r"(u) : "f"(x));
    return __uint_as_float(u);
}
__device__ __forceinline__ void mma8(float* c, const unsigned* a, const unsigned* b) {
    asm volatile(
        "mma.sync.aligned.m16n8k8.row.col.f32.tf32.tf32.f32 "
        "{%0,%1,%2,%3}, {%4,%5,%6,%7}, {%8,%9}, {%0,%1,%2,%3};"
        : "+f"(c[0]), "+f"(c[1]), "+f"(c[2]), "+f"(c[3])
        : "r"(a[0]), "r"(a[1]), "r"(a[2]), "r"(a[3]), "r"(b[0]), "r"(b[1]));
}
__device__ __forceinline__ void mma16(float* c, const unsigned* a, const unsigned* b) {
    asm volatile(
        "mma.sync.aligned.m16n8k16.row.col.f32.f16.f16.f32 "
        "{%0,%1,%2,%3}, {%4,%5,%6,%7}, {%8,%9}, {%0,%1,%2,%3};"
        : "+f"(c[0]), "+f"(c[1]), "+f"(c[2]), "+f"(c[3])
        : "r"(a[0]), "r"(a[1]), "r"(a[2]), "r"(a[3]), "r"(b[0]), "r"(b[1]));
}
__device__ __forceinline__ void cpa16(void* dst, const void* src) {
    unsigned d = (unsigned)__cvta_generic_to_shared(dst);
    asm volatile("cp.async.cg.shared.global [%0], [%1], 16;" :: "r"(d), "l"(src));
}
__device__ __forceinline__ void cp_commit() { asm volatile("cp.async.commit_group;"); }
__device__ __forceinline__ void cp_wait0()  { asm volatile("cp.async.wait_group 0;"); }
__device__ __forceinline__ unsigned packh(float a, float b) {
    __half2 h = __floats2half2_rn(a, b);
    return *(unsigned*)&h;
}

#define LDB 264   // tf32 B tile stride
#define LDB2 520

// ---------------------------------------------------------------------------
// Kernel 0: convert/pack weights
// ---------------------------------------------------------------------------
__global__ void k_cvtw(const float* __restrict__ enc_w, const float* __restrict__ core_w,
                       const float* __restrict__ ctx_w, const float* __restrict__ att1_w,
                       const float* __restrict__ out_w)
{
    int i = blockIdx.x * blockDim.x + threadIdx.x;
    int n = gridDim.x * blockDim.x;
    for (int idx = i; idx < HDIM * FCN; idx += n) g_wenc[idx] = to_tf32(enc_w[idx]);
    for (int idx = i; idx < FCN * 2 * FCN; idx += n) {
        int k = idx >> 9, c = idx & 511;
        float v = (c < FCN) ? core_w[k * FCN + c] : core_w[(FCN + k) * FCN + (c - FCN)];
        g_wuv[idx] = to_tf32(v);
    }
    for (int idx = i; idx < KOUT * FCN; idx += n) g_wout[idx] = to_tf32(out_w[idx]);
    // fp16 fragment pack: att1_w (256x128)
    for (int idx = i; idx < (FCN/16) * (LASTN/8) * 32; idx += n) {
        int kt = idx >> 9;
        int n8 = (idx >> 5) & 15;
        int lane = idx & 31;
        int g = lane >> 2, t = lane & 3;
        int nn = n8 * 8 + g, k0 = kt * 16;
        g_wattp[idx] = make_uint2(
            packh(att1_w[(k0 + 2*t)     * LASTN + nn], att1_w[(k0 + 2*t + 1) * LASTN + nn]),
            packh(att1_w[(k0 + 8 + 2*t) * LASTN + nn], att1_w[(k0 + 9 + 2*t) * LASTN + nn]));
    }
    // fp16 fragment pack: ctx_w (256x256)
    for (int idx = i; idx < (FCN/16) * (FCN/8) * 32; idx += n) {
        int kt = idx >> 10;
        int n8 = (idx >> 5) & 31;
        int lane = idx & 31;
        int g = lane >> 2, t = lane & 3;
        int nn = n8 * 8 + g, k0 = kt * 16;
        g_wctxp[idx] = make_uint2(
            packh(ctx_w[(k0 + 2*t)     * FCN + nn], ctx_w[(k0 + 2*t + 1) * FCN + nn]),
            packh(ctx_w[(k0 + 8 + 2*t) * FCN + nn], ctx_w[(k0 + 9 + 2*t) * FCN + nn]));
    }
}

// ---------------------------------------------------------------------------
// Kernel 1: s1 = relu(LN(state @ enc_w + enc_b))    (tf32, unchanged)
// ---------------------------------------------------------------------------
__global__ __launch_bounds__(512, 1) void k_enc(
    const float* __restrict__ state, const float* __restrict__ bias,
    const float* __restrict__ gam, const float* __restrict__ bet)
{
    extern __shared__ float sm[];
    float*  sA  = sm;
    float*  sB  = sm + 2 * 128 * 36;
    float2* red = (float2*)(sB + 2 * 32 * LDB);

    const int tid = threadIdx.x;
    const int wid = tid >> 5, lane = tid & 31;
    const int g = lane >> 2, t = lane & 3;
    const int wm = wid & 3, wn = wid >> 2;
    const int R0 = blockIdx.x * 128;
    const int ar0 = (tid) >> 3,        af0 = ((tid) & 7) * 4;
    const int ar1 = (tid + 512) >> 3,  af1 = ((tid + 512) & 7) * 4;

    float c[2][8][4];
#pragma unroll
    for (int mt = 0; mt < 2; mt++)
#pragma unroll
        for (int nt = 0; nt < 8; nt++)
#pragma unroll
            for (int e = 0; e < 4; e++) c[mt][nt][e] = 0.f;

    float4 a0, a1;
    a0 = *(const float4*)&state[(size_t)(R0 + ar0) * HDIM + af0];
    a1 = *(const float4*)&state[(size_t)(R0 + ar1) * HDIM + af1];
    {
        float* d0 = &sA[ar0 * 36 + af0];
        d0[0]=to_tf32(a0.x); d0[1]=to_tf32(a0.y); d0[2]=to_tf32(a0.z); d0[3]=to_tf32(a0.w);
        float* d1 = &sA[ar1 * 36 + af1];
        d1[0]=to_tf32(a1.x); d1[1]=to_tf32(a1.y); d1[2]=to_tf32(a1.z); d1[3]=to_tf32(a1.w);
    }
#pragma unroll
    for (int p = 0; p < 4; p++) {
        int idx = tid + 512 * p;
        int kk = idx >> 6, n4 = (idx & 63) * 4;
        cpa16(&sB[kk * LDB + n4], &g_wenc[(size_t)kk * FCN + n4]);
    }
    cp_commit(); cp_wait0(); __syncthreads();

    const int T = HDIM / 32;
    for (int kt = 0; kt < T; kt++) {
        const int bt = kt & 1, bn = bt ^ 1;
        float* cA = sA + bt * 128 * 36;
        float* cB = sB + bt * 32 * LDB;
        if (kt + 1 < T) {
            float* nB = sB + bn * 32 * LDB;
#pragma unroll
            for (int p = 0; p < 4; p++) {
                int idx = tid + 512 * p;
                int kk = idx >> 6, n4 = (idx & 63) * 4;
                cpa16(&nB[kk * LDB + n4], &g_wenc[(size_t)((kt + 1) * 32 + kk) * FCN + n4]);
            }
            cp_commit();
            a0 = *(const float4*)&state[(size_t)(R0 + ar0) * HDIM + (kt + 1) * 32 + af0];
            a1 = *(const float4*)&state[(size_t)(R0 + ar1) * HDIM + (kt + 1) * 32 + af1];
        }
#pragma unroll
        for (int ks = 0; ks < 32; ks += 8) {
            unsigned a[2][4], b[8][2];
#pragma unroll
            for (int mt = 0; mt < 2; mt++) {
                int r = wm * 32 + mt * 16 + g;
                a[mt][0] = __float_as_uint(cA[r * 36 + ks + t]);
                a[mt][1] = __float_as_uint(cA[(r + 8) * 36 + ks + t]);
                a[mt][2] = __float_as_uint(cA[r * 36 + ks + t + 4]);
                a[mt][3] = __float_as_uint(cA[(r + 8) * 36 + ks + t + 4]);
            }
#pragma unroll
            for (int nt = 0; nt < 8; nt++) {
                int n = wn * 64 + nt * 8 + g;
                b[nt][0] = __float_as_uint(cB[(ks + t) * LDB + n]);
                b[nt][1] = __float_as_uint(cB[(ks + t + 4) * LDB + n]);
            }
#pragma unroll
            for (int mt = 0; mt < 2; mt++)
#pragma unroll
                for (int nt = 0; nt < 8; nt++) mma8(c[mt][nt], a[mt], b[nt]);
        }
        if (kt + 1 < T) {
            float* nA = sA + bn * 128 * 36;
            float* d0 = &nA[ar0 * 36 + af0];
            d0[0]=to_tf32(a0.x); d0[1]=to_tf32(a0.y); d0[2]=to_tf32(a0.z); d0[3]=to_tf32(a0.w);
            float* d1 = &nA[ar1 * 36 + af1];
            d1[0]=to_tf32(a1.x); d1[1]=to_tf32(a1.y); d1[2]=to_tf32(a1.z); d1[3]=to_tf32(a1.w);
        }
        cp_wait0(); __syncthreads();
    }

#pragma unroll
    for (int nt = 0; nt < 8; nt++) {
        int col = wn * 64 + nt * 8 + 2 * t;
        float b0 = __ldg(&bias[col]), b1 = __ldg(&bias[col + 1]);
#pragma unroll
        for (int mt = 0; mt < 2; mt++) {
            c[mt][nt][0] += b0; c[mt][nt][1] += b1;
            c[mt][nt][2] += b0; c[mt][nt][3] += b1;
        }
    }
#pragma unroll
    for (int mt = 0; mt < 2; mt++) {
        float s0 = 0, q0 = 0, s1v = 0, q1 = 0;
#pragma unroll
        for (int nt = 0; nt < 8; nt++) {
            s0 += c[mt][nt][0] + c[mt][nt][1];
            q0 += c[mt][nt][0] * c[mt][nt][0] + c[mt][nt][1] * c[mt][nt][1];
            s1v += c[mt][nt][2] + c[mt][nt][3];
            q1 += c[mt][nt][2] * c[mt][nt][2] + c[mt][nt][3] * c[mt][nt][3];
        }
#pragma unroll
        for (int o = 1; o <= 2; o <<= 1) {
            s0 += __shfl_xor_sync(~0u, s0, o); q0 += __shfl_xor_sync(~0u, q0, o);
            s1v += __shfl_xor_sync(~0u, s1v, o); q1 += __shfl_xor_sync(~0u, q1, o);
        }
        if (t == 0) {
            red[wn * 128 + wm * 32 + mt * 16 + g]     = make_float2(s0, q0);
            red[wn * 128 + wm * 32 + mt * 16 + g + 8] = make_float2(s1v, q1);
        }
    }
    __syncthreads();
#pragma unroll
    for (int mt = 0; mt < 2; mt++)
#pragma unroll
        for (int h = 0; h < 2; h++) {
            int row = wm * 32 + mt * 16 + g + 8 * h;
            float s = 0, q = 0;
#pragma unroll
            for (int w2 = 0; w2 < 4; w2++) {
                float2 r2 = red[w2 * 128 + row]; s += r2.x; q += r2.y;
            }
            float mu = s * (1.f / FCN);
            float rs = rsqrtf(q * (1.f / FCN) - mu * mu + 1e-5f);
#pragma unroll
            for (int nt = 0; nt < 8; nt++) {
                int col = wn * 64 + nt * 8 + 2 * t;
                float o0 = fmaxf((c[mt][nt][2 * h]     - mu) * rs * __ldg(&gam[col])     + __ldg(&bet[col]),     0.f);
                float o1 = fmaxf((c[mt][nt][2 * h + 1] - mu) * rs * __ldg(&gam[col + 1]) + __ldg(&bet[col + 1]), 0.f);
                *(float2*)&g_s1[(size_t)(R0 + row) * FCN + col] =
                    make_float2(to_tf32(o0), to_tf32(o1));
            }
        }
}

// ---------------------------------------------------------------------------
// Kernel 2: [U|V] = s1 @ packed(core_w)   (tf32, unchanged)
// ---------------------------------------------------------------------------
__global__ __launch_bounds__(512, 1) void k_uv()
{
    extern __shared__ float sm[];
    float* sA = sm;
    float* sB = sm + 2 * 64 * 36;

    const int tid = threadIdx.x;
    const int wid = tid >> 5, lane = tid & 31;
    const int g = lane >> 2, t = lane & 3;
    const int wm = wid & 1, wn = wid >> 1;
    const int R0 = blockIdx.x * 64;
    const int ar = tid >> 3, af = (tid & 7) * 4;

    float c[2][8][4];
#pragma unroll
    for (int mt = 0; mt < 2; mt++)
#pragma unroll
        for (int nt = 0; nt < 8; nt++)
#pragma unroll
            for (int e = 0; e < 4; e++) c[mt][nt][e] = 0.f;

    float4 a0;
    a0 = *(const float4*)&g_s1[(size_t)(R0 + ar) * FCN + af];
    *(float4*)&sA[ar * 36 + af] = a0;
#pragma unroll
    for (int p = 0; p < 8; p++) {
        int idx = tid + 512 * p;
        int kk = idx >> 7, n4 = (idx & 127) * 4;
        cpa16(&sB[kk * LDB2 + n4], &g_wuv[(size_t)kk * 512 + n4]);
    }
    cp_commit(); cp_wait0(); __syncthreads();

    const int T = FCN / 32;
    for (int kt = 0; kt < T; kt++) {
        const int bt = kt & 1, bn = bt ^ 1;
        float* cA = sA + bt * 64 * 36;
        float* cB = sB + bt * 32 * LDB2;
        if (kt + 1 < T) {
            float* nB = sB + bn * 32 * LDB2;
#pragma unroll
            for (int p = 0; p < 8; p++) {
                int idx = tid + 512 * p;
                int kk = idx >> 7, n4 = (idx & 127) * 4;
                cpa16(&nB[kk * LDB2 + n4], &g_wuv[(size_t)((kt + 1) * 32 + kk) * 512 + n4]);
            }
            cp_commit();
            a0 = *(const float4*)&g_s1[(size_t)(R0 + ar) * FCN + (kt + 1) * 32 + af];
        }
#pragma unroll
        for (int ks = 0; ks < 32; ks += 8) {
            unsigned a[2][4], b[8][2];
#pragma unroll
            for (int mt = 0; mt < 2; mt++) {
                int r = wm * 32 + mt * 16 + g;
                a[mt][0] = __float_as_uint(cA[r * 36 + ks + t]);
                a[mt][1] = __float_as_uint(cA[(r + 8) * 36 + ks + t]);
                a[mt][2] = __float_as_uint(cA[r * 36 + ks + t + 4]);
                a[mt][3] = __float_as_uint(cA[(r + 8) * 36 + ks + t + 4]);
            }
#pragma unroll
            for (int nt = 0; nt < 8; nt++) {
                int n = wn * 64 + nt * 8 + g;
                b[nt][0] = __float_as_uint(cB[(ks + t) * LDB2 + n]);
                b[nt][1] = __float_as_uint(cB[(ks + t + 4) * LDB2 + n]);
            }
#pragma unroll
            for (int mt = 0; mt < 2; mt++)
#pragma unroll
                for (int nt = 0; nt < 8; nt++) mma8(c[mt][nt], a[mt], b[nt]);
        }
        if (kt + 1 < T)
            *(float4*)&sA[bn * 64 * 36 + ar * 36 + af] = a0;
        cp_wait0(); __syncthreads();
    }

#pragma unroll
    for (int mt = 0; mt < 2; mt++)
#pragma unroll
        for (int h = 0; h < 2; h++) {
            int row = R0 + wm * 32 + mt * 16 + g + 8 * h;
#pragma unroll
            for (int nt = 0; nt < 8; nt++) {
                int col = wn * 64 + nt * 8 + 2 * t;
                *(float2*)&g_uv[(size_t)row * 512 + col] =
                    make_float2(c[mt][nt][2 * h], c[mt][nt][2 * h + 1]);
            }
        }
}

// ---------------------------------------------------------------------------
// Kernel 3 (fp16): packed core rows in smem; B fragments via direct LDG.
// 512 threads, 16 warps (4 row x 4 col). Tile 128 rows (112 real).
// Packed A: [mt16(8)][kt16(16)] blocks of 528B; slot = lane*16B = a0..a3.
// NO barriers inside either GEMM mainloop.
// ---------------------------------------------------------------------------
__global__ __launch_bounds__(512, 1) void k_eff(
    const float* __restrict__ core_b, const float* __restrict__ core_g,
    const float* __restrict__ core_bb,
    const float* __restrict__ ctx_b,
    const float* __restrict__ ctx_g, const float* __restrict__ ctx_bb,
    const float* __restrict__ a1_b,
    const float* __restrict__ att_g, const float* __restrict__ att_bb,
    const float* __restrict__ a2W,  const float* __restrict__ a2_b)
{
    extern __shared__ float sm[];
    char*   sAp  = (char*)sm;                   // 8*16*528 = 67584 B
    float*  sEff = sm + 67584 / 4;              // [16][257]
    float2* sRed = (float2*)(sEff + 16 * 257);  // [4][128]
    float*  sDot = (float*)(sRed + 4 * 128);    // [4][128]
    float*  sAtt = sDot + 4 * 128;              // [128]

    const int tid = threadIdx.x;
    const int wid = tid >> 5, lane = tid & 31;
    const int g = lane >> 2, t = lane & 3;
    const int wm = wid & 3, wn = wid >> 2;
    const int R0 = blockIdx.x * 112;
    const int NKT = FCN / 16;   // 16 k16-tiles

    for (int idx = tid; idx < 16 * 257; idx += 512) sEff[idx] = 0.f;
    {   // zero pad slab mt=7 (rows 112..127)
        float* z = (float*)(sAp + 7 * 16 * 528);
        for (int i = tid; i < 16 * 528 / 4; i += 512) z[i] = 0.f;
    }

    // ---- phase a: core rows -> packed fp16 sA. lane owns col pairs 2lane+64e
    {
#pragma unroll
        for (int rr = 0; rr < 7; rr++) {
            int lrow = wid * 7 + rr;
            int v = R0 + lrow;
            int p = v / 7;
            int jj = v - p * 7;
            int i = p & 7;
            int j = jj + (jj >= i ? 1 : 0);
            int q = (p & ~7) + j;
            float2 val[4];
            float s = 0.f, s2 = 0.f;
#pragma unroll
            for (int e = 0; e < 4; e++) {
                int col = 2 * lane + 64 * e;
                float2 u  = *(const float2*)&g_uv[(size_t)p * 512 + col];
                float2 vq = *(const float2*)&g_uv[(size_t)q * 512 + 256 + col];
                float2 cb = *(const float2*)&core_b[col];
                val[e].x = u.x + vq.x + cb.x;
                val[e].y = u.y + vq.y + cb.y;
                s += val[e].x + val[e].y;
                s2 += val[e].x * val[e].x + val[e].y * val[e].y;
            }
#pragma unroll
            for (int o = 16; o; o >>= 1) {
                s  += __shfl_xor_sync(~0u, s,  o);
                s2 += __shfl_xor_sync(~0u, s2, o);
            }
            float mu = s * (1.f / FCN);
            float rs = rsqrtf(s2 * (1.f / FCN) - mu * mu + 1e-5f);
            int mtile = lrow >> 4, gg = lrow & 7, hm = (lrow >> 3) & 1;
            int tt = lane & 3, hk = (lane >> 2) & 1;
#pragma unroll
            for (int e = 0; e < 4; e++) {
                int col = 2 * lane + 64 * e;
                float2 cg = *(const float2*)&core_g[col];
                float2 cbb = *(const float2*)&core_bb[col];
                float o0 = fmaxf((val[e].x - mu) * rs * cg.x + cbb.x, 0.f);
                float o1 = fmaxf((val[e].y - mu) * rs * cg.y + cbb.y, 0.f);
                int kt = (lane >> 3) + 4 * e;
                unsigned off = (unsigned)((mtile * 16 + kt) * 528
                                          + ((gg << 2) + tt) * 16 + (hk * 2 + hm) * 4);
                *(unsigned*)(sAp + off) = packh(o0, o1);
            }
        }
    }
    __syncthreads();

    // ---- pass 1: attention (N=128, warp owns 32 cols = 4 n8-tiles) ----
    {
        float ca[2][4][4];
#pragma unroll
        for (int mt = 0; mt < 2; mt++)
#pragma unroll
            for (int nt = 0; nt < 4; nt++)
#pragma unroll
                for (int e = 0; e < 4; e++) ca[mt][nt][e] = 0.f;

#pragma unroll
        for (int kt = 0; kt < NKT; kt++) {
            unsigned a[2][4];
#pragma unroll
            for (int mt = 0; mt < 2; mt++) {
                uint4 av = *(uint4*)(sAp + ((wm * 2 + mt) * 16 + kt) * 528 + lane * 16);
                a[mt][0] = av.x; a[mt][1] = av.y; a[mt][2] = av.z; a[mt][3] = av.w;
            }
#pragma unroll
            for (int nt = 0; nt < 4; nt++) {
                uint2 bv = __ldg(&g_wattp[(size_t)(kt * 16 + wn * 4 + nt) * 32 + lane]);
                unsigned b[2] = {bv.x, bv.y};
                mma16(ca[0][nt], a[0], b);
                mma16(ca[1][nt], a[1], b);
            }
        }
        // epilogue: bias + LN(128) stats
#pragma unroll
        for (int nt = 0; nt < 4; nt++) {
            int col = wn * 32 + nt * 8 + 2 * t;
            float b0 = __ldg(&a1_b[col]), b1 = __ldg(&a1_b[col + 1]);
#pragma unroll
            for (int mt = 0; mt < 2; mt++) {
                ca[mt][nt][0] += b0; ca[mt][nt][1] += b1;
                ca[mt][nt][2] += b0; ca[mt][nt][3] += b1;
            }
        }
#pragma unroll
        for (int mt = 0; mt < 2; mt++) {
            float s0 = 0, q0 = 0, s1v = 0, q1 = 0;
#pragma unroll
            for (int nt = 0; nt < 4; nt++) {
                s0 += ca[mt][nt][0] + ca[mt][nt][1];
                q0 += ca[mt][nt][0] * ca[mt][nt][0] + ca[mt][nt][1] * ca[mt][nt][1];
                s1v += ca[mt][nt][2] + ca[mt][nt][3];
                q1 += ca[mt][nt][2] * ca[mt][nt][2] + ca[mt][nt][3] * ca[mt][nt][3];
            }
#pragma unroll
            for (int o = 1; o <= 2; o <<= 1) {
                s0 += __shfl_xor_sync(~0u, s0, o); q0 += __shfl_xor_sync(~0u, q0, o);
                s1v += __shfl_xor_sync(~0u, s1v, o); q1 += __shfl_xor_sync(~0u, q1, o);
            }
            if (t == 0) {
                sRed[wn * 128 + wm * 32 + mt * 16 + g]     = make_float2(s0, q0);
                sRed[wn * 128 + wm * 32 + mt * 16 + g + 8] = make_float2(s1v, q1);
            }
        }
        __syncthreads();
#pragma unroll
        for (int mt = 0; mt < 2; mt++)
#pragma unroll
            for (int h = 0; h < 2; h++) {
                int row = wm * 32 + mt * 16 + g + 8 * h;
                float s = 0, q = 0;
#pragma unroll
                for (int w2 = 0; w2 < 4; w2++) {
                    float2 r2 = sRed[w2 * 128 + row]; s += r2.x; q += r2.y;
                }
                float mu = s * (1.f / LASTN);
                float rs = rsqrtf(q * (1.f / LASTN) - mu * mu + 1e-5f);
                float d = 0.f;
#pragma unroll
                for (int nt = 0; nt < 4; nt++) {
                    int col = wn * 32 + nt * 8 + 2 * t;
                    float gg0 = __ldg(&att_g[col]),   bb0 = __ldg(&att_bb[col]),   w0 = __ldg(&a2W[col]);
                    float gg1 = __ldg(&att_g[col+1]), bb1 = __ldg(&att_bb[col+1]), w1 = __ldg(&a2W[col+1]);
                    d += tanhf((ca[mt][nt][2*h]   - mu) * rs * gg0 + bb0) * w0;
                    d += tanhf((ca[mt][nt][2*h+1] - mu) * rs * gg1 + bb1) * w1;
                }
#pragma unroll
                for (int o = 1; o <= 2; o <<= 1) d += __shfl_xor_sync(~0u, d, o);
                if (t == 0) sDot[wn * 128 + row] = d;
            }
        __syncthreads();
        if (wid < 4) {
            int row = wid * 32 + lane;
            float a2b = __ldg(&a2_b[0]);
            float d = sDot[row] + sDot[128 + row] + sDot[256 + row] + sDot[384 + row];
            sAtt[row] = 1.f / (1.f + expf(-(d + a2b)));
        }
        __syncthreads();
    }

    // ---- pass 2: ctx (N=256, warp owns 64 cols = 8 n8-tiles) + effect ----
    {
        float cc[2][8][4];
#pragma unroll
        for (int mt = 0; mt < 2; mt++)
#pragma unroll
            for (int nt = 0; nt < 8; nt++)
#pragma unroll
                for (int e = 0; e < 4; e++) cc[mt][nt][e] = 0.f;

#pragma unroll 4
        for (int kt = 0; kt < NKT; kt++) {
            unsigned a[2][4];
#pragma unroll
            for (int mt = 0; mt < 2; mt++) {
                uint4 av = *(uint4*)(sAp + ((wm * 2 + mt) * 16 + kt) * 528 + lane * 16);
                a[mt][0] = av.x; a[mt][1] = av.y; a[mt][2] = av.z; a[mt][3] = av.w;
            }
#pragma unroll
            for (int nt = 0; nt < 8; nt++) {
                uint2 bv = __ldg(&g_wctxp[(size_t)(kt * 32 + wn * 8 + nt) * 32 + lane]);
                unsigned b[2] = {bv.x, bv.y};
                mma16(cc[0][nt], a[0], b);
                mma16(cc[1][nt], a[1], b);
            }
        }
        // epilogue: bias + LN stats
#pragma unroll
        for (int nt = 0; nt < 8; nt++) {
            int col = wn * 64 + nt * 8 + 2 * t;
            float b0 = __ldg(&ctx_b[col]), b1 = __ldg(&ctx_b[col + 1]);
#pragma unroll
            for (int mt = 0; mt < 2; mt++) {
                cc[mt][nt][0] += b0; cc[mt][nt][1] += b1;
                cc[mt][nt][2] += b0; cc[mt][nt][3] += b1;
            }
        }
#pragma unroll
        for (int mt = 0; mt < 2; mt++) {
            float s0 = 0, q0 = 0, s1v = 0, q1 = 0;
#pragma unroll
            for (int nt = 0; nt < 8; nt++) {
                s0 += cc[mt][nt][0] + cc[mt][nt][1];
                q0 += cc[mt][nt][0] * cc[mt][nt][0] + cc[mt][nt][1] * cc[mt][nt][1];
                s1v += cc[mt][nt][2] + cc[mt][nt][3];
                q1 += cc[mt][nt][2] * cc[mt][nt][2] + cc[mt][nt][3] * cc[mt][nt][3];
            }
#pragma unroll
            for (int o = 1; o <= 2; o <<= 1) {
                s0 += __shfl_xor_sync(~0u, s0, o); q0 += __shfl_xor_sync(~0u, q0, o);
                s1v += __shfl_xor_sync(~0u, s1v, o); q1 += __shfl_xor_sync(~0u, q1, o);
            }
            if (t == 0) {
                sRed[wn * 128 + wm * 32 + mt * 16 + g]     = make_float2(s0, q0);
                sRed[wn * 128 + wm * 32 + mt * 16 + g + 8] = make_float2(s1v, q1);
            }
        }
        __syncthreads();
#pragma unroll
        for (int mt = 0; mt < 2; mt++)
#pragma unroll
            for (int h = 0; h < 2; h++) {
                int row = wm * 32 + mt * 16 + g + 8 * h;
                if (row >= 112) continue;
                float s = 0, q = 0;
#pragma unroll
                for (int w2 = 0; w2 < 4; w2++) {
                    float2 r2 = sRed[w2 * 128 + row]; s += r2.x; q += r2.y;
                }
                float mu = s * (1.f / FCN);
                float rs = rsqrtf(q * (1.f / FCN) - mu * mu + 1e-5f);
                float at = sAtt[row];
                int gl = row / 7;
#pragma unroll
                for (int nt = 0; nt < 8; nt++) {
                    int col = wn * 64 + nt * 8 + 2 * t;
                    float gg0 = __ldg(&ctx_g[col]),   bb0 = __ldg(&ctx_bb[col]);
                    float gg1 = __ldg(&ctx_g[col+1]), bb1 = __ldg(&ctx_bb[col+1]);
                    float v0 = fmaxf((cc[mt][nt][2*h]   - mu) * rs * gg0 + bb0, 0.f) * at;
                    float v1 = fmaxf((cc[mt][nt][2*h+1] - mu) * rs * gg1 + bb1, 0.f) * at;
                    atomicAdd(&sEff[gl * 257 + col],     v0);
                    atomicAdd(&sEff[gl * 257 + col + 1], v1);
                }
            }
    }
    __syncthreads();
    for (int idx = tid; idx < 16 * FCN; idx += 512) {
        int gg = idx >> 8, col = idx & 255;
        g_eff[(size_t)(blockIdx.x * 16 + gg) * FCN + col] = to_tf32(sEff[gg * 257 + col]);
    }
}

// ---------------------------------------------------------------------------
// Kernel 4: new_state = concat(s1, effect, x) @ out_w + out_b  (tf32)
// ---------------------------------------------------------------------------
__global__ __launch_bounds__(512, 1) void k_out(
    const float* __restrict__ xin, const float* __restrict__ bias,
    float* __restrict__ out, int dup)
{
    extern __shared__ float sm[];
    float* sA = sm;
    float* sB = sm + 2 * 128 * 36;

    const int tid = threadIdx.x;
    const int wid = tid >> 5, lane = tid & 31;
    const int g = lane >> 2, t = lane & 3;
    const int wm = wid & 3, wn = wid >> 2;
    const int R0 = blockIdx.x * 128;
    const int ar0 = (tid) >> 3,        af0 = ((tid) & 7) * 4;
    const int ar1 = (tid + 512) >> 3,  af1 = ((tid + 512) & 7) * 4;

    float c[2][8][4];
#pragma unroll
    for (int mt = 0; mt < 2; mt++)
#pragma unroll
        for (int nt = 0; nt < 8; nt++)
#pragma unroll
            for (int e = 0; e < 4; e++) c[mt][nt][e] = 0.f;

    auto ldA = [&](int kt, float4& v0, float4& v1, bool& cvt) {
        int base = kt * 32;
        if (base < FCN) {
            v0 = *(const float4*)&g_s1[(size_t)(R0 + ar0) * FCN + base + af0];
            v1 = *(const float4*)&g_s1[(size_t)(R0 + ar1) * FCN + base + af1];
            cvt = false;
        } else if (base < 2 * FCN) {
            v0 = *(const float4*)&g_eff[(size_t)(R0 + ar0) * FCN + base - FCN + af0];
            v1 = *(const float4*)&g_eff[(size_t)(R0 + ar1) * FCN + base - FCN + af1];
            cvt = false;
        } else {
            v0 = *(const float4*)&xin[(size_t)(R0 + ar0) * MDIM + base - 2 * FCN + af0];
            v1 = *(const float4*)&xin[(size_t)(R0 + ar1) * MDIM + base - 2 * FCN + af1];
            cvt = true;
        }
    };
    auto stA = [&](float* buf, float4 v0, float4 v1, bool cvt) {
        float* d0 = &buf[ar0 * 36 + af0];
        float* d1 = &buf[ar1 * 36 + af1];
        if (cvt) {
            d0[0]=to_tf32(v0.x); d0[1]=to_tf32(v0.y); d0[2]=to_tf32(v0.z); d0[3]=to_tf32(v0.w);
            d1[0]=to_tf32(v1.x); d1[1]=to_tf32(v1.y); d1[2]=to_tf32(v1.z); d1[3]=to_tf32(v1.w);
        } else {
            *(float4*)d0 = v0; *(float4*)d1 = v1;
        }
    };

    float4 a0, a1; bool cvt;
    ldA(0, a0, a1, cvt);
    stA(sA, a0, a1, cvt);
#pragma unroll
    for (int p = 0; p < 4; p++) {
        int idx = tid + 512 * p;
        int kk = idx >> 6, n4 = (idx & 63) * 4;
        cpa16(&sB[kk * LDB + n4], &g_wout[(size_t)kk * FCN + n4]);
    }
    cp_commit(); cp_wait0(); __syncthreads();

    const int T = KOUT / 32;
    for (int kt = 0; kt < T; kt++) {
        const int bt = kt & 1, bn = bt ^ 1;
        float* cA = sA + bt * 128 * 36;
        float* cB = sB + bt * 32 * LDB;
        if (kt + 1 < T) {
            float* nB = sB + bn * 32 * LDB;
#pragma unroll
            for (int p = 0; p < 4; p++) {
                int idx = tid + 512 * p;
                int kk = idx >> 6, n4 = (idx & 63) * 4;
                cpa16(&nB[kk * LDB + n4], &g_wout[(size_t)((kt + 1) * 32 + kk) * FCN + n4]);
            }
            cp_commit();
            ldA(kt + 1, a0, a1, cvt);
        }
#pragma unroll
        for (int ks = 0; ks < 32; ks += 8) {
            unsigned a[2][4], b[8][2];
#pragma unroll
            for (int mt = 0; mt < 2; mt++) {
                int r = wm * 32 + mt * 16 + g;
                a[mt][0] = __float_as_uint(cA[r * 36 + ks + t]);
                a[mt][1] = __float_as_uint(cA[(r + 8) * 36 + ks + t]);
                a[mt][2] = __float_as_uint(cA[r * 36 + ks + t + 4]);
                a[mt][3] = __float_as_uint(cA[(r + 8) * 36 + ks + t + 4]);
            }
#pragma unroll
            for (int nt = 0; nt < 8; nt++) {
                int n = wn * 64 + nt * 8 + g;
                b[nt][0] = __float_as_uint(cB[(ks + t) * LDB + n]);
                b[nt][1] = __float_as_uint(cB[(ks + t + 4) * LDB + n]);
            }
#pragma unroll
            for (int mt = 0; mt < 2; mt++)
#pragma unroll
                for (int nt = 0; nt < 8; nt++) mma8(c[mt][nt], a[mt], b[nt]);
        }
        if (kt + 1 < T)
            stA(sA + bn * 128 * 36, a0, a1, cvt);
        cp_wait0(); __syncthreads();
    }

#pragma unroll
    for (int mt = 0; mt < 2; mt++)
#pragma unroll
        for (int h = 0; h < 2; h++) {
            int row = R0 + wm * 32 + mt * 16 + g + 8 * h;
#pragma unroll
            for (int nt = 0; nt < 8; nt++) {
                int col = wn * 64 + nt * 8 + 2 * t;
                float o0 = c[mt][nt][2 * h]     + __ldg(&bias[col]);
                float o1 = c[mt][nt][2 * h + 1] + __ldg(&bias[col + 1]);
                size_t off = (size_t)row * FCN + col;
                *(float2*)&out[off] = make_float2(o0, o1);
                if (dup) *(float2*)&out[(size_t)NR1 * FCN + off] = make_float2(o0, o1);
            }
        }
}

// ---------------------------------------------------------------------------
extern "C" void kernel_launch(void* const* d_in, const int* in_sizes, int n_in,
                              void* d_out, int out_size) {
    const float* x      = (const float*)d_in[0];
    const float* state  = (const float*)d_in[1];
    const float* enc_w  = (const float*)d_in[2];
    const float* enc_b  = (const float*)d_in[3];
    const float* enc_g  = (const float*)d_in[4];
    const float* enc_bb = (const float*)d_in[5];
    const float* core_w = (const float*)d_in[6];
    const float* core_b = (const float*)d_in[7];
    const float* core_g = (const float*)d_in[8];
    const float* core_bb= (const float*)d_in[9];
    const float* ctx_w  = (const float*)d_in[10];
    const float* ctx_b  = (const float*)d_in[11];
    const float* ctx_g  = (const float*)d_in[12];
    const float* ctx_bb = (const float*)d_in[13];
    const float* att1_w = (const float*)d_in[14];
    const float* att1_b = (const float*)d_in[15];
    const float* att_g  = (const float*)d_in[16];
    const float* att_bb = (const float*)d_in[17];
    const float* att2_w = (const float*)d_in[18];
    const float* att2_b = (const float*)d_in[19];
    const float* out_w  = (const float*)d_in[20];
    const float* out_b  = (const float*)d_in[21];
    float* out = (float*)d_out;
    int dup = (out_size >= 2 * NR1 * FCN) ? 1 : 0;

    const int smem_enc = (2 * 128 * 36 + 2 * 32 * LDB) * 4 + 4 * 128 * 8;
    const int smem_uv  = (2 * 64 * 36 + 2 * 32 * LDB2) * 4;
    const int smem_eff = 67584 + 16 * 257 * 4
                       + 4 * 128 * 8 + 4 * 128 * 4 + 128 * 4;
    const int smem_out = (2 * 128 * 36 + 2 * 32 * LDB) * 4;

    static int attr_done = 0;
    if (!attr_done) {
        cudaFuncSetAttribute(k_enc, cudaFuncAttributeMaxDynamicSharedMemorySize, smem_enc);
        cudaFuncSetAttribute(k_uv,  cudaFuncAttributeMaxDynamicSharedMemorySize, smem_uv);
        cudaFuncSetAttribute(k_eff, cudaFuncAttributeMaxDynamicSharedMemorySize, smem_eff);
        cudaFuncSetAttribute(k_out, cudaFuncAttributeMaxDynamicSharedMemorySize, smem_out);
        attr_done = 1;
    }

    k_cvtw<<<256, 256>>>(enc_w, core_w, ctx_w, att1_w, out_w);
    k_enc<<<NR1 / 128, 512, smem_enc>>>(state, enc_b, enc_g, enc_bb);
    k_uv <<<NR1 / 64,  512, smem_uv >>>();
    k_eff<<<NR2 / 112, 512, smem_eff>>>(core_b, core_g, core_bb,
                                        ctx_b, ctx_g, ctx_bb,
                                        att1_b, att_g, att_bb,
                                        att2_w, att2_b);
    k_out<<<NR1 / 128, 512, smem_out>>>(x, out_b, out, dup);
}

// round 9
// speedup vs baseline: 5.4268x; 1.1147x over previous
#include <cuda_runtime.h>
#include <cuda_fp16.h>
#include <cstdint>
#include <math.h>

// ---------------------------------------------------------------------------
// R-NEM cell. tf32 pipeline for enc/uv/out; fp16 m16n8k16 for k_eff.
// R9: k_eff = 256-thread CTAs (2 CTAs/SM for epilogue overlap), 56-row tiles,
//     uint4-packed B fragments (1 LDG.128 = 2 n8 fragments).
//   K=8, FC=256, LAST=128, B=2048, M=1024, H=512
// core_pre[v] = U[p] + V[q] + core_b, [U|V] = s1 @ core_w (packed k-major)
// ---------------------------------------------------------------------------

#define FCN   256
#define LASTN 128
#define HDIM  512
#define MDIM  1024
#define NR1   16384
#define NR2   114688
#define KOUT  (2 * FCN + MDIM)

__device__ float g_s1[NR1 * FCN];        // tf32-rounded
__device__ float g_uv[NR1 * 2 * FCN];    // fp32
__device__ float g_eff[NR1 * FCN];       // tf32-rounded

// tf32 weights
__device__ float g_wenc[HDIM * FCN];
__device__ float g_wuv[FCN * 2 * FCN];   // packed: [k][512] = [Wtop | Wbot]
__device__ float g_wout[KOUT * FCN];

// fp16 fragment-packed weights (uint4 = two adjacent n8 fragments):
//   slot = (kt16 * (N/16) + n16) * 32 + lane ; {b0_lo,b1_lo,b0_hi,b1_hi}
__device__ __align__(16) uint4 g_wattp4[(FCN / 16) * (LASTN / 16) * 32]; // 64 KB
__device__ __align__(16) uint4 g_wctxp4[(FCN / 16) * (FCN / 16) * 32];   // 128 KB

// -------------------------------- helpers ---------------------------------
__device__ __forceinline__ float to_tf32(float x) {
    unsigned u; asm("cvt.rna.tf32.f32 %0, %1;" : "=r"(u) : "f"(x));
    return __uint_as_float(u);
}
__device__ __forceinline__ void mma8(float* c, const unsigned* a, const unsigned* b) {
    asm volatile(
        "mma.sync.aligned.m16n8k8.row.col.f32.tf32.tf32.f32 "
        "{%0,%1,%2,%3}, {%4,%5,%6,%7}, {%8,%9}, {%0,%1,%2,%3};"
        : "+f"(c[0]), "+f"(c[1]), "+f"(c[2]), "+f"(c[3])
        : "r"(a[0]), "r"(a[1]), "r"(a[2]), "r"(a[3]), "r"(b[0]), "r"(b[1]));
}
__device__ __forceinline__ void mma16(float* c, const unsigned* a, const unsigned* b) {
    asm volatile(
        "mma.sync.aligned.m16n8k16.row.col.f32.f16.f16.f32 "
        "{%0,%1,%2,%3}, {%4,%5,%6,%7}, {%8,%9}, {%0,%1,%2,%3};"
        : "+f"(c[0]), "+f"(c[1]), "+f"(c[2]), "+f"(c[3])
        : "r"(a[0]), "r"(a[1]), "r"(a[2]), "r"(a[3]), "r"(b[0]), "r"(b[1]));
}
__device__ __forceinline__ void cpa16(void* dst, const void* src) {
    unsigned d = (unsigned)__cvta_generic_to_shared(dst);
    asm volatile("cp.async.cg.shared.global [%0], [%1], 16;" :: "r"(d), "l"(src));
}
__device__ __forceinline__ void cp_commit() { asm volatile("cp.async.commit_group;"); }
__device__ __forceinline__ void cp_wait0()  { asm volatile("cp.async.wait_group 0;"); }
__device__ __forceinline__ unsigned packh(float a, float b) {
    __half2 h = __floats2half2_rn(a, b);
    return *(unsigned*)&h;
}

#define LDB 264   // tf32 B tile stride
#define LDB2 520

// ---------------------------------------------------------------------------
// Kernel 0: convert/pack weights
// ---------------------------------------------------------------------------
__global__ void k_cvtw(const float* __restrict__ enc_w, const float* __restrict__ core_w,
                       const float* __restrict__ ctx_w, const float* __restrict__ att1_w,
                       const float* __restrict__ out_w)
{
    int i = blockIdx.x * blockDim.x + threadIdx.x;
    int n = gridDim.x * blockDim.x;
    for (int idx = i; idx < HDIM * FCN; idx += n) g_wenc[idx] = to_tf32(enc_w[idx]);
    for (int idx = i; idx < FCN * 2 * FCN; idx += n) {
        int k = idx >> 9, c = idx & 511;
        float v = (c < FCN) ? core_w[k * FCN + c] : core_w[(FCN + k) * FCN + (c - FCN)];
        g_wuv[idx] = to_tf32(v);
    }
    for (int idx = i; idx < KOUT * FCN; idx += n) g_wout[idx] = to_tf32(out_w[idx]);
    // att1_w (256x128): uint4 fragment pairs
    for (int idx = i; idx < (FCN/16) * (LASTN/16) * 32; idx += n) {
        int kt = idx >> 8;            // /(8*32)
        int n16 = (idx >> 5) & 7;
        int lane = idx & 31;
        int g = lane >> 2, t = lane & 3;
        int na = n16 * 16 + g, nb = na + 8, k0 = kt * 16;
        g_wattp4[idx] = make_uint4(
            packh(att1_w[(k0 + 2*t)     * LASTN + na], att1_w[(k0 + 2*t + 1) * LASTN + na]),
            packh(att1_w[(k0 + 8 + 2*t) * LASTN + na], att1_w[(k0 + 9 + 2*t) * LASTN + na]),
            packh(att1_w[(k0 + 2*t)     * LASTN + nb], att1_w[(k0 + 2*t + 1) * LASTN + nb]),
            packh(att1_w[(k0 + 8 + 2*t) * LASTN + nb], att1_w[(k0 + 9 + 2*t) * LASTN + nb]));
    }
    // ctx_w (256x256): uint4 fragment pairs
    for (int idx = i; idx < (FCN/16) * (FCN/16) * 32; idx += n) {
        int kt = idx >> 9;            // /(16*32)
        int n16 = (idx >> 5) & 15;
        int lane = idx & 31;
        int g = lane >> 2, t = lane & 3;
        int na = n16 * 16 + g, nb = na + 8, k0 = kt * 16;
        g_wctxp4[idx] = make_uint4(
            packh(ctx_w[(k0 + 2*t)     * FCN + na], ctx_w[(k0 + 2*t + 1) * FCN + na]),
            packh(ctx_w[(k0 + 8 + 2*t) * FCN + na], ctx_w[(k0 + 9 + 2*t) * FCN + na]),
            packh(ctx_w[(k0 + 2*t)     * FCN + nb], ctx_w[(k0 + 2*t + 1) * FCN + nb]),
            packh(ctx_w[(k0 + 8 + 2*t) * FCN + nb], ctx_w[(k0 + 9 + 2*t) * FCN + nb]));
    }
}

// ---------------------------------------------------------------------------
// Kernel 1: s1 = relu(LN(state @ enc_w + enc_b))    (tf32, unchanged)
// ---------------------------------------------------------------------------
__global__ __launch_bounds__(512, 1) void k_enc(
    const float* __restrict__ state, const float* __restrict__ bias,
    const float* __restrict__ gam, const float* __restrict__ bet)
{
    extern __shared__ float sm[];
    float*  sA  = sm;
    float*  sB  = sm + 2 * 128 * 36;
    float2* red = (float2*)(sB + 2 * 32 * LDB);

    const int tid = threadIdx.x;
    const int wid = tid >> 5, lane = tid & 31;
    const int g = lane >> 2, t = lane & 3;
    const int wm = wid & 3, wn = wid >> 2;
    const int R0 = blockIdx.x * 128;
    const int ar0 = (tid) >> 3,        af0 = ((tid) & 7) * 4;
    const int ar1 = (tid + 512) >> 3,  af1 = ((tid + 512) & 7) * 4;

    float c[2][8][4];
#pragma unroll
    for (int mt = 0; mt < 2; mt++)
#pragma unroll
        for (int nt = 0; nt < 8; nt++)
#pragma unroll
            for (int e = 0; e < 4; e++) c[mt][nt][e] = 0.f;

    float4 a0, a1;
    a0 = *(const float4*)&state[(size_t)(R0 + ar0) * HDIM + af0];
    a1 = *(const float4*)&state[(size_t)(R0 + ar1) * HDIM + af1];
    {
        float* d0 = &sA[ar0 * 36 + af0];
        d0[0]=to_tf32(a0.x); d0[1]=to_tf32(a0.y); d0[2]=to_tf32(a0.z); d0[3]=to_tf32(a0.w);
        float* d1 = &sA[ar1 * 36 + af1];
        d1[0]=to_tf32(a1.x); d1[1]=to_tf32(a1.y); d1[2]=to_tf32(a1.z); d1[3]=to_tf32(a1.w);
    }
#pragma unroll
    for (int p = 0; p < 4; p++) {
        int idx = tid + 512 * p;
        int kk = idx >> 6, n4 = (idx & 63) * 4;
        cpa16(&sB[kk * LDB + n4], &g_wenc[(size_t)kk * FCN + n4]);
    }
    cp_commit(); cp_wait0(); __syncthreads();

    const int T = HDIM / 32;
    for (int kt = 0; kt < T; kt++) {
        const int bt = kt & 1, bn = bt ^ 1;
        float* cA = sA + bt * 128 * 36;
        float* cB = sB + bt * 32 * LDB;
        if (kt + 1 < T) {
            float* nB = sB + bn * 32 * LDB;
#pragma unroll
            for (int p = 0; p < 4; p++) {
                int idx = tid + 512 * p;
                int kk = idx >> 6, n4 = (idx & 63) * 4;
                cpa16(&nB[kk * LDB + n4], &g_wenc[(size_t)((kt + 1) * 32 + kk) * FCN + n4]);
            }
            cp_commit();
            a0 = *(const float4*)&state[(size_t)(R0 + ar0) * HDIM + (kt + 1) * 32 + af0];
            a1 = *(const float4*)&state[(size_t)(R0 + ar1) * HDIM + (kt + 1) * 32 + af1];
        }
#pragma unroll
        for (int ks = 0; ks < 32; ks += 8) {
            unsigned a[2][4], b[8][2];
#pragma unroll
            for (int mt = 0; mt < 2; mt++) {
                int r = wm * 32 + mt * 16 + g;
                a[mt][0] = __float_as_uint(cA[r * 36 + ks + t]);
                a[mt][1] = __float_as_uint(cA[(r + 8) * 36 + ks + t]);
                a[mt][2] = __float_as_uint(cA[r * 36 + ks + t + 4]);
                a[mt][3] = __float_as_uint(cA[(r + 8) * 36 + ks + t + 4]);
            }
#pragma unroll
            for (int nt = 0; nt < 8; nt++) {
                int n = wn * 64 + nt * 8 + g;
                b[nt][0] = __float_as_uint(cB[(ks + t) * LDB + n]);
                b[nt][1] = __float_as_uint(cB[(ks + t + 4) * LDB + n]);
            }
#pragma unroll
            for (int mt = 0; mt < 2; mt++)
#pragma unroll
                for (int nt = 0; nt < 8; nt++) mma8(c[mt][nt], a[mt], b[nt]);
        }
        if (kt + 1 < T) {
            float* nA = sA + bn * 128 * 36;
            float* d0 = &nA[ar0 * 36 + af0];
            d0[0]=to_tf32(a0.x); d0[1]=to_tf32(a0.y); d0[2]=to_tf32(a0.z); d0[3]=to_tf32(a0.w);
            float* d1 = &nA[ar1 * 36 + af1];
            d1[0]=to_tf32(a1.x); d1[1]=to_tf32(a1.y); d1[2]=to_tf32(a1.z); d1[3]=to_tf32(a1.w);
        }
        cp_wait0(); __syncthreads();
    }

#pragma unroll
    for (int nt = 0; nt < 8; nt++) {
        int col = wn * 64 + nt * 8 + 2 * t;
        float b0 = __ldg(&bias[col]), b1 = __ldg(&bias[col + 1]);
#pragma unroll
        for (int mt = 0; mt < 2; mt++) {
            c[mt][nt][0] += b0; c[mt][nt][1] += b1;
            c[mt][nt][2] += b0; c[mt][nt][3] += b1;
        }
    }
#pragma unroll
    for (int mt = 0; mt < 2; mt++) {
        float s0 = 0, q0 = 0, s1v = 0, q1 = 0;
#pragma unroll
        for (int nt = 0; nt < 8; nt++) {
            s0 += c[mt][nt][0] + c[mt][nt][1];
            q0 += c[mt][nt][0] * c[mt][nt][0] + c[mt][nt][1] * c[mt][nt][1];
            s1v += c[mt][nt][2] + c[mt][nt][3];
            q1 += c[mt][nt][2] * c[mt][nt][2] + c[mt][nt][3] * c[mt][nt][3];
        }
#pragma unroll
        for (int o = 1; o <= 2; o <<= 1) {
            s0 += __shfl_xor_sync(~0u, s0, o); q0 += __shfl_xor_sync(~0u, q0, o);
            s1v += __shfl_xor_sync(~0u, s1v, o); q1 += __shfl_xor_sync(~0u, q1, o);
        }
        if (t == 0) {
            red[wn * 128 + wm * 32 + mt * 16 + g]     = make_float2(s0, q0);
            red[wn * 128 + wm * 32 + mt * 16 + g + 8] = make_float2(s1v, q1);
        }
    }
    __syncthreads();
#pragma unroll
    for (int mt = 0; mt < 2; mt++)
#pragma unroll
        for (int h = 0; h < 2; h++) {
            int row = wm * 32 + mt * 16 + g + 8 * h;
            float s = 0, q = 0;
#pragma unroll
            for (int w2 = 0; w2 < 4; w2++) {
                float2 r2 = red[w2 * 128 + row]; s += r2.x; q += r2.y;
            }
            float mu = s * (1.f / FCN);
            float rs = rsqrtf(q * (1.f / FCN) - mu * mu + 1e-5f);
#pragma unroll
            for (int nt = 0; nt < 8; nt++) {
                int col = wn * 64 + nt * 8 + 2 * t;
                float o0 = fmaxf((c[mt][nt][2 * h]     - mu) * rs * __ldg(&gam[col])     + __ldg(&bet[col]),     0.f);
                float o1 = fmaxf((c[mt][nt][2 * h + 1] - mu) * rs * __ldg(&gam[col + 1]) + __ldg(&bet[col + 1]), 0.f);
                *(float2*)&g_s1[(size_t)(R0 + row) * FCN + col] =
                    make_float2(to_tf32(o0), to_tf32(o1));
            }
        }
}

// ---------------------------------------------------------------------------
// Kernel 2: [U|V] = s1 @ packed(core_w)   (tf32, unchanged)
// ---------------------------------------------------------------------------
__global__ __launch_bounds__(512, 1) void k_uv()
{
    extern __shared__ float sm[];
    float* sA = sm;
    float* sB = sm + 2 * 64 * 36;

    const int tid = threadIdx.x;
    const int wid = tid >> 5, lane = tid & 31;
    const int g = lane >> 2, t = lane & 3;
    const int wm = wid & 1, wn = wid >> 1;
    const int R0 = blockIdx.x * 64;
    const int ar = tid >> 3, af = (tid & 7) * 4;

    float c[2][8][4];
#pragma unroll
    for (int mt = 0; mt < 2; mt++)
#pragma unroll
        for (int nt = 0; nt < 8; nt++)
#pragma unroll
            for (int e = 0; e < 4; e++) c[mt][nt][e] = 0.f;

    float4 a0;
    a0 = *(const float4*)&g_s1[(size_t)(R0 + ar) * FCN + af];
    *(float4*)&sA[ar * 36 + af] = a0;
#pragma unroll
    for (int p = 0; p < 8; p++) {
        int idx = tid + 512 * p;
        int kk = idx >> 7, n4 = (idx & 127) * 4;
        cpa16(&sB[kk * LDB2 + n4], &g_wuv[(size_t)kk * 512 + n4]);
    }
    cp_commit(); cp_wait0(); __syncthreads();

    const int T = FCN / 32;
    for (int kt = 0; kt < T; kt++) {
        const int bt = kt & 1, bn = bt ^ 1;
        float* cA = sA + bt * 64 * 36;
        float* cB = sB + bt * 32 * LDB2;
        if (kt + 1 < T) {
            float* nB = sB + bn * 32 * LDB2;
#pragma unroll
            for (int p = 0; p < 8; p++) {
                int idx = tid + 512 * p;
                int kk = idx >> 7, n4 = (idx & 127) * 4;
                cpa16(&nB[kk * LDB2 + n4], &g_wuv[(size_t)((kt + 1) * 32 + kk) * 512 + n4]);
            }
            cp_commit();
            a0 = *(const float4*)&g_s1[(size_t)(R0 + ar) * FCN + (kt + 1) * 32 + af];
        }
#pragma unroll
        for (int ks = 0; ks < 32; ks += 8) {
            unsigned a[2][4], b[8][2];
#pragma unroll
            for (int mt = 0; mt < 2; mt++) {
                int r = wm * 32 + mt * 16 + g;
                a[mt][0] = __float_as_uint(cA[r * 36 + ks + t]);
                a[mt][1] = __float_as_uint(cA[(r + 8) * 36 + ks + t]);
                a[mt][2] = __float_as_uint(cA[r * 36 + ks + t + 4]);
                a[mt][3] = __float_as_uint(cA[(r + 8) * 36 + ks + t + 4]);
            }
#pragma unroll
            for (int nt = 0; nt < 8; nt++) {
                int n = wn * 64 + nt * 8 + g;
                b[nt][0] = __float_as_uint(cB[(ks + t) * LDB2 + n]);
                b[nt][1] = __float_as_uint(cB[(ks + t + 4) * LDB2 + n]);
            }
#pragma unroll
            for (int mt = 0; mt < 2; mt++)
#pragma unroll
                for (int nt = 0; nt < 8; nt++) mma8(c[mt][nt], a[mt], b[nt]);
        }
        if (kt + 1 < T)
            *(float4*)&sA[bn * 64 * 36 + ar * 36 + af] = a0;
        cp_wait0(); __syncthreads();
    }

#pragma unroll
    for (int mt = 0; mt < 2; mt++)
#pragma unroll
        for (int h = 0; h < 2; h++) {
            int row = R0 + wm * 32 + mt * 16 + g + 8 * h;
#pragma unroll
            for (int nt = 0; nt < 8; nt++) {
                int col = wn * 64 + nt * 8 + 2 * t;
                *(float2*)&g_uv[(size_t)row * 512 + col] =
                    make_float2(c[mt][nt][2 * h], c[mt][nt][2 * h + 1]);
            }
        }
}

// ---------------------------------------------------------------------------
// Kernel 3 (fp16): 256 threads, 8 warps (2 row x 4 col), 56-real-row tile
// (64 padded). 2 CTAs/SM so epilogues overlap with the other CTA's mainloop.
// Packed A: [mt16(4)][kt16(16)] blocks of 528B; slot = lane*16B = a0..a3.
// B via direct LDG.128 (uint4 = 2 n8 fragments). No barriers in mainloops.
// ---------------------------------------------------------------------------
__global__ __launch_bounds__(256, 2) void k_eff(
    const float* __restrict__ core_b, const float* __restrict__ core_g,
    const float* __restrict__ core_bb,
    const float* __restrict__ ctx_b,
    const float* __restrict__ ctx_g, const float* __restrict__ ctx_bb,
    const float* __restrict__ a1_b,
    const float* __restrict__ att_g, const float* __restrict__ att_bb,
    const float* __restrict__ a2W,  const float* __restrict__ a2_b)
{
    extern __shared__ float sm[];
    char*   sAp  = (char*)sm;                   // 4*16*528 = 33792 B
    float*  sEff = sm + 33792 / 4;              // [8][257]
    float2* sRed = (float2*)(sEff + 8 * 257);   // [4][64]
    float*  sDot = (float*)(sRed + 4 * 64);     // [4][64]
    float*  sAtt = sDot + 4 * 64;               // [64]

    const int tid = threadIdx.x;
    const int wid = tid >> 5, lane = tid & 31;
    const int g = lane >> 2, t = lane & 3;
    const int wm = wid & 1, wn = wid >> 1;      // 2 row-warps x 4 col-warps
    const int R0 = blockIdx.x * 56;
    const int NKT = FCN / 16;   // 16 k16-tiles

    for (int idx = tid; idx < 8 * 257; idx += 256) sEff[idx] = 0.f;
    {   // zero pad slab mt=3 (rows 48..63; rows 48-55 get overwritten in phase a)
        float* z = (float*)(sAp + 3 * 16 * 528);
        for (int i = tid; i < 16 * 528 / 4; i += 256) z[i] = 0.f;
    }
    __syncthreads();

    // ---- phase a: core rows -> packed fp16 sA (rows 0..55) ----
    {
#pragma unroll
        for (int rr = 0; rr < 7; rr++) {
            int lrow = wid * 7 + rr;
            int v = R0 + lrow;
            int p = v / 7;
            int jj = v - p * 7;
            int i = p & 7;
            int j = jj + (jj >= i ? 1 : 0);
            int q = (p & ~7) + j;
            float2 val[4];
            float s = 0.f, s2 = 0.f;
#pragma unroll
            for (int e = 0; e < 4; e++) {
                int col = 2 * lane + 64 * e;
                float2 u  = *(const float2*)&g_uv[(size_t)p * 512 + col];
                float2 vq = *(const float2*)&g_uv[(size_t)q * 512 + 256 + col];
                float2 cb = *(const float2*)&core_b[col];
                val[e].x = u.x + vq.x + cb.x;
                val[e].y = u.y + vq.y + cb.y;
                s += val[e].x + val[e].y;
                s2 += val[e].x * val[e].x + val[e].y * val[e].y;
            }
#pragma unroll
            for (int o = 16; o; o >>= 1) {
                s  += __shfl_xor_sync(~0u, s,  o);
                s2 += __shfl_xor_sync(~0u, s2, o);
            }
            float mu = s * (1.f / FCN);
            float rs = rsqrtf(s2 * (1.f / FCN) - mu * mu + 1e-5f);
            int mtile = lrow >> 4, gg = lrow & 7, hm = (lrow >> 3) & 1;
            int tt = lane & 3, hk = (lane >> 2) & 1;
#pragma unroll
            for (int e = 0; e < 4; e++) {
                int col = 2 * lane + 64 * e;
                float2 cg = *(const float2*)&core_g[col];
                float2 cbb = *(const float2*)&core_bb[col];
                float o0 = fmaxf((val[e].x - mu) * rs * cg.x + cbb.x, 0.f);
                float o1 = fmaxf((val[e].y - mu) * rs * cg.y + cbb.y, 0.f);
                int kt = (lane >> 3) + 4 * e;
                unsigned off = (unsigned)((mtile * 16 + kt) * 528
                                          + ((gg << 2) + tt) * 16 + (hk * 2 + hm) * 4);
                *(unsigned*)(sAp + off) = packh(o0, o1);
            }
        }
    }
    __syncthreads();

    // ---- pass 1: attention (N=128, warp owns 32 cols = 2 uint4 loads) ----
    {
        float ca[2][4][4];
#pragma unroll
        for (int mt = 0; mt < 2; mt++)
#pragma unroll
            for (int nt = 0; nt < 4; nt++)
#pragma unroll
                for (int e = 0; e < 4; e++) ca[mt][nt][e] = 0.f;

#pragma unroll
        for (int kt = 0; kt < NKT; kt++) {
            unsigned a[2][4];
#pragma unroll
            for (int mt = 0; mt < 2; mt++) {
                uint4 av = *(uint4*)(sAp + ((wm * 2 + mt) * 16 + kt) * 528 + lane * 16);
                a[mt][0] = av.x; a[mt][1] = av.y; a[mt][2] = av.z; a[mt][3] = av.w;
            }
#pragma unroll
            for (int nt2 = 0; nt2 < 2; nt2++) {
                uint4 bv = __ldg(&g_wattp4[(size_t)(kt * 8 + wn * 2 + nt2) * 32 + lane]);
                unsigned bl[2] = {bv.x, bv.y}, bh[2] = {bv.z, bv.w};
                mma16(ca[0][2*nt2],   a[0], bl);
                mma16(ca[1][2*nt2],   a[1], bl);
                mma16(ca[0][2*nt2+1], a[0], bh);
                mma16(ca[1][2*nt2+1], a[1], bh);
            }
        }
        // epilogue: bias + LN(128) stats
#pragma unroll
        for (int nt = 0; nt < 4; nt++) {
            int col = wn * 32 + nt * 8 + 2 * t;
            float b0 = __ldg(&a1_b[col]), b1 = __ldg(&a1_b[col + 1]);
#pragma unroll
            for (int mt = 0; mt < 2; mt++) {
                ca[mt][nt][0] += b0; ca[mt][nt][1] += b1;
                ca[mt][nt][2] += b0; ca[mt][nt][3] += b1;
            }
        }
#pragma unroll
        for (int mt = 0; mt < 2; mt++) {
            float s0 = 0, q0 = 0, s1v = 0, q1 = 0;
#pragma unroll
            for (int nt = 0; nt < 4; nt++) {
                s0 += ca[mt][nt][0] + ca[mt][nt][1];
                q0 += ca[mt][nt][0] * ca[mt][nt][0] + ca[mt][nt][1] * ca[mt][nt][1];
                s1v += ca[mt][nt][2] + ca[mt][nt][3];
                q1 += ca[mt][nt][2] * ca[mt][nt][2] + ca[mt][nt][3] * ca[mt][nt][3];
            }
#pragma unroll
            for (int o = 1; o <= 2; o <<= 1) {
                s0 += __shfl_xor_sync(~0u, s0, o); q0 += __shfl_xor_sync(~0u, q0, o);
                s1v += __shfl_xor_sync(~0u, s1v, o); q1 += __shfl_xor_sync(~0u, q1, o);
            }
            if (t == 0) {
                sRed[wn * 64 + wm * 32 + mt * 16 + g]     = make_float2(s0, q0);
                sRed[wn * 64 + wm * 32 + mt * 16 + g + 8] = make_float2(s1v, q1);
            }
        }
        __syncthreads();
#pragma unroll
        for (int mt = 0; mt < 2; mt++)
#pragma unroll
            for (int h = 0; h < 2; h++) {
                int row = wm * 32 + mt * 16 + g + 8 * h;
                float s = 0, q = 0;
#pragma unroll
                for (int w2 = 0; w2 < 4; w2++) {
                    float2 r2 = sRed[w2 * 64 + row]; s += r2.x; q += r2.y;
                }
                float mu = s * (1.f / LASTN);
                float rs = rsqrtf(q * (1.f / LASTN) - mu * mu + 1e-5f);
                float d = 0.f;
#pragma unroll
                for (int nt = 0; nt < 4; nt++) {
                    int col = wn * 32 + nt * 8 + 2 * t;
                    float gg0 = __ldg(&att_g[col]),   bb0 = __ldg(&att_bb[col]),   w0 = __ldg(&a2W[col]);
                    float gg1 = __ldg(&att_g[col+1]), bb1 = __ldg(&att_bb[col+1]), w1 = __ldg(&a2W[col+1]);
                    d += tanhf((ca[mt][nt][2*h]   - mu) * rs * gg0 + bb0) * w0;
                    d += tanhf((ca[mt][nt][2*h+1] - mu) * rs * gg1 + bb1) * w1;
                }
#pragma unroll
                for (int o = 1; o <= 2; o <<= 1) d += __shfl_xor_sync(~0u, d, o);
                if (t == 0) sDot[wn * 64 + row] = d;
            }
        __syncthreads();
        if (wid < 2) {
            int row = wid * 32 + lane;
            float a2b = __ldg(&a2_b[0]);
            float d = sDot[row] + sDot[64 + row] + sDot[128 + row] + sDot[192 + row];
            sAtt[row] = 1.f / (1.f + expf(-(d + a2b)));
        }
        __syncthreads();
    }

    // ---- pass 2: ctx (N=256, warp owns 64 cols = 4 uint4 loads) + effect ----
    {
        float cc[2][8][4];
#pragma unroll
        for (int mt = 0; mt < 2; mt++)
#pragma unroll
            for (int nt = 0; nt < 8; nt++)
#pragma unroll
                for (int e = 0; e < 4; e++) cc[mt][nt][e] = 0.f;

#pragma unroll 4
        for (int kt = 0; kt < NKT; kt++) {
            unsigned a[2][4];
#pragma unroll
            for (int mt = 0; mt < 2; mt++) {
                uint4 av = *(uint4*)(sAp + ((wm * 2 + mt) * 16 + kt) * 528 + lane * 16);
                a[mt][0] = av.x; a[mt][1] = av.y; a[mt][2] = av.z; a[mt][3] = av.w;
            }
#pragma unroll
            for (int nt2 = 0; nt2 < 4; nt2++) {
                uint4 bv = __ldg(&g_wctxp4[(size_t)(kt * 16 + wn * 4 + nt2) * 32 + lane]);
                unsigned bl[2] = {bv.x, bv.y}, bh[2] = {bv.z, bv.w};
                mma16(cc[0][2*nt2],   a[0], bl);
                mma16(cc[1][2*nt2],   a[1], bl);
                mma16(cc[0][2*nt2+1], a[0], bh);
                mma16(cc[1][2*nt2+1], a[1], bh);
            }
        }
        // epilogue: bias + LN stats
#pragma unroll
        for (int nt = 0; nt < 8; nt++) {
            int col = wn * 64 + nt * 8 + 2 * t;
            float b0 = __ldg(&ctx_b[col]), b1 = __ldg(&ctx_b[col + 1]);
#pragma unroll
            for (int mt = 0; mt < 2; mt++) {
                cc[mt][nt][0] += b0; cc[mt][nt][1] += b1;
                cc[mt][nt][2] += b0; cc[mt][nt][3] += b1;
            }
        }
#pragma unroll
        for (int mt = 0; mt < 2; mt++) {
            float s0 = 0, q0 = 0, s1v = 0, q1 = 0;
#pragma unroll
            for (int nt = 0; nt < 8; nt++) {
                s0 += cc[mt][nt][0] + cc[mt][nt][1];
                q0 += cc[mt][nt][0] * cc[mt][nt][0] + cc[mt][nt][1] * cc[mt][nt][1];
                s1v += cc[mt][nt][2] + cc[mt][nt][3];
                q1 += cc[mt][nt][2] * cc[mt][nt][2] + cc[mt][nt][3] * cc[mt][nt][3];
            }
#pragma unroll
            for (int o = 1; o <= 2; o <<= 1) {
                s0 += __shfl_xor_sync(~0u, s0, o); q0 += __shfl_xor_sync(~0u, q0, o);
                s1v += __shfl_xor_sync(~0u, s1v, o); q1 += __shfl_xor_sync(~0u, q1, o);
            }
            if (t == 0) {
                sRed[wn * 64 + wm * 32 + mt * 16 + g]     = make_float2(s0, q0);
                sRed[wn * 64 + wm * 32 + mt * 16 + g + 8] = make_float2(s1v, q1);
            }
        }
        __syncthreads();
#pragma unroll
        for (int mt = 0; mt < 2; mt++)
#pragma unroll
            for (int h = 0; h < 2; h++) {
                int row = wm * 32 + mt * 16 + g + 8 * h;
                if (row >= 56) continue;
                float s = 0, q = 0;
#pragma unroll
                for (int w2 = 0; w2 < 4; w2++) {
                    float2 r2 = sRed[w2 * 64 + row]; s += r2.x; q += r2.y;
                }
                float mu = s * (1.f / FCN);
                float rs = rsqrtf(q * (1.f / FCN) - mu * mu + 1e-5f);
                float at = sAtt[row];
                int gl = row / 7;
#pragma unroll
                for (int nt = 0; nt < 8; nt++) {
                    int col = wn * 64 + nt * 8 + 2 * t;
                    float gg0 = __ldg(&ctx_g[col]),   bb0 = __ldg(&ctx_bb[col]);
                    float gg1 = __ldg(&ctx_g[col+1]), bb1 = __ldg(&ctx_bb[col+1]);
                    float v0 = fmaxf((cc[mt][nt][2*h]   - mu) * rs * gg0 + bb0, 0.f) * at;
                    float v1 = fmaxf((cc[mt][nt][2*h+1] - mu) * rs * gg1 + bb1, 0.f) * at;
                    atomicAdd(&sEff[gl * 257 + col],     v0);
                    atomicAdd(&sEff[gl * 257 + col + 1], v1);
                }
            }
    }
    __syncthreads();
    for (int idx = tid; idx < 8 * FCN; idx += 256) {
        int gg = idx >> 8, col = idx & 255;
        g_eff[(size_t)(blockIdx.x * 8 + gg) * FCN + col] = to_tf32(sEff[gg * 257 + col]);
    }
}

// ---------------------------------------------------------------------------
// Kernel 4: new_state = concat(s1, effect, x) @ out_w + out_b  (tf32)
// ---------------------------------------------------------------------------
__global__ __launch_bounds__(512, 1) void k_out(
    const float* __restrict__ xin, const float* __restrict__ bias,
    float* __restrict__ out, int dup)
{
    extern __shared__ float sm[];
    float* sA = sm;
    float* sB = sm + 2 * 128 * 36;

    const int tid = threadIdx.x;
    const int wid = tid >> 5, lane = tid & 31;
    const int g = lane >> 2, t = lane & 3;
    const int wm = wid & 3, wn = wid >> 2;
    const int R0 = blockIdx.x * 128;
    const int ar0 = (tid) >> 3,        af0 = ((tid) & 7) * 4;
    const int ar1 = (tid + 512) >> 3,  af1 = ((tid + 512) & 7) * 4;

    float c[2][8][4];
#pragma unroll
    for (int mt = 0; mt < 2; mt++)
#pragma unroll
        for (int nt = 0; nt < 8; nt++)
#pragma unroll
            for (int e = 0; e < 4; e++) c[mt][nt][e] = 0.f;

    auto ldA = [&](int kt, float4& v0, float4& v1, bool& cvt) {
        int base = kt * 32;
        if (base < FCN) {
            v0 = *(const float4*)&g_s1[(size_t)(R0 + ar0) * FCN + base + af0];
            v1 = *(const float4*)&g_s1[(size_t)(R0 + ar1) * FCN + base + af1];
            cvt = false;
        } else if (base < 2 * FCN) {
            v0 = *(const float4*)&g_eff[(size_t)(R0 + ar0) * FCN + base - FCN + af0];
            v1 = *(const float4*)&g_eff[(size_t)(R0 + ar1) * FCN + base - FCN + af1];
            cvt = false;
        } else {
            v0 = *(const float4*)&xin[(size_t)(R0 + ar0) * MDIM + base - 2 * FCN + af0];
            v1 = *(const float4*)&xin[(size_t)(R0 + ar1) * MDIM + base - 2 * FCN + af1];
            cvt = true;
        }
    };
    auto stA = [&](float* buf, float4 v0, float4 v1, bool cvt) {
        float* d0 = &buf[ar0 * 36 + af0];
        float* d1 = &buf[ar1 * 36 + af1];
        if (cvt) {
            d0[0]=to_tf32(v0.x); d0[1]=to_tf32(v0.y); d0[2]=to_tf32(v0.z); d0[3]=to_tf32(v0.w);
            d1[0]=to_tf32(v1.x); d1[1]=to_tf32(v1.y); d1[2]=to_tf32(v1.z); d1[3]=to_tf32(v1.w);
        } else {
            *(float4*)d0 = v0; *(float4*)d1 = v1;
        }
    };

    float4 a0, a1; bool cvt;
    ldA(0, a0, a1, cvt);
    stA(sA, a0, a1, cvt);
#pragma unroll
    for (int p = 0; p < 4; p++) {
        int idx = tid + 512 * p;
        int kk = idx >> 6, n4 = (idx & 63) * 4;
        cpa16(&sB[kk * LDB + n4], &g_wout[(size_t)kk * FCN + n4]);
    }
    cp_commit(); cp_wait0(); __syncthreads();

    const int T = KOUT / 32;
    for (int kt = 0; kt < T; kt++) {
        const int bt = kt & 1, bn = bt ^ 1;
        float* cA = sA + bt * 128 * 36;
        float* cB = sB + bt * 32 * LDB;
        if (kt + 1 < T) {
            float* nB = sB + bn * 32 * LDB;
#pragma unroll
            for (int p = 0; p < 4; p++) {
                int idx = tid + 512 * p;
                int kk = idx >> 6, n4 = (idx & 63) * 4;
                cpa16(&nB[kk * LDB + n4], &g_wout[(size_t)((kt + 1) * 32 + kk) * FCN + n4]);
            }
            cp_commit();
            ldA(kt + 1, a0, a1, cvt);
        }
#pragma unroll
        for (int ks = 0; ks < 32; ks += 8) {
            unsigned a[2][4], b[8][2];
#pragma unroll
            for (int mt = 0; mt < 2; mt++) {
                int r = wm * 32 + mt * 16 + g;
                a[mt][0] = __float_as_uint(cA[r * 36 + ks + t]);
                a[mt][1] = __float_as_uint(cA[(r + 8) * 36 + ks + t]);
                a[mt][2] = __float_as_uint(cA[r * 36 + ks + t + 4]);
                a[mt][3] = __float_as_uint(cA[(r + 8) * 36 + ks + t + 4]);
            }
#pragma unroll
            for (int nt = 0; nt < 8; nt++) {
                int n = wn * 64 + nt * 8 + g;
                b[nt][0] = __float_as_uint(cB[(ks + t) * LDB + n]);
                b[nt][1] = __float_as_uint(cB[(ks + t + 4) * LDB + n]);
            }
#pragma unroll
            for (int mt = 0; mt < 2; mt++)
#pragma unroll
                for (int nt = 0; nt < 8; nt++) mma8(c[mt][nt], a[mt], b[nt]);
        }
        if (kt + 1 < T)
            stA(sA + bn * 128 * 36, a0, a1, cvt);
        cp_wait0(); __syncthreads();
    }

#pragma unroll
    for (int mt = 0; mt < 2; mt++)
#pragma unroll
        for (int h = 0; h < 2; h++) {
            int row = R0 + wm * 32 + mt * 16 + g + 8 * h;
#pragma unroll
            for (int nt = 0; nt < 8; nt++) {
                int col = wn * 64 + nt * 8 + 2 * t;
                float o0 = c[mt][nt][2 * h]     + __ldg(&bias[col]);
                float o1 = c[mt][nt][2 * h + 1] + __ldg(&bias[col + 1]);
                size_t off = (size_t)row * FCN + col;
                *(float2*)&out[off] = make_float2(o0, o1);
                if (dup) *(float2*)&out[(size_t)NR1 * FCN + off] = make_float2(o0, o1);
            }
        }
}

// ---------------------------------------------------------------------------
extern "C" void kernel_launch(void* const* d_in, const int* in_sizes, int n_in,
                              void* d_out, int out_size) {
    const float* x      = (const float*)d_in[0];
    const float* state  = (const float*)d_in[1];
    const float* enc_w  = (const float*)d_in[2];
    const float* enc_b  = (const float*)d_in[3];
    const float* enc_g  = (const float*)d_in[4];
    const float* enc_bb = (const float*)d_in[5];
    const float* core_w = (const float*)d_in[6];
    const float* core_b = (const float*)d_in[7];
    const float* core_g = (const float*)d_in[8];
    const float* core_bb= (const float*)d_in[9];
    const float* ctx_w  = (const float*)d_in[10];
    const float* ctx_b  = (const float*)d_in[11];
    const float* ctx_g  = (const float*)d_in[12];
    const float* ctx_bb = (const float*)d_in[13];
    const float* att1_w = (const float*)d_in[14];
    const float* att1_b = (const float*)d_in[15];
    const float* att_g  = (const float*)d_in[16];
    const float* att_bb = (const float*)d_in[17];
    const float* att2_w = (const float*)d_in[18];
    const float* att2_b = (const float*)d_in[19];
    const float* out_w  = (const float*)d_in[20];
    const float* out_b  = (const float*)d_in[21];
    float* out = (float*)d_out;
    int dup = (out_size >= 2 * NR1 * FCN) ? 1 : 0;

    const int smem_enc = (2 * 128 * 36 + 2 * 32 * LDB) * 4 + 4 * 128 * 8;
    const int smem_uv  = (2 * 64 * 36 + 2 * 32 * LDB2) * 4;
    const int smem_eff = 33792 + 8 * 257 * 4 + 4 * 64 * 8 + 4 * 64 * 4 + 64 * 4;
    const int smem_out = (2 * 128 * 36 + 2 * 32 * LDB) * 4;

    static int attr_done = 0;
    if (!attr_done) {
        cudaFuncSetAttribute(k_enc, cudaFuncAttributeMaxDynamicSharedMemorySize, smem_enc);
        cudaFuncSetAttribute(k_uv,  cudaFuncAttributeMaxDynamicSharedMemorySize, smem_uv);
        cudaFuncSetAttribute(k_eff, cudaFuncAttributeMaxDynamicSharedMemorySize, smem_eff);
        cudaFuncSetAttribute(k_out, cudaFuncAttributeMaxDynamicSharedMemorySize, smem_out);
        attr_done = 1;
    }

    k_cvtw<<<256, 256>>>(enc_w, core_w, ctx_w, att1_w, out_w);
    k_enc<<<NR1 / 128, 512, smem_enc>>>(state, enc_b, enc_g, enc_bb);
    k_uv <<<NR1 / 64,  512, smem_uv >>>();
    k_eff<<<NR2 / 56,  256, smem_eff>>>(core_b, core_g, core_bb,
                                        ctx_b, ctx_g, ctx_bb,
                                        att1_b, att_g, att_bb,
                                        att2_w, att2_b);
    k_out<<<NR1 / 128, 512, smem_out>>>(x, out_b, out, dup);
}

// round 10
// speedup vs baseline: 7.8773x; 1.4516x over previous
#include <cuda_runtime.h>
#include <cuda_fp16.h>
#include <cstdint>
#include <math.h>

// ---------------------------------------------------------------------------
// R-NEM cell. tf32 pipeline for enc/uv/out; fp16 m16n8k16 for k_eff.
// R10: k_eff -> 3 CTAs/SM (pass2 split into two N=128 halves, 32 live accs),
//      no shared atomics (fp16 ctx buffer + exact LN-from-buffer + gather),
//      tanh.approx / ex2 sigmoid.
// core_pre[v] = U[p] + V[q] + core_b, [U|V] = s1 @ core_w (packed k-major)
// ---------------------------------------------------------------------------

#define FCN   256
#define LASTN 128
#define HDIM  512
#define MDIM  1024
#define NR1   16384
#define NR2   114688
#define KOUT  (2 * FCN + MDIM)

__device__ float g_s1[NR1 * FCN];        // tf32-rounded
__device__ float g_uv[NR1 * 2 * FCN];    // fp32
__device__ float g_eff[NR1 * FCN];       // tf32-rounded

// tf32 weights
__device__ float g_wenc[HDIM * FCN];
__device__ float g_wuv[FCN * 2 * FCN];   // packed: [k][512] = [Wtop | Wbot]
__device__ float g_wout[KOUT * FCN];

// fp16 fragment-packed weights (uint4 = two adjacent n8 fragments):
//   slot = (kt16 * (N/16) + n16) * 32 + lane ; {b0_lo,b1_lo,b0_hi,b1_hi}
__device__ __align__(16) uint4 g_wattp4[(FCN / 16) * (LASTN / 16) * 32]; // 64 KB
__device__ __align__(16) uint4 g_wctxp4[(FCN / 16) * (FCN / 16) * 32];   // 128 KB

// -------------------------------- helpers ---------------------------------
__device__ __forceinline__ float to_tf32(float x) {
    unsigned u; asm("cvt.rna.tf32.f32 %0, %1;" : "=r"(u) : "f"(x));
    return __uint_as_float(u);
}
__device__ __forceinline__ void mma8(float* c, const unsigned* a, const unsigned* b) {
    asm volatile(
        "mma.sync.aligned.m16n8k8.row.col.f32.tf32.tf32.f32 "
        "{%0,%1,%2,%3}, {%4,%5,%6,%7}, {%8,%9}, {%0,%1,%2,%3};"
        : "+f"(c[0]), "+f"(c[1]), "+f"(c[2]), "+f"(c[3])
        : "r"(a[0]), "r"(a[1]), "r"(a[2]), "r"(a[3]), "r"(b[0]), "r"(b[1]));
}
__device__ __forceinline__ void mma16(float* c, const unsigned* a, const unsigned* b) {
    asm volatile(
        "mma.sync.aligned.m16n8k16.row.col.f32.f16.f16.f32 "
        "{%0,%1,%2,%3}, {%4,%5,%6,%7}, {%8,%9}, {%0,%1,%2,%3};"
        : "+f"(c[0]), "+f"(c[1]), "+f"(c[2]), "+f"(c[3])
        : "r"(a[0]), "r"(a[1]), "r"(a[2]), "r"(a[3]), "r"(b[0]), "r"(b[1]));
}
__device__ __forceinline__ void cpa16(void* dst, const void* src) {
    unsigned d = (unsigned)__cvta_generic_to_shared(dst);
    asm volatile("cp.async.cg.shared.global [%0], [%1], 16;" :: "r"(d), "l"(src));
}
__device__ __forceinline__ void cp_commit() { asm volatile("cp.async.commit_group;"); }
__device__ __forceinline__ void cp_wait0()  { asm volatile("cp.async.wait_group 0;"); }
__device__ __forceinline__ unsigned packh(float a, float b) {
    __half2 h = __floats2half2_rn(a, b);
    return *(unsigned*)&h;
}
__device__ __forceinline__ float tanh_ax(float x) {
    float y; asm("tanh.approx.f32 %0, %1;" : "=f"(y) : "f"(x)); return y;
}
__device__ __forceinline__ float sigmoid_ax(float x) {
    float e; asm("ex2.approx.f32 %0, %1;" : "=f"(e) : "f"(-x * 1.4426950408889634f));
    return 1.f / (1.f + e);
}

#define LDB 264   // tf32 B tile stride
#define LDB2 520

// ---------------------------------------------------------------------------
// Kernel 0: convert/pack weights
// ---------------------------------------------------------------------------
__global__ void k_cvtw(const float* __restrict__ enc_w, const float* __restrict__ core_w,
                       const float* __restrict__ ctx_w, const float* __restrict__ att1_w,
                       const float* __restrict__ out_w)
{
    int i = blockIdx.x * blockDim.x + threadIdx.x;
    int n = gridDim.x * blockDim.x;
    for (int idx = i; idx < HDIM * FCN; idx += n) g_wenc[idx] = to_tf32(enc_w[idx]);
    for (int idx = i; idx < FCN * 2 * FCN; idx += n) {
        int k = idx >> 9, c = idx & 511;
        float v = (c < FCN) ? core_w[k * FCN + c] : core_w[(FCN + k) * FCN + (c - FCN)];
        g_wuv[idx] = to_tf32(v);
    }
    for (int idx = i; idx < KOUT * FCN; idx += n) g_wout[idx] = to_tf32(out_w[idx]);
    // att1_w (256x128): uint4 fragment pairs
    for (int idx = i; idx < (FCN/16) * (LASTN/16) * 32; idx += n) {
        int kt = idx >> 8;
        int n16 = (idx >> 5) & 7;
        int lane = idx & 31;
        int g = lane >> 2, t = lane & 3;
        int na = n16 * 16 + g, nb = na + 8, k0 = kt * 16;
        g_wattp4[idx] = make_uint4(
            packh(att1_w[(k0 + 2*t)     * LASTN + na], att1_w[(k0 + 2*t + 1) * LASTN + na]),
            packh(att1_w[(k0 + 8 + 2*t) * LASTN + na], att1_w[(k0 + 9 + 2*t) * LASTN + na]),
            packh(att1_w[(k0 + 2*t)     * LASTN + nb], att1_w[(k0 + 2*t + 1) * LASTN + nb]),
            packh(att1_w[(k0 + 8 + 2*t) * LASTN + nb], att1_w[(k0 + 9 + 2*t) * LASTN + nb]));
    }
    // ctx_w (256x256): uint4 fragment pairs
    for (int idx = i; idx < (FCN/16) * (FCN/16) * 32; idx += n) {
        int kt = idx >> 9;
        int n16 = (idx >> 5) & 15;
        int lane = idx & 31;
        int g = lane >> 2, t = lane & 3;
        int na = n16 * 16 + g, nb = na + 8, k0 = kt * 16;
        g_wctxp4[idx] = make_uint4(
            packh(ctx_w[(k0 + 2*t)     * FCN + na], ctx_w[(k0 + 2*t + 1) * FCN + na]),
            packh(ctx_w[(k0 + 8 + 2*t) * FCN + na], ctx_w[(k0 + 9 + 2*t) * FCN + na]),
            packh(ctx_w[(k0 + 2*t)     * FCN + nb], ctx_w[(k0 + 2*t + 1) * FCN + nb]),
            packh(ctx_w[(k0 + 8 + 2*t) * FCN + nb], ctx_w[(k0 + 9 + 2*t) * FCN + nb]));
    }
}

// ---------------------------------------------------------------------------
// Kernel 1: s1 = relu(LN(state @ enc_w + enc_b))    (tf32, unchanged)
// ---------------------------------------------------------------------------
__global__ __launch_bounds__(512, 1) void k_enc(
    const float* __restrict__ state, const float* __restrict__ bias,
    const float* __restrict__ gam, const float* __restrict__ bet)
{
    extern __shared__ float sm[];
    float*  sA  = sm;
    float*  sB  = sm + 2 * 128 * 36;
    float2* red = (float2*)(sB + 2 * 32 * LDB);

    const int tid = threadIdx.x;
    const int wid = tid >> 5, lane = tid & 31;
    const int g = lane >> 2, t = lane & 3;
    const int wm = wid & 3, wn = wid >> 2;
    const int R0 = blockIdx.x * 128;
    const int ar0 = (tid) >> 3,        af0 = ((tid) & 7) * 4;
    const int ar1 = (tid + 512) >> 3,  af1 = ((tid + 512) & 7) * 4;

    float c[2][8][4];
#pragma unroll
    for (int mt = 0; mt < 2; mt++)
#pragma unroll
        for (int nt = 0; nt < 8; nt++)
#pragma unroll
            for (int e = 0; e < 4; e++) c[mt][nt][e] = 0.f;

    float4 a0, a1;
    a0 = *(const float4*)&state[(size_t)(R0 + ar0) * HDIM + af0];
    a1 = *(const float4*)&state[(size_t)(R0 + ar1) * HDIM + af1];
    {
        float* d0 = &sA[ar0 * 36 + af0];
        d0[0]=to_tf32(a0.x); d0[1]=to_tf32(a0.y); d0[2]=to_tf32(a0.z); d0[3]=to_tf32(a0.w);
        float* d1 = &sA[ar1 * 36 + af1];
        d1[0]=to_tf32(a1.x); d1[1]=to_tf32(a1.y); d1[2]=to_tf32(a1.z); d1[3]=to_tf32(a1.w);
    }
#pragma unroll
    for (int p = 0; p < 4; p++) {
        int idx = tid + 512 * p;
        int kk = idx >> 6, n4 = (idx & 63) * 4;
        cpa16(&sB[kk * LDB + n4], &g_wenc[(size_t)kk * FCN + n4]);
    }
    cp_commit(); cp_wait0(); __syncthreads();

    const int T = HDIM / 32;
    for (int kt = 0; kt < T; kt++) {
        const int bt = kt & 1, bn = bt ^ 1;
        float* cA = sA + bt * 128 * 36;
        float* cB = sB + bt * 32 * LDB;
        if (kt + 1 < T) {
            float* nB = sB + bn * 32 * LDB;
#pragma unroll
            for (int p = 0; p < 4; p++) {
                int idx = tid + 512 * p;
                int kk = idx >> 6, n4 = (idx & 63) * 4;
                cpa16(&nB[kk * LDB + n4], &g_wenc[(size_t)((kt + 1) * 32 + kk) * FCN + n4]);
            }
            cp_commit();
            a0 = *(const float4*)&state[(size_t)(R0 + ar0) * HDIM + (kt + 1) * 32 + af0];
            a1 = *(const float4*)&state[(size_t)(R0 + ar1) * HDIM + (kt + 1) * 32 + af1];
        }
#pragma unroll
        for (int ks = 0; ks < 32; ks += 8) {
            unsigned a[2][4], b[8][2];
#pragma unroll
            for (int mt = 0; mt < 2; mt++) {
                int r = wm * 32 + mt * 16 + g;
                a[mt][0] = __float_as_uint(cA[r * 36 + ks + t]);
                a[mt][1] = __float_as_uint(cA[(r + 8) * 36 + ks + t]);
                a[mt][2] = __float_as_uint(cA[r * 36 + ks + t + 4]);
                a[mt][3] = __float_as_uint(cA[(r + 8) * 36 + ks + t + 4]);
            }
#pragma unroll
            for (int nt = 0; nt < 8; nt++) {
                int n = wn * 64 + nt * 8 + g;
                b[nt][0] = __float_as_uint(cB[(ks + t) * LDB + n]);
                b[nt][1] = __float_as_uint(cB[(ks + t + 4) * LDB + n]);
            }
#pragma unroll
            for (int mt = 0; mt < 2; mt++)
#pragma unroll
                for (int nt = 0; nt < 8; nt++) mma8(c[mt][nt], a[mt], b[nt]);
        }
        if (kt + 1 < T) {
            float* nA = sA + bn * 128 * 36;
            float* d0 = &nA[ar0 * 36 + af0];
            d0[0]=to_tf32(a0.x); d0[1]=to_tf32(a0.y); d0[2]=to_tf32(a0.z); d0[3]=to_tf32(a0.w);
            float* d1 = &nA[ar1 * 36 + af1];
            d1[0]=to_tf32(a1.x); d1[1]=to_tf32(a1.y); d1[2]=to_tf32(a1.z); d1[3]=to_tf32(a1.w);
        }
        cp_wait0(); __syncthreads();
    }

#pragma unroll
    for (int nt = 0; nt < 8; nt++) {
        int col = wn * 64 + nt * 8 + 2 * t;
        float b0 = __ldg(&bias[col]), b1 = __ldg(&bias[col + 1]);
#pragma unroll
        for (int mt = 0; mt < 2; mt++) {
            c[mt][nt][0] += b0; c[mt][nt][1] += b1;
            c[mt][nt][2] += b0; c[mt][nt][3] += b1;
        }
    }
#pragma unroll
    for (int mt = 0; mt < 2; mt++) {
        float s0 = 0, q0 = 0, s1v = 0, q1 = 0;
#pragma unroll
        for (int nt = 0; nt < 8; nt++) {
            s0 += c[mt][nt][0] + c[mt][nt][1];
            q0 += c[mt][nt][0] * c[mt][nt][0] + c[mt][nt][1] * c[mt][nt][1];
            s1v += c[mt][nt][2] + c[mt][nt][3];
            q1 += c[mt][nt][2] * c[mt][nt][2] + c[mt][nt][3] * c[mt][nt][3];
        }
#pragma unroll
        for (int o = 1; o <= 2; o <<= 1) {
            s0 += __shfl_xor_sync(~0u, s0, o); q0 += __shfl_xor_sync(~0u, q0, o);
            s1v += __shfl_xor_sync(~0u, s1v, o); q1 += __shfl_xor_sync(~0u, q1, o);
        }
        if (t == 0) {
            red[wn * 128 + wm * 32 + mt * 16 + g]     = make_float2(s0, q0);
            red[wn * 128 + wm * 32 + mt * 16 + g + 8] = make_float2(s1v, q1);
        }
    }
    __syncthreads();
#pragma unroll
    for (int mt = 0; mt < 2; mt++)
#pragma unroll
        for (int h = 0; h < 2; h++) {
            int row = wm * 32 + mt * 16 + g + 8 * h;
            float s = 0, q = 0;
#pragma unroll
            for (int w2 = 0; w2 < 4; w2++) {
                float2 r2 = red[w2 * 128 + row]; s += r2.x; q += r2.y;
            }
            float mu = s * (1.f / FCN);
            float rs = rsqrtf(q * (1.f / FCN) - mu * mu + 1e-5f);
#pragma unroll
            for (int nt = 0; nt < 8; nt++) {
                int col = wn * 64 + nt * 8 + 2 * t;
                float o0 = fmaxf((c[mt][nt][2 * h]     - mu) * rs * __ldg(&gam[col])     + __ldg(&bet[col]),     0.f);
                float o1 = fmaxf((c[mt][nt][2 * h + 1] - mu) * rs * __ldg(&gam[col + 1]) + __ldg(&bet[col + 1]), 0.f);
                *(float2*)&g_s1[(size_t)(R0 + row) * FCN + col] =
                    make_float2(to_tf32(o0), to_tf32(o1));
            }
        }
}

// ---------------------------------------------------------------------------
// Kernel 2: [U|V] = s1 @ packed(core_w)   (tf32, unchanged)
// ---------------------------------------------------------------------------
__global__ __launch_bounds__(512, 1) void k_uv()
{
    extern __shared__ float sm[];
    float* sA = sm;
    float* sB = sm + 2 * 64 * 36;

    const int tid = threadIdx.x;
    const int wid = tid >> 5, lane = tid & 31;
    const int g = lane >> 2, t = lane & 3;
    const int wm = wid & 1, wn = wid >> 1;
    const int R0 = blockIdx.x * 64;
    const int ar = tid >> 3, af = (tid & 7) * 4;

    float c[2][8][4];
#pragma unroll
    for (int mt = 0; mt < 2; mt++)
#pragma unroll
        for (int nt = 0; nt < 8; nt++)
#pragma unroll
            for (int e = 0; e < 4; e++) c[mt][nt][e] = 0.f;

    float4 a0;
    a0 = *(const float4*)&g_s1[(size_t)(R0 + ar) * FCN + af];
    *(float4*)&sA[ar * 36 + af] = a0;
#pragma unroll
    for (int p = 0; p < 8; p++) {
        int idx = tid + 512 * p;
        int kk = idx >> 7, n4 = (idx & 127) * 4;
        cpa16(&sB[kk * LDB2 + n4], &g_wuv[(size_t)kk * 512 + n4]);
    }
    cp_commit(); cp_wait0(); __syncthreads();

    const int T = FCN / 32;
    for (int kt = 0; kt < T; kt++) {
        const int bt = kt & 1, bn = bt ^ 1;
        float* cA = sA + bt * 64 * 36;
        float* cB = sB + bt * 32 * LDB2;
        if (kt + 1 < T) {
            float* nB = sB + bn * 32 * LDB2;
#pragma unroll
            for (int p = 0; p < 8; p++) {
                int idx = tid + 512 * p;
                int kk = idx >> 7, n4 = (idx & 127) * 4;
                cpa16(&nB[kk * LDB2 + n4], &g_wuv[(size_t)((kt + 1) * 32 + kk) * 512 + n4]);
            }
            cp_commit();
            a0 = *(const float4*)&g_s1[(size_t)(R0 + ar) * FCN + (kt + 1) * 32 + af];
        }
#pragma unroll
        for (int ks = 0; ks < 32; ks += 8) {
            unsigned a[2][4], b[8][2];
#pragma unroll
            for (int mt = 0; mt < 2; mt++) {
                int r = wm * 32 + mt * 16 + g;
                a[mt][0] = __float_as_uint(cA[r * 36 + ks + t]);
                a[mt][1] = __float_as_uint(cA[(r + 8) * 36 + ks + t]);
                a[mt][2] = __float_as_uint(cA[r * 36 + ks + t + 4]);
                a[mt][3] = __float_as_uint(cA[(r + 8) * 36 + ks + t + 4]);
            }
#pragma unroll
            for (int nt = 0; nt < 8; nt++) {
                int n = wn * 64 + nt * 8 + g;
                b[nt][0] = __float_as_uint(cB[(ks + t) * LDB2 + n]);
                b[nt][1] = __float_as_uint(cB[(ks + t + 4) * LDB2 + n]);
            }
#pragma unroll
            for (int mt = 0; mt < 2; mt++)
#pragma unroll
                for (int nt = 0; nt < 8; nt++) mma8(c[mt][nt], a[mt], b[nt]);
        }
        if (kt + 1 < T)
            *(float4*)&sA[bn * 64 * 36 + ar * 36 + af] = a0;
        cp_wait0(); __syncthreads();
    }

#pragma unroll
    for (int mt = 0; mt < 2; mt++)
#pragma unroll
        for (int h = 0; h < 2; h++) {
            int row = R0 + wm * 32 + mt * 16 + g + 8 * h;
#pragma unroll
            for (int nt = 0; nt < 8; nt++) {
                int col = wn * 64 + nt * 8 + 2 * t;
                *(float2*)&g_uv[(size_t)row * 512 + col] =
                    make_float2(c[mt][nt][2 * h], c[mt][nt][2 * h + 1]);
            }
        }
}

// ---------------------------------------------------------------------------
// Kernel 3 (fp16): 256 threads, 8 warps (2 row x 4 col), 56-real-row tile.
// 3 CTAs/SM. Pass 2 split into two N=128 halves (32 live accumulators).
// Effect path: fp16 raw-ctx buffer -> exact LN stats -> gather (no atomics).
// ---------------------------------------------------------------------------
__global__ __launch_bounds__(256, 3) void k_eff(
    const float* __restrict__ core_b, const float* __restrict__ core_g,
    const float* __restrict__ core_bb,
    const float* __restrict__ ctx_b,
    const float* __restrict__ ctx_g, const float* __restrict__ ctx_bb,
    const float* __restrict__ a1_b,
    const float* __restrict__ att_g, const float* __restrict__ att_bb,
    const float* __restrict__ a2W,  const float* __restrict__ a2_b)
{
    extern __shared__ float sm[];
    char*     sAp   = (char*)sm;                     // 4*16*528 = 33792 B
    unsigned* sCtx2 = (unsigned*)(sAp + 33792);      // [64][132] half2 = 33792 B
    float2*   sRed  = (float2*)(sCtx2 + 64 * 132);   // [4][64]
    float*    sDot  = (float*)(sRed + 4 * 64);       // [4][64]
    float*    sAtt  = sDot + 4 * 64;                 // [64]
    float2*   sMu   = (float2*)(sAtt + 64);          // [64]

    const int tid = threadIdx.x;
    const int wid = tid >> 5, lane = tid & 31;
    const int g = lane >> 2, t = lane & 3;
    const int wm = wid & 1, wn = wid >> 1;      // 2 row-warps x 4 col-warps
    const int R0 = blockIdx.x * 56;
    const int NKT = FCN / 16;   // 16 k16-tiles

    {   // zero pad slab mt=3 (rows 48..63; rows 48-55 overwritten in phase a)
        float* z = (float*)(sAp + 3 * 16 * 528);
        for (int i = tid; i < 16 * 528 / 4; i += 256) z[i] = 0.f;
    }
    __syncthreads();

    // ---- phase a: core rows -> packed fp16 sA (rows 0..55) ----
    {
#pragma unroll
        for (int rr = 0; rr < 7; rr++) {
            int lrow = wid * 7 + rr;
            int v = R0 + lrow;
            int p = v / 7;
            int jj = v - p * 7;
            int i = p & 7;
            int j = jj + (jj >= i ? 1 : 0);
            int q = (p & ~7) + j;
            float2 val[4];
            float s = 0.f, s2 = 0.f;
#pragma unroll
            for (int e = 0; e < 4; e++) {
                int col = 2 * lane + 64 * e;
                float2 u  = *(const float2*)&g_uv[(size_t)p * 512 + col];
                float2 vq = *(const float2*)&g_uv[(size_t)q * 512 + 256 + col];
                float2 cb = *(const float2*)&core_b[col];
                val[e].x = u.x + vq.x + cb.x;
                val[e].y = u.y + vq.y + cb.y;
                s += val[e].x + val[e].y;
                s2 += val[e].x * val[e].x + val[e].y * val[e].y;
            }
#pragma unroll
            for (int o = 16; o; o >>= 1) {
                s  += __shfl_xor_sync(~0u, s,  o);
                s2 += __shfl_xor_sync(~0u, s2, o);
            }
            float mu = s * (1.f / FCN);
            float rs = rsqrtf(s2 * (1.f / FCN) - mu * mu + 1e-5f);
            int mtile = lrow >> 4, gg = lrow & 7, hm = (lrow >> 3) & 1;
            int tt = lane & 3, hk = (lane >> 2) & 1;
#pragma unroll
            for (int e = 0; e < 4; e++) {
                int col = 2 * lane + 64 * e;
                float2 cg = *(const float2*)&core_g[col];
                float2 cbb = *(const float2*)&core_bb[col];
                float o0 = fmaxf((val[e].x - mu) * rs * cg.x + cbb.x, 0.f);
                float o1 = fmaxf((val[e].y - mu) * rs * cg.y + cbb.y, 0.f);
                int kt = (lane >> 3) + 4 * e;
                unsigned off = (unsigned)((mtile * 16 + kt) * 528
                                          + ((gg << 2) + tt) * 16 + (hk * 2 + hm) * 4);
                *(unsigned*)(sAp + off) = packh(o0, o1);
            }
        }
    }
    __syncthreads();

    // ---- pass 1: attention (N=128, warp owns 32 cols = 2 uint4 loads) ----
    {
        float ca[2][4][4];
#pragma unroll
        for (int mt = 0; mt < 2; mt++)
#pragma unroll
            for (int nt = 0; nt < 4; nt++)
#pragma unroll
                for (int e = 0; e < 4; e++) ca[mt][nt][e] = 0.f;

#pragma unroll
        for (int kt = 0; kt < NKT; kt++) {
            unsigned a[2][4];
#pragma unroll
            for (int mt = 0; mt < 2; mt++) {
                uint4 av = *(uint4*)(sAp + ((wm * 2 + mt) * 16 + kt) * 528 + lane * 16);
                a[mt][0] = av.x; a[mt][1] = av.y; a[mt][2] = av.z; a[mt][3] = av.w;
            }
#pragma unroll
            for (int nt2 = 0; nt2 < 2; nt2++) {
                uint4 bv = __ldg(&g_wattp4[(size_t)(kt * 8 + wn * 2 + nt2) * 32 + lane]);
                unsigned bl[2] = {bv.x, bv.y}, bh[2] = {bv.z, bv.w};
                mma16(ca[0][2*nt2],   a[0], bl);
                mma16(ca[1][2*nt2],   a[1], bl);
                mma16(ca[0][2*nt2+1], a[0], bh);
                mma16(ca[1][2*nt2+1], a[1], bh);
            }
        }
        // epilogue: bias + LN(128) stats
#pragma unroll
        for (int nt = 0; nt < 4; nt++) {
            int col = wn * 32 + nt * 8 + 2 * t;
            float b0 = __ldg(&a1_b[col]), b1 = __ldg(&a1_b[col + 1]);
#pragma unroll
            for (int mt = 0; mt < 2; mt++) {
                ca[mt][nt][0] += b0; ca[mt][nt][1] += b1;
                ca[mt][nt][2] += b0; ca[mt][nt][3] += b1;
            }
        }
#pragma unroll
        for (int mt = 0; mt < 2; mt++) {
            float s0 = 0, q0 = 0, s1v = 0, q1 = 0;
#pragma unroll
            for (int nt = 0; nt < 4; nt++) {
                s0 += ca[mt][nt][0] + ca[mt][nt][1];
                q0 += ca[mt][nt][0] * ca[mt][nt][0] + ca[mt][nt][1] * ca[mt][nt][1];
                s1v += ca[mt][nt][2] + ca[mt][nt][3];
                q1 += ca[mt][nt][2] * ca[mt][nt][2] + ca[mt][nt][3] * ca[mt][nt][3];
            }
#pragma unroll
            for (int o = 1; o <= 2; o <<= 1) {
                s0 += __shfl_xor_sync(~0u, s0, o); q0 += __shfl_xor_sync(~0u, q0, o);
                s1v += __shfl_xor_sync(~0u, s1v, o); q1 += __shfl_xor_sync(~0u, q1, o);
            }
            if (t == 0) {
                sRed[wn * 64 + wm * 32 + mt * 16 + g]     = make_float2(s0, q0);
                sRed[wn * 64 + wm * 32 + mt * 16 + g + 8] = make_float2(s1v, q1);
            }
        }
        __syncthreads();
#pragma unroll
        for (int mt = 0; mt < 2; mt++)
#pragma unroll
            for (int h = 0; h < 2; h++) {
                int row = wm * 32 + mt * 16 + g + 8 * h;
                float s = 0, q = 0;
#pragma unroll
                for (int w2 = 0; w2 < 4; w2++) {
                    float2 r2 = sRed[w2 * 64 + row]; s += r2.x; q += r2.y;
                }
                float mu = s * (1.f / LASTN);
                float rs = rsqrtf(q * (1.f / LASTN) - mu * mu + 1e-5f);
                float d = 0.f;
#pragma unroll
                for (int nt = 0; nt < 4; nt++) {
                    int col = wn * 32 + nt * 8 + 2 * t;
                    float gg0 = __ldg(&att_g[col]),   bb0 = __ldg(&att_bb[col]),   w0 = __ldg(&a2W[col]);
                    float gg1 = __ldg(&att_g[col+1]), bb1 = __ldg(&att_bb[col+1]), w1 = __ldg(&a2W[col+1]);
                    d += tanh_ax((ca[mt][nt][2*h]   - mu) * rs * gg0 + bb0) * w0;
                    d += tanh_ax((ca[mt][nt][2*h+1] - mu) * rs * gg1 + bb1) * w1;
                }
#pragma unroll
                for (int o = 1; o <= 2; o <<= 1) d += __shfl_xor_sync(~0u, d, o);
                if (t == 0) sDot[wn * 64 + row] = d;
            }
        __syncthreads();
        if (wid < 2) {
            int row = wid * 32 + lane;
            float a2b = __ldg(&a2_b[0]);
            float d = sDot[row] + sDot[64 + row] + sDot[128 + row] + sDot[192 + row];
            sAtt[row] = sigmoid_ax(d + a2b);
        }
        __syncthreads();
    }

    // ---- pass 2: ctx in two N=128 halves; raw (bias-added) -> fp16 buffer ----
    for (int half = 0; half < 2; half++) {
        float cc[2][4][4];
#pragma unroll
        for (int mt = 0; mt < 2; mt++)
#pragma unroll
            for (int nt = 0; nt < 4; nt++)
#pragma unroll
                for (int e = 0; e < 4; e++) cc[mt][nt][e] = 0.f;

#pragma unroll
        for (int kt = 0; kt < NKT; kt++) {
            unsigned a[2][4];
#pragma unroll
            for (int mt = 0; mt < 2; mt++) {
                uint4 av = *(uint4*)(sAp + ((wm * 2 + mt) * 16 + kt) * 528 + lane * 16);
                a[mt][0] = av.x; a[mt][1] = av.y; a[mt][2] = av.z; a[mt][3] = av.w;
            }
#pragma unroll
            for (int nt2 = 0; nt2 < 2; nt2++) {
                uint4 bv = __ldg(&g_wctxp4[(size_t)(kt * 16 + half * 8 + wn * 2 + nt2) * 32 + lane]);
                unsigned bl[2] = {bv.x, bv.y}, bh[2] = {bv.z, bv.w};
                mma16(cc[0][2*nt2],   a[0], bl);
                mma16(cc[1][2*nt2],   a[1], bl);
                mma16(cc[0][2*nt2+1], a[0], bh);
                mma16(cc[1][2*nt2+1], a[1], bh);
            }
        }
        // epilogue: add bias, pack fp16, store raw to sCtx2
#pragma unroll
        for (int mt = 0; mt < 2; mt++)
#pragma unroll
            for (int nt = 0; nt < 4; nt++) {
                int col = half * 128 + wn * 32 + nt * 8 + 2 * t;
                float b0 = __ldg(&ctx_b[col]), b1 = __ldg(&ctx_b[col + 1]);
                int r0 = wm * 32 + mt * 16 + g;
                int ci = col >> 1;
                sCtx2[r0 * 132 + ci]       = packh(cc[mt][nt][0] + b0, cc[mt][nt][1] + b1);
                sCtx2[(r0 + 8) * 132 + ci] = packh(cc[mt][nt][2] + b0, cc[mt][nt][3] + b1);
            }
    }
    __syncthreads();

    // ---- stats pass: exact LN params from the fp16 buffer ----
    {
        int r = tid >> 2, b = tid & 3;
        float s = 0.f, q = 0.f;
        if (r < 56) {
#pragma unroll
            for (int j = 0; j < 32; j++) {
                __half2 h = *(__half2*)&sCtx2[r * 132 + b + 4 * j];
                float2 f = __half22float2(h);
                s += f.x + f.y; q += f.x * f.x + f.y * f.y;
            }
        }
        s += __shfl_xor_sync(~0u, s, 1); q += __shfl_xor_sync(~0u, q, 1);
        s += __shfl_xor_sync(~0u, s, 2); q += __shfl_xor_sync(~0u, q, 2);
        if (b == 0 && r < 56) {
            float mu = s * (1.f / FCN);
            float rs = rsqrtf(q * (1.f / FCN) - mu * mu + 1e-5f);
            sMu[r] = make_float2(mu, rs);
        }
    }
    __syncthreads();

    // ---- effect gather: sum over 7 rows per group, no atomics ----
    for (int s0 = tid; s0 < 8 * 128; s0 += 256) {
        int gg = s0 >> 7, c2 = s0 & 127;
        float2 gm = __ldg((const float2*)&ctx_g[2 * c2]);
        float2 bb = __ldg((const float2*)&ctx_bb[2 * c2]);
        float e0 = 0.f, e1 = 0.f;
        int rb = gg * 7;
#pragma unroll
        for (int rr = 0; rr < 7; rr++) {
            int r = rb + rr;
            float2 mr = sMu[r];
            float at = sAtt[r];
            float2 f = __half22float2(*(__half2*)&sCtx2[r * 132 + c2]);
            e0 += fmaxf((f.x - mr.x) * mr.y * gm.x + bb.x, 0.f) * at;
            e1 += fmaxf((f.y - mr.x) * mr.y * gm.y + bb.y, 0.f) * at;
        }
        *(float2*)&g_eff[(size_t)(blockIdx.x * 8 + gg) * FCN + 2 * c2] =
            make_float2(to_tf32(e0), to_tf32(e1));
    }
}

// ---------------------------------------------------------------------------
// Kernel 4: new_state = concat(s1, effect, x) @ out_w + out_b  (tf32)
// ---------------------------------------------------------------------------
__global__ __launch_bounds__(512, 1) void k_out(
    const float* __restrict__ xin, const float* __restrict__ bias,
    float* __restrict__ out, int dup)
{
    extern __shared__ float sm[];
    float* sA = sm;
    float* sB = sm + 2 * 128 * 36;

    const int tid = threadIdx.x;
    const int wid = tid >> 5, lane = tid & 31;
    const int g = lane >> 2, t = lane & 3;
    const int wm = wid & 3, wn = wid >> 2;
    const int R0 = blockIdx.x * 128;
    const int ar0 = (tid) >> 3,        af0 = ((tid) & 7) * 4;
    const int ar1 = (tid + 512) >> 3,  af1 = ((tid + 512) & 7) * 4;

    float c[2][8][4];
#pragma unroll
    for (int mt = 0; mt < 2; mt++)
#pragma unroll
        for (int nt = 0; nt < 8; nt++)
#pragma unroll
            for (int e = 0; e < 4; e++) c[mt][nt][e] = 0.f;

    auto ldA = [&](int kt, float4& v0, float4& v1, bool& cvt) {
        int base = kt * 32;
        if (base < FCN) {
            v0 = *(const float4*)&g_s1[(size_t)(R0 + ar0) * FCN + base + af0];
            v1 = *(const float4*)&g_s1[(size_t)(R0 + ar1) * FCN + base + af1];
            cvt = false;
        } else if (base < 2 * FCN) {
            v0 = *(const float4*)&g_eff[(size_t)(R0 + ar0) * FCN + base - FCN + af0];
            v1 = *(const float4*)&g_eff[(size_t)(R0 + ar1) * FCN + base - FCN + af1];
            cvt = false;
        } else {
            v0 = *(const float4*)&xin[(size_t)(R0 + ar0) * MDIM + base - 2 * FCN + af0];
            v1 = *(const float4*)&xin[(size_t)(R0 + ar1) * MDIM + base - 2 * FCN + af1];
            cvt = true;
        }
    };
    auto stA = [&](float* buf, float4 v0, float4 v1, bool cvt) {
        float* d0 = &buf[ar0 * 36 + af0];
        float* d1 = &buf[ar1 * 36 + af1];
        if (cvt) {
            d0[0]=to_tf32(v0.x); d0[1]=to_tf32(v0.y); d0[2]=to_tf32(v0.z); d0[3]=to_tf32(v0.w);
            d1[0]=to_tf32(v1.x); d1[1]=to_tf32(v1.y); d1[2]=to_tf32(v1.z); d1[3]=to_tf32(v1.w);
        } else {
            *(float4*)d0 = v0; *(float4*)d1 = v1;
        }
    };

    float4 a0, a1; bool cvt;
    ldA(0, a0, a1, cvt);
    stA(sA, a0, a1, cvt);
#pragma unroll
    for (int p = 0; p < 4; p++) {
        int idx = tid + 512 * p;
        int kk = idx >> 6, n4 = (idx & 63) * 4;
        cpa16(&sB[kk * LDB + n4], &g_wout[(size_t)kk * FCN + n4]);
    }
    cp_commit(); cp_wait0(); __syncthreads();

    const int T = KOUT / 32;
    for (int kt = 0; kt < T; kt++) {
        const int bt = kt & 1, bn = bt ^ 1;
        float* cA = sA + bt * 128 * 36;
        float* cB = sB + bt * 32 * LDB;
        if (kt + 1 < T) {
            float* nB = sB + bn * 32 * LDB;
#pragma unroll
            for (int p = 0; p < 4; p++) {
                int idx = tid + 512 * p;
                int kk = idx >> 6, n4 = (idx & 63) * 4;
                cpa16(&nB[kk * LDB + n4], &g_wout[(size_t)((kt + 1) * 32 + kk) * FCN + n4]);
            }
            cp_commit();
            ldA(kt + 1, a0, a1, cvt);
        }
#pragma unroll
        for (int ks = 0; ks < 32; ks += 8) {
            unsigned a[2][4], b[8][2];
#pragma unroll
            for (int mt = 0; mt < 2; mt++) {
                int r = wm * 32 + mt * 16 + g;
                a[mt][0] = __float_as_uint(cA[r * 36 + ks + t]);
                a[mt][1] = __float_as_uint(cA[(r + 8) * 36 + ks + t]);
                a[mt][2] = __float_as_uint(cA[r * 36 + ks + t + 4]);
                a[mt][3] = __float_as_uint(cA[(r + 8) * 36 + ks + t + 4]);
            }
#pragma unroll
            for (int nt = 0; nt < 8; nt++) {
                int n = wn * 64 + nt * 8 + g;
                b[nt][0] = __float_as_uint(cB[(ks + t) * LDB + n]);
                b[nt][1] = __float_as_uint(cB[(ks + t + 4) * LDB + n]);
            }
#pragma unroll
            for (int mt = 0; mt < 2; mt++)
#pragma unroll
                for (int nt = 0; nt < 8; nt++) mma8(c[mt][nt], a[mt], b[nt]);
        }
        if (kt + 1 < T)
            stA(sA + bn * 128 * 36, a0, a1, cvt);
        cp_wait0(); __syncthreads();
    }

#pragma unroll
    for (int mt = 0; mt < 2; mt++)
#pragma unroll
        for (int h = 0; h < 2; h++) {
            int row = R0 + wm * 32 + mt * 16 + g + 8 * h;
#pragma unroll
            for (int nt = 0; nt < 8; nt++) {
                int col = wn * 64 + nt * 8 + 2 * t;
                float o0 = c[mt][nt][2 * h]     + __ldg(&bias[col]);
                float o1 = c[mt][nt][2 * h + 1] + __ldg(&bias[col + 1]);
                size_t off = (size_t)row * FCN + col;
                *(float2*)&out[off] = make_float2(o0, o1);
                if (dup) *(float2*)&out[(size_t)NR1 * FCN + off] = make_float2(o0, o1);
            }
        }
}

// ---------------------------------------------------------------------------
extern "C" void kernel_launch(void* const* d_in, const int* in_sizes, int n_in,
                              void* d_out, int out_size) {
    const float* x      = (const float*)d_in[0];
    const float* state  = (const float*)d_in[1];
    const float* enc_w  = (const float*)d_in[2];
    const float* enc_b  = (const float*)d_in[3];
    const float* enc_g  = (const float*)d_in[4];
    const float* enc_bb = (const float*)d_in[5];
    const float* core_w = (const float*)d_in[6];
    const float* core_b = (const float*)d_in[7];
    const float* core_g = (const float*)d_in[8];
    const float* core_bb= (const float*)d_in[9];
    const float* ctx_w  = (const float*)d_in[10];
    const float* ctx_b  = (const float*)d_in[11];
    const float* ctx_g  = (const float*)d_in[12];
    const float* ctx_bb = (const float*)d_in[13];
    const float* att1_w = (const float*)d_in[14];
    const float* att1_b = (const float*)d_in[15];
    const float* att_g  = (const float*)d_in[16];
    const float* att_bb = (const float*)d_in[17];
    const float* att2_w = (const float*)d_in[18];
    const float* att2_b = (const float*)d_in[19];
    const float* out_w  = (const float*)d_in[20];
    const float* out_b  = (const float*)d_in[21];
    float* out = (float*)d_out;
    int dup = (out_size >= 2 * NR1 * FCN) ? 1 : 0;

    const int smem_enc = (2 * 128 * 36 + 2 * 32 * LDB) * 4 + 4 * 128 * 8;
    const int smem_uv  = (2 * 64 * 36 + 2 * 32 * LDB2) * 4;
    const int smem_eff = 33792 + 33792 + 4 * 64 * 8 + 4 * 64 * 4 + 64 * 4 + 64 * 8;
    const int smem_out = (2 * 128 * 36 + 2 * 32 * LDB) * 4;

    static int attr_done = 0;
    if (!attr_done) {
        cudaFuncSetAttribute(k_enc, cudaFuncAttributeMaxDynamicSharedMemorySize, smem_enc);
        cudaFuncSetAttribute(k_uv,  cudaFuncAttributeMaxDynamicSharedMemorySize, smem_uv);
        cudaFuncSetAttribute(k_eff, cudaFuncAttributeMaxDynamicSharedMemorySize, smem_eff);
        cudaFuncSetAttribute(k_out, cudaFuncAttributeMaxDynamicSharedMemorySize, smem_out);
        attr_done = 1;
    }

    k_cvtw<<<256, 256>>>(enc_w, core_w, ctx_w, att1_w, out_w);
    k_enc<<<NR1 / 128, 512, smem_enc>>>(state, enc_b, enc_g, enc_bb);
    k_uv <<<NR1 / 64,  512, smem_uv >>>();
    k_eff<<<NR2 / 56,  256, smem_eff>>>(core_b, core_g, core_bb,
                                        ctx_b, ctx_g, ctx_bb,
                                        att1_b, att_g, att_bb,
                                        att2_w, att2_b);
    k_out<<<NR1 / 128, 512, smem_out>>>(x, out_b, out, dup);
}

// round 11
// speedup vs baseline: 9.1220x; 1.1580x over previous
#include <cuda_runtime.h>
#include <cuda_fp16.h>
#include <cstdint>
#include <math.h>

// ---------------------------------------------------------------------------
// R-NEM cell — full fp16 m16n8k16 pipeline (fp32 accumulate).
// R11: enc/uv/out ported to the k_eff recipe: 256-thr CTAs (2/SM), fragment-
//      packed B via direct LDG.128, packed-fp16 A in smem, minimal barriers.
//      k_uv keeps its whole A tile resident (barrier-free mainloop).
// core_pre[v] = U[p] + V[q] + core_b, [U|V] = s1 @ core_w (packed k-major)
// ---------------------------------------------------------------------------

#define FCN   256
#define LASTN 128
#define HDIM  512
#define MDIM  1024
#define NR1   16384
#define NR2   114688
#define KOUT  (2 * FCN + MDIM)

__device__ float g_s1[NR1 * FCN];
__device__ float g_uv[NR1 * 2 * FCN];
__device__ float g_eff[NR1 * FCN];

// fp16 fragment-packed weights: slot = (kt16 * (N/16) + n16) * 32 + lane
//   uint4 = {b0_lo, b1_lo, b0_hi, b1_hi} = two adjacent n8 fragments
__device__ __align__(16) uint4 g_wencp4[(HDIM / 16) * (FCN / 16) * 32];      // 256 KB
__device__ __align__(16) uint4 g_wuvp4 [(FCN / 16) * (2 * FCN / 16) * 32];   // 256 KB
__device__ __align__(16) uint4 g_woutp4[(KOUT / 16) * (FCN / 16) * 32];      // 768 KB
__device__ __align__(16) uint4 g_wattp4[(FCN / 16) * (LASTN / 16) * 32];     //  64 KB
__device__ __align__(16) uint4 g_wctxp4[(FCN / 16) * (FCN / 16) * 32];       // 128 KB

// -------------------------------- helpers ---------------------------------
__device__ __forceinline__ float to_tf32(float x) {
    unsigned u; asm("cvt.rna.tf32.f32 %0, %1;" : "=r"(u) : "f"(x));
    return __uint_as_float(u);
}
__device__ __forceinline__ void mma16(float* c, const unsigned* a, const unsigned* b) {
    asm volatile(
        "mma.sync.aligned.m16n8k16.row.col.f32.f16.f16.f32 "
        "{%0,%1,%2,%3}, {%4,%5,%6,%7}, {%8,%9}, {%0,%1,%2,%3};"
        : "+f"(c[0]), "+f"(c[1]), "+f"(c[2]), "+f"(c[3])
        : "r"(a[0]), "r"(a[1]), "r"(a[2]), "r"(a[3]), "r"(b[0]), "r"(b[1]));
}
__device__ __forceinline__ unsigned packh(float a, float b) {
    __half2 h = __floats2half2_rn(a, b);
    return *(unsigned*)&h;
}
__device__ __forceinline__ float tanh_ax(float x) {
    float y; asm("tanh.approx.f32 %0, %1;" : "=f"(y) : "f"(x)); return y;
}
__device__ __forceinline__ float sigmoid_ax(float x) {
    float e; asm("ex2.approx.f32 %0, %1;" : "=f"(e) : "f"(-x * 1.4426950408889634f));
    return 1.f / (1.f + e);
}
// Pack one float4 (row, col..col+3) into fragment-layout A buffer.
// Buffer = [mt(4)][kt(nkt)] blocks of 528 B; within block lane*16 holds a0..a3.
__device__ __forceinline__ void packA(char* buf, int nkt, int row, int col, float4 v) {
    int mt = row >> 4, hm = (row >> 3) & 1, gg = row & 7;
    int kt = col >> 4;
    int p0 = (col & 15) >> 1;          // 0,2,4,6
    char* blk = buf + (mt * nkt + kt) * 528;
    int tt0 = p0 & 3, hk0 = p0 >> 2;
    int p1 = p0 + 1, tt1 = p1 & 3, hk1 = p1 >> 2;
    *(unsigned*)(blk + ((gg << 2) + tt0) * 16 + (hk0 * 2 + hm) * 4) = packh(v.x, v.y);
    *(unsigned*)(blk + ((gg << 2) + tt1) * 16 + (hk1 * 2 + hm) * 4) = packh(v.z, v.w);
}

// ---------------------------------------------------------------------------
// Kernel 0: pack all weights into fp16 fragment layout
// ---------------------------------------------------------------------------
__global__ void k_cvtw(const float* __restrict__ enc_w, const float* __restrict__ core_w,
                       const float* __restrict__ ctx_w, const float* __restrict__ att1_w,
                       const float* __restrict__ out_w)
{
    int i = blockIdx.x * blockDim.x + threadIdx.x;
    int n = gridDim.x * blockDim.x;

    // enc_w: 512 x 256
    for (int idx = i; idx < (HDIM/16) * (FCN/16) * 32; idx += n) {
        int kt = idx / ((FCN/16) * 32);
        int rem = idx - kt * ((FCN/16) * 32);
        int n16 = rem >> 5, lane = rem & 31;
        int gg = lane >> 2, tt = lane & 3;
        int na = n16 * 16 + gg, nb = na + 8, k0 = kt * 16;
        g_wencp4[idx] = make_uint4(
            packh(enc_w[(k0+2*tt)*FCN+na],   enc_w[(k0+2*tt+1)*FCN+na]),
            packh(enc_w[(k0+8+2*tt)*FCN+na], enc_w[(k0+9+2*tt)*FCN+na]),
            packh(enc_w[(k0+2*tt)*FCN+nb],   enc_w[(k0+2*tt+1)*FCN+nb]),
            packh(enc_w[(k0+8+2*tt)*FCN+nb], enc_w[(k0+9+2*tt)*FCN+nb]));
    }
    // uv weight: logical [k(256)][c(512)] = [Wtop | Wbot] from core_w (512x256)
    for (int idx = i; idx < (FCN/16) * (2*FCN/16) * 32; idx += n) {
        int kt = idx / ((2*FCN/16) * 32);
        int rem = idx - kt * ((2*FCN/16) * 32);
        int n16 = rem >> 5, lane = rem & 31;
        int gg = lane >> 2, tt = lane & 3;
        int na = n16 * 16 + gg, nb = na + 8, k0 = kt * 16;
        #define GUV(k,c) ((c) < FCN ? core_w[(k)*FCN+(c)] : core_w[(FCN+(k))*FCN+((c)-FCN)])
        g_wuvp4[idx] = make_uint4(
            packh(GUV(k0+2*tt,na),   GUV(k0+2*tt+1,na)),
            packh(GUV(k0+8+2*tt,na), GUV(k0+9+2*tt,na)),
            packh(GUV(k0+2*tt,nb),   GUV(k0+2*tt+1,nb)),
            packh(GUV(k0+8+2*tt,nb), GUV(k0+9+2*tt,nb)));
        #undef GUV
    }
    // out_w: 1536 x 256
    for (int idx = i; idx < (KOUT/16) * (FCN/16) * 32; idx += n) {
        int kt = idx / ((FCN/16) * 32);
        int rem = idx - kt * ((FCN/16) * 32);
        int n16 = rem >> 5, lane = rem & 31;
        int gg = lane >> 2, tt = lane & 3;
        int na = n16 * 16 + gg, nb = na + 8, k0 = kt * 16;
        g_woutp4[idx] = make_uint4(
            packh(out_w[(k0+2*tt)*FCN+na],   out_w[(k0+2*tt+1)*FCN+na]),
            packh(out_w[(k0+8+2*tt)*FCN+na], out_w[(k0+9+2*tt)*FCN+na]),
            packh(out_w[(k0+2*tt)*FCN+nb],   out_w[(k0+2*tt+1)*FCN+nb]),
            packh(out_w[(k0+8+2*tt)*FCN+nb], out_w[(k0+9+2*tt)*FCN+nb]));
    }
    // att1_w: 256 x 128
    for (int idx = i; idx < (FCN/16) * (LASTN/16) * 32; idx += n) {
        int kt = idx / ((LASTN/16) * 32);
        int rem = idx - kt * ((LASTN/16) * 32);
        int n16 = rem >> 5, lane = rem & 31;
        int gg = lane >> 2, tt = lane & 3;
        int na = n16 * 16 + gg, nb = na + 8, k0 = kt * 16;
        g_wattp4[idx] = make_uint4(
            packh(att1_w[(k0+2*tt)*LASTN+na],   att1_w[(k0+2*tt+1)*LASTN+na]),
            packh(att1_w[(k0+8+2*tt)*LASTN+na], att1_w[(k0+9+2*tt)*LASTN+na]),
            packh(att1_w[(k0+2*tt)*LASTN+nb],   att1_w[(k0+2*tt+1)*LASTN+nb]),
            packh(att1_w[(k0+8+2*tt)*LASTN+nb], att1_w[(k0+9+2*tt)*LASTN+nb]));
    }
    // ctx_w: 256 x 256
    for (int idx = i; idx < (FCN/16) * (FCN/16) * 32; idx += n) {
        int kt = idx / ((FCN/16) * 32);
        int rem = idx - kt * ((FCN/16) * 32);
        int n16 = rem >> 5, lane = rem & 31;
        int gg = lane >> 2, tt = lane & 3;
        int na = n16 * 16 + gg, nb = na + 8, k0 = kt * 16;
        g_wctxp4[idx] = make_uint4(
            packh(ctx_w[(k0+2*tt)*FCN+na],   ctx_w[(k0+2*tt+1)*FCN+na]),
            packh(ctx_w[(k0+8+2*tt)*FCN+na], ctx_w[(k0+9+2*tt)*FCN+na]),
            packh(ctx_w[(k0+2*tt)*FCN+nb],   ctx_w[(k0+2*tt+1)*FCN+nb]),
            packh(ctx_w[(k0+8+2*tt)*FCN+nb], ctx_w[(k0+9+2*tt)*FCN+nb]));
    }
}

// ---------------------------------------------------------------------------
// Kernel 1 (fp16): s1 = relu(LN(state @ enc_w + enc_b))  M=16384 K=512 N=256
// 256 thr, 8 warps (2 row x 4 col), tile M=64. A double-buffered 32-k chunks.
// ---------------------------------------------------------------------------
__global__ __launch_bounds__(256, 2) void k_enc(
    const float* __restrict__ state, const float* __restrict__ bias,
    const float* __restrict__ gam, const float* __restrict__ bet)
{
    extern __shared__ float sm[];
    char*   sA  = (char*)sm;                 // 2 x 4224 B
    float2* red = (float2*)(sA + 2 * 4224);  // [4][64]

    const int tid = threadIdx.x;
    const int wid = tid >> 5, lane = tid & 31;
    const int g = lane >> 2, t = lane & 3;
    const int wm = wid & 1, wn = wid >> 1;
    const int R0 = blockIdx.x * 64;
    const int r0 = tid >> 3,         f0 = (tid & 7) * 4;
    const int r1 = (tid + 256) >> 3, f1 = ((tid + 256) & 7) * 4;

    float c[2][8][4];
#pragma unroll
    for (int mt = 0; mt < 2; mt++)
#pragma unroll
        for (int nt = 0; nt < 8; nt++)
#pragma unroll
            for (int e = 0; e < 4; e++) c[mt][nt][e] = 0.f;

    float4 a0 = *(const float4*)&state[(size_t)(R0 + r0) * HDIM + f0];
    float4 a1 = *(const float4*)&state[(size_t)(R0 + r1) * HDIM + f1];
    packA(sA, 2, r0, f0, a0);
    packA(sA, 2, r1, f1, a1);
    __syncthreads();

    const int T = HDIM / 32;   // 16 chunks
    for (int ch = 0; ch < T; ch++) {
        char* cur = sA + (ch & 1) * 4224;
        if (ch + 1 < T) {
            a0 = *(const float4*)&state[(size_t)(R0 + r0) * HDIM + (ch + 1) * 32 + f0];
            a1 = *(const float4*)&state[(size_t)(R0 + r1) * HDIM + (ch + 1) * 32 + f1];
        }
#pragma unroll
        for (int ktl = 0; ktl < 2; ktl++) {
            unsigned a[2][4];
#pragma unroll
            for (int mt = 0; mt < 2; mt++) {
                uint4 av = *(uint4*)(cur + ((wm * 2 + mt) * 2 + ktl) * 528 + lane * 16);
                a[mt][0] = av.x; a[mt][1] = av.y; a[mt][2] = av.z; a[mt][3] = av.w;
            }
            int ktg = ch * 2 + ktl;
#pragma unroll
            for (int nt2 = 0; nt2 < 4; nt2++) {
                uint4 bv = __ldg(&g_wencp4[(size_t)(ktg * 16 + wn * 4 + nt2) * 32 + lane]);
                unsigned bl[2] = {bv.x, bv.y}, bh[2] = {bv.z, bv.w};
                mma16(c[0][2*nt2],   a[0], bl);
                mma16(c[1][2*nt2],   a[1], bl);
                mma16(c[0][2*nt2+1], a[0], bh);
                mma16(c[1][2*nt2+1], a[1], bh);
            }
        }
        if (ch + 1 < T) {
            char* nxt = sA + ((ch + 1) & 1) * 4224;
            packA(nxt, 2, r0, f0, a0);
            packA(nxt, 2, r1, f1, a1);
        }
        __syncthreads();
    }

    // epilogue: bias + LN + relu
#pragma unroll
    for (int nt = 0; nt < 8; nt++) {
        int col = wn * 64 + nt * 8 + 2 * t;
        float b0 = __ldg(&bias[col]), b1 = __ldg(&bias[col + 1]);
#pragma unroll
        for (int mt = 0; mt < 2; mt++) {
            c[mt][nt][0] += b0; c[mt][nt][1] += b1;
            c[mt][nt][2] += b0; c[mt][nt][3] += b1;
        }
    }
#pragma unroll
    for (int mt = 0; mt < 2; mt++) {
        float s0 = 0, q0 = 0, s1v = 0, q1 = 0;
#pragma unroll
        for (int nt = 0; nt < 8; nt++) {
            s0 += c[mt][nt][0] + c[mt][nt][1];
            q0 += c[mt][nt][0] * c[mt][nt][0] + c[mt][nt][1] * c[mt][nt][1];
            s1v += c[mt][nt][2] + c[mt][nt][3];
            q1 += c[mt][nt][2] * c[mt][nt][2] + c[mt][nt][3] * c[mt][nt][3];
        }
#pragma unroll
        for (int o = 1; o <= 2; o <<= 1) {
            s0 += __shfl_xor_sync(~0u, s0, o); q0 += __shfl_xor_sync(~0u, q0, o);
            s1v += __shfl_xor_sync(~0u, s1v, o); q1 += __shfl_xor_sync(~0u, q1, o);
        }
        if (t == 0) {
            red[wn * 64 + wm * 32 + mt * 16 + g]     = make_float2(s0, q0);
            red[wn * 64 + wm * 32 + mt * 16 + g + 8] = make_float2(s1v, q1);
        }
    }
    __syncthreads();
#pragma unroll
    for (int mt = 0; mt < 2; mt++)
#pragma unroll
        for (int h = 0; h < 2; h++) {
            int row = wm * 32 + mt * 16 + g + 8 * h;
            float s = 0, q = 0;
#pragma unroll
            for (int w2 = 0; w2 < 4; w2++) {
                float2 r2 = red[w2 * 64 + row]; s += r2.x; q += r2.y;
            }
            float mu = s * (1.f / FCN);
            float rs = rsqrtf(q * (1.f / FCN) - mu * mu + 1e-5f);
#pragma unroll
            for (int nt = 0; nt < 8; nt++) {
                int col = wn * 64 + nt * 8 + 2 * t;
                float o0 = fmaxf((c[mt][nt][2*h]   - mu) * rs * __ldg(&gam[col])   + __ldg(&bet[col]),   0.f);
                float o1 = fmaxf((c[mt][nt][2*h+1] - mu) * rs * __ldg(&gam[col+1]) + __ldg(&bet[col+1]), 0.f);
                *(float2*)&g_s1[(size_t)(R0 + row) * FCN + col] = make_float2(o0, o1);
            }
        }
}

// ---------------------------------------------------------------------------
// Kernel 2 (fp16): [U|V] = s1 @ packed(core_w)   M=16384 K=256 N=512
// Whole 64x256 A tile resident in smem (33792 B) -> barrier-free mainloop.
// N processed as two 256-wide halves (64 live accumulators each).
// ---------------------------------------------------------------------------
__global__ __launch_bounds__(256, 2) void k_uv()
{
    extern __shared__ float sm[];
    char* sA = (char*)sm;   // 4 mt x 16 kt x 528 = 33792 B

    const int tid = threadIdx.x;
    const int wid = tid >> 5, lane = tid & 31;
    const int g = lane >> 2, t = lane & 3;
    const int wm = wid & 1, wn = wid >> 1;
    const int R0 = blockIdx.x * 64;

    // stage whole A tile
#pragma unroll
    for (int i = 0; i < 16; i++) {
        int idx = tid + 256 * i;
        int row = idx >> 6, f = (idx & 63) * 4;
        float4 v = *(const float4*)&g_s1[(size_t)(R0 + row) * FCN + f];
        packA(sA, 16, row, f, v);
    }
    __syncthreads();

    for (int half = 0; half < 2; half++) {
        float c[2][8][4];
#pragma unroll
        for (int mt = 0; mt < 2; mt++)
#pragma unroll
            for (int nt = 0; nt < 8; nt++)
#pragma unroll
                for (int e = 0; e < 4; e++) c[mt][nt][e] = 0.f;

#pragma unroll 4
        for (int kt = 0; kt < 16; kt++) {
            unsigned a[2][4];
#pragma unroll
            for (int mt = 0; mt < 2; mt++) {
                uint4 av = *(uint4*)(sA + ((wm * 2 + mt) * 16 + kt) * 528 + lane * 16);
                a[mt][0] = av.x; a[mt][1] = av.y; a[mt][2] = av.z; a[mt][3] = av.w;
            }
#pragma unroll
            for (int nt2 = 0; nt2 < 4; nt2++) {
                uint4 bv = __ldg(&g_wuvp4[(size_t)(kt * 32 + half * 16 + wn * 4 + nt2) * 32 + lane]);
                unsigned bl[2] = {bv.x, bv.y}, bh[2] = {bv.z, bv.w};
                mma16(c[0][2*nt2],   a[0], bl);
                mma16(c[1][2*nt2],   a[1], bl);
                mma16(c[0][2*nt2+1], a[0], bh);
                mma16(c[1][2*nt2+1], a[1], bh);
            }
        }
#pragma unroll
        for (int mt = 0; mt < 2; mt++)
#pragma unroll
            for (int h = 0; h < 2; h++) {
                int row = R0 + wm * 32 + mt * 16 + g + 8 * h;
#pragma unroll
                for (int nt = 0; nt < 8; nt++) {
                    int col = half * 256 + wn * 64 + nt * 8 + 2 * t;
                    *(float2*)&g_uv[(size_t)row * 512 + col] =
                        make_float2(c[mt][nt][2*h], c[mt][nt][2*h+1]);
                }
            }
    }
}

// ---------------------------------------------------------------------------
// Kernel 3 (fp16): k_eff — unchanged from R10 (101 us winner).
// ---------------------------------------------------------------------------
__global__ __launch_bounds__(256, 3) void k_eff(
    const float* __restrict__ core_b, const float* __restrict__ core_g,
    const float* __restrict__ core_bb,
    const float* __restrict__ ctx_b,
    const float* __restrict__ ctx_g, const float* __restrict__ ctx_bb,
    const float* __restrict__ a1_b,
    const float* __restrict__ att_g, const float* __restrict__ att_bb,
    const float* __restrict__ a2W,  const float* __restrict__ a2_b)
{
    extern __shared__ float sm[];
    char*     sAp   = (char*)sm;                     // 4*16*528 = 33792 B
    unsigned* sCtx2 = (unsigned*)(sAp + 33792);      // [64][132] half2 = 33792 B
    float2*   sRed  = (float2*)(sCtx2 + 64 * 132);   // [4][64]
    float*    sDot  = (float*)(sRed + 4 * 64);       // [4][64]
    float*    sAtt  = sDot + 4 * 64;                 // [64]
    float2*   sMu   = (float2*)(sAtt + 64);          // [64]

    const int tid = threadIdx.x;
    const int wid = tid >> 5, lane = tid & 31;
    const int g = lane >> 2, t = lane & 3;
    const int wm = wid & 1, wn = wid >> 1;
    const int R0 = blockIdx.x * 56;
    const int NKT = FCN / 16;

    {
        float* z = (float*)(sAp + 3 * 16 * 528);
        for (int i = tid; i < 16 * 528 / 4; i += 256) z[i] = 0.f;
    }
    __syncthreads();

    // ---- phase a: core rows -> packed fp16 sA (rows 0..55) ----
    {
#pragma unroll
        for (int rr = 0; rr < 7; rr++) {
            int lrow = wid * 7 + rr;
            int v = R0 + lrow;
            int p = v / 7;
            int jj = v - p * 7;
            int i = p & 7;
            int j = jj + (jj >= i ? 1 : 0);
            int q = (p & ~7) + j;
            float2 val[4];
            float s = 0.f, s2 = 0.f;
#pragma unroll
            for (int e = 0; e < 4; e++) {
                int col = 2 * lane + 64 * e;
                float2 u  = *(const float2*)&g_uv[(size_t)p * 512 + col];
                float2 vq = *(const float2*)&g_uv[(size_t)q * 512 + 256 + col];
                float2 cb = *(const float2*)&core_b[col];
                val[e].x = u.x + vq.x + cb.x;
                val[e].y = u.y + vq.y + cb.y;
                s += val[e].x + val[e].y;
                s2 += val[e].x * val[e].x + val[e].y * val[e].y;
            }
#pragma unroll
            for (int o = 16; o; o >>= 1) {
                s  += __shfl_xor_sync(~0u, s,  o);
                s2 += __shfl_xor_sync(~0u, s2, o);
            }
            float mu = s * (1.f / FCN);
            float rs = rsqrtf(s2 * (1.f / FCN) - mu * mu + 1e-5f);
            int mtile = lrow >> 4, gg = lrow & 7, hm = (lrow >> 3) & 1;
            int tt = lane & 3, hk = (lane >> 2) & 1;
#pragma unroll
            for (int e = 0; e < 4; e++) {
                int col = 2 * lane + 64 * e;
                float2 cg = *(const float2*)&core_g[col];
                float2 cbb = *(const float2*)&core_bb[col];
                float o0 = fmaxf((val[e].x - mu) * rs * cg.x + cbb.x, 0.f);
                float o1 = fmaxf((val[e].y - mu) * rs * cg.y + cbb.y, 0.f);
                int kt = (lane >> 3) + 4 * e;
                unsigned off = (unsigned)((mtile * 16 + kt) * 528
                                          + ((gg << 2) + tt) * 16 + (hk * 2 + hm) * 4);
                *(unsigned*)(sAp + off) = packh(o0, o1);
            }
        }
    }
    __syncthreads();

    // ---- pass 1: attention ----
    {
        float ca[2][4][4];
#pragma unroll
        for (int mt = 0; mt < 2; mt++)
#pragma unroll
            for (int nt = 0; nt < 4; nt++)
#pragma unroll
                for (int e = 0; e < 4; e++) ca[mt][nt][e] = 0.f;

#pragma unroll
        for (int kt = 0; kt < NKT; kt++) {
            unsigned a[2][4];
#pragma unroll
            for (int mt = 0; mt < 2; mt++) {
                uint4 av = *(uint4*)(sAp + ((wm * 2 + mt) * 16 + kt) * 528 + lane * 16);
                a[mt][0] = av.x; a[mt][1] = av.y; a[mt][2] = av.z; a[mt][3] = av.w;
            }
#pragma unroll
            for (int nt2 = 0; nt2 < 2; nt2++) {
                uint4 bv = __ldg(&g_wattp4[(size_t)(kt * 8 + wn * 2 + nt2) * 32 + lane]);
                unsigned bl[2] = {bv.x, bv.y}, bh[2] = {bv.z, bv.w};
                mma16(ca[0][2*nt2],   a[0], bl);
                mma16(ca[1][2*nt2],   a[1], bl);
                mma16(ca[0][2*nt2+1], a[0], bh);
                mma16(ca[1][2*nt2+1], a[1], bh);
            }
        }
#pragma unroll
        for (int nt = 0; nt < 4; nt++) {
            int col = wn * 32 + nt * 8 + 2 * t;
            float b0 = __ldg(&a1_b[col]), b1 = __ldg(&a1_b[col + 1]);
#pragma unroll
            for (int mt = 0; mt < 2; mt++) {
                ca[mt][nt][0] += b0; ca[mt][nt][1] += b1;
                ca[mt][nt][2] += b0; ca[mt][nt][3] += b1;
            }
        }
#pragma unroll
        for (int mt = 0; mt < 2; mt++) {
            float s0 = 0, q0 = 0, s1v = 0, q1 = 0;
#pragma unroll
            for (int nt = 0; nt < 4; nt++) {
                s0 += ca[mt][nt][0] + ca[mt][nt][1];
                q0 += ca[mt][nt][0] * ca[mt][nt][0] + ca[mt][nt][1] * ca[mt][nt][1];
                s1v += ca[mt][nt][2] + ca[mt][nt][3];
                q1 += ca[mt][nt][2] * ca[mt][nt][2] + ca[mt][nt][3] * ca[mt][nt][3];
            }
#pragma unroll
            for (int o = 1; o <= 2; o <<= 1) {
                s0 += __shfl_xor_sync(~0u, s0, o); q0 += __shfl_xor_sync(~0u, q0, o);
                s1v += __shfl_xor_sync(~0u, s1v, o); q1 += __shfl_xor_sync(~0u, q1, o);
            }
            if (t == 0) {
                sRed[wn * 64 + wm * 32 + mt * 16 + g]     = make_float2(s0, q0);
                sRed[wn * 64 + wm * 32 + mt * 16 + g + 8] = make_float2(s1v, q1);
            }
        }
        __syncthreads();
#pragma unroll
        for (int mt = 0; mt < 2; mt++)
#pragma unroll
            for (int h = 0; h < 2; h++) {
                int row = wm * 32 + mt * 16 + g + 8 * h;
                float s = 0, q = 0;
#pragma unroll
                for (int w2 = 0; w2 < 4; w2++) {
                    float2 r2 = sRed[w2 * 64 + row]; s += r2.x; q += r2.y;
                }
                float mu = s * (1.f / LASTN);
                float rs = rsqrtf(q * (1.f / LASTN) - mu * mu + 1e-5f);
                float d = 0.f;
#pragma unroll
                for (int nt = 0; nt < 4; nt++) {
                    int col = wn * 32 + nt * 8 + 2 * t;
                    float gg0 = __ldg(&att_g[col]),   bb0 = __ldg(&att_bb[col]),   w0 = __ldg(&a2W[col]);
                    float gg1 = __ldg(&att_g[col+1]), bb1 = __ldg(&att_bb[col+1]), w1 = __ldg(&a2W[col+1]);
                    d += tanh_ax((ca[mt][nt][2*h]   - mu) * rs * gg0 + bb0) * w0;
                    d += tanh_ax((ca[mt][nt][2*h+1] - mu) * rs * gg1 + bb1) * w1;
                }
#pragma unroll
                for (int o = 1; o <= 2; o <<= 1) d += __shfl_xor_sync(~0u, d, o);
                if (t == 0) sDot[wn * 64 + row] = d;
            }
        __syncthreads();
        if (wid < 2) {
            int row = wid * 32 + lane;
            float a2b = __ldg(&a2_b[0]);
            float d = sDot[row] + sDot[64 + row] + sDot[128 + row] + sDot[192 + row];
            sAtt[row] = sigmoid_ax(d + a2b);
        }
        __syncthreads();
    }

    // ---- pass 2: ctx in two N=128 halves; raw -> fp16 buffer ----
    for (int half = 0; half < 2; half++) {
        float cc[2][4][4];
#pragma unroll
        for (int mt = 0; mt < 2; mt++)
#pragma unroll
            for (int nt = 0; nt < 4; nt++)
#pragma unroll
                for (int e = 0; e < 4; e++) cc[mt][nt][e] = 0.f;

#pragma unroll
        for (int kt = 0; kt < NKT; kt++) {
            unsigned a[2][4];
#pragma unroll
            for (int mt = 0; mt < 2; mt++) {
                uint4 av = *(uint4*)(sAp + ((wm * 2 + mt) * 16 + kt) * 528 + lane * 16);
                a[mt][0] = av.x; a[mt][1] = av.y; a[mt][2] = av.z; a[mt][3] = av.w;
            }
#pragma unroll
            for (int nt2 = 0; nt2 < 2; nt2++) {
                uint4 bv = __ldg(&g_wctxp4[(size_t)(kt * 16 + half * 8 + wn * 2 + nt2) * 32 + lane]);
                unsigned bl[2] = {bv.x, bv.y}, bh[2] = {bv.z, bv.w};
                mma16(cc[0][2*nt2],   a[0], bl);
                mma16(cc[1][2*nt2],   a[1], bl);
                mma16(cc[0][2*nt2+1], a[0], bh);
                mma16(cc[1][2*nt2+1], a[1], bh);
            }
        }
#pragma unroll
        for (int mt = 0; mt < 2; mt++)
#pragma unroll
            for (int nt = 0; nt < 4; nt++) {
                int col = half * 128 + wn * 32 + nt * 8 + 2 * t;
                float b0 = __ldg(&ctx_b[col]), b1 = __ldg(&ctx_b[col + 1]);
                int r0 = wm * 32 + mt * 16 + g;
                int ci = col >> 1;
                sCtx2[r0 * 132 + ci]       = packh(cc[mt][nt][0] + b0, cc[mt][nt][1] + b1);
                sCtx2[(r0 + 8) * 132 + ci] = packh(cc[mt][nt][2] + b0, cc[mt][nt][3] + b1);
            }
    }
    __syncthreads();

    // ---- exact LN stats from buffer ----
    {
        int r = tid >> 2, b = tid & 3;
        float s = 0.f, q = 0.f;
        if (r < 56) {
#pragma unroll
            for (int j = 0; j < 32; j++) {
                __half2 h = *(__half2*)&sCtx2[r * 132 + b + 4 * j];
                float2 f = __half22float2(h);
                s += f.x + f.y; q += f.x * f.x + f.y * f.y;
            }
        }
        s += __shfl_xor_sync(~0u, s, 1); q += __shfl_xor_sync(~0u, q, 1);
        s += __shfl_xor_sync(~0u, s, 2); q += __shfl_xor_sync(~0u, q, 2);
        if (b == 0 && r < 56) {
            float mu = s * (1.f / FCN);
            float rs = rsqrtf(q * (1.f / FCN) - mu * mu + 1e-5f);
            sMu[r] = make_float2(mu, rs);
        }
    }
    __syncthreads();

    // ---- effect gather ----
    for (int s0 = tid; s0 < 8 * 128; s0 += 256) {
        int gg = s0 >> 7, c2 = s0 & 127;
        float2 gm = __ldg((const float2*)&ctx_g[2 * c2]);
        float2 bb = __ldg((const float2*)&ctx_bb[2 * c2]);
        float e0 = 0.f, e1 = 0.f;
        int rb = gg * 7;
#pragma unroll
        for (int rr = 0; rr < 7; rr++) {
            int r = rb + rr;
            float2 mr = sMu[r];
            float at = sAtt[r];
            float2 f = __half22float2(*(__half2*)&sCtx2[r * 132 + c2]);
            e0 += fmaxf((f.x - mr.x) * mr.y * gm.x + bb.x, 0.f) * at;
            e1 += fmaxf((f.y - mr.x) * mr.y * gm.y + bb.y, 0.f) * at;
        }
        *(float2*)&g_eff[(size_t)(blockIdx.x * 8 + gg) * FCN + 2 * c2] =
            make_float2(to_tf32(e0), to_tf32(e1));
    }
}

// ---------------------------------------------------------------------------
// Kernel 4 (fp16): new_state = concat(s1, effect, x) @ out_w + out_b
// M=16384 K=1536 N=256, tile M=64, A double-buffered 32-k chunks.
// ---------------------------------------------------------------------------
__global__ __launch_bounds__(256, 2) void k_out(
    const float* __restrict__ xin, const float* __restrict__ bias,
    float* __restrict__ out, int dup)
{
    extern __shared__ float sm[];
    char* sA = (char*)sm;   // 2 x 4224 B

    const int tid = threadIdx.x;
    const int wid = tid >> 5, lane = tid & 31;
    const int g = lane >> 2, t = lane & 3;
    const int wm = wid & 1, wn = wid >> 1;
    const int R0 = blockIdx.x * 64;
    const int r0 = tid >> 3,         f0 = (tid & 7) * 4;
    const int r1 = (tid + 256) >> 3, f1 = ((tid + 256) & 7) * 4;

    float c[2][8][4];
#pragma unroll
    for (int mt = 0; mt < 2; mt++)
#pragma unroll
        for (int nt = 0; nt < 8; nt++)
#pragma unroll
            for (int e = 0; e < 4; e++) c[mt][nt][e] = 0.f;

    auto ldA = [&](int ch, float4& v0, float4& v1) {
        int base = ch * 32;
        if (base < FCN) {
            v0 = *(const float4*)&g_s1[(size_t)(R0 + r0) * FCN + base + f0];
            v1 = *(const float4*)&g_s1[(size_t)(R0 + r1) * FCN + base + f1];
        } else if (base < 2 * FCN) {
            v0 = *(const float4*)&g_eff[(size_t)(R0 + r0) * FCN + base - FCN + f0];
            v1 = *(const float4*)&g_eff[(size_t)(R0 + r1) * FCN + base - FCN + f1];
        } else {
            v0 = *(const float4*)&xin[(size_t)(R0 + r0) * MDIM + base - 2 * FCN + f0];
            v1 = *(const float4*)&xin[(size_t)(R0 + r1) * MDIM + base - 2 * FCN + f1];
        }
    };

    float4 a0, a1;
    ldA(0, a0, a1);
    packA(sA, 2, r0, f0, a0);
    packA(sA, 2, r1, f1, a1);
    __syncthreads();

    const int T = KOUT / 32;   // 48 chunks
    for (int ch = 0; ch < T; ch++) {
        char* cur = sA + (ch & 1) * 4224;
        if (ch + 1 < T) ldA(ch + 1, a0, a1);
#pragma unroll
        for (int ktl = 0; ktl < 2; ktl++) {
            unsigned a[2][4];
#pragma unroll
            for (int mt = 0; mt < 2; mt++) {
                uint4 av = *(uint4*)(cur + ((wm * 2 + mt) * 2 + ktl) * 528 + lane * 16);
                a[mt][0] = av.x; a[mt][1] = av.y; a[mt][2] = av.z; a[mt][3] = av.w;
            }
            int ktg = ch * 2 + ktl;
#pragma unroll
            for (int nt2 = 0; nt2 < 4; nt2++) {
                uint4 bv = __ldg(&g_woutp4[(size_t)(ktg * 16 + wn * 4 + nt2) * 32 + lane]);
                unsigned bl[2] = {bv.x, bv.y}, bh[2] = {bv.z, bv.w};
                mma16(c[0][2*nt2],   a[0], bl);
                mma16(c[1][2*nt2],   a[1], bl);
                mma16(c[0][2*nt2+1], a[0], bh);
                mma16(c[1][2*nt2+1], a[1], bh);
            }
        }
        if (ch + 1 < T) {
            char* nxt = sA + ((ch + 1) & 1) * 4224;
            packA(nxt, 2, r0, f0, a0);
            packA(nxt, 2, r1, f1, a1);
        }
        __syncthreads();
    }

#pragma unroll
    for (int mt = 0; mt < 2; mt++)
#pragma unroll
        for (int h = 0; h < 2; h++) {
            int row = R0 + wm * 32 + mt * 16 + g + 8 * h;
#pragma unroll
            for (int nt = 0; nt < 8; nt++) {
                int col = wn * 64 + nt * 8 + 2 * t;
                float o0 = c[mt][nt][2*h]   + __ldg(&bias[col]);
                float o1 = c[mt][nt][2*h+1] + __ldg(&bias[col + 1]);
                size_t off = (size_t)row * FCN + col;
                *(float2*)&out[off] = make_float2(o0, o1);
                if (dup) *(float2*)&out[(size_t)NR1 * FCN + off] = make_float2(o0, o1);
            }
        }
}

// ---------------------------------------------------------------------------
extern "C" void kernel_launch(void* const* d_in, const int* in_sizes, int n_in,
                              void* d_out, int out_size) {
    const float* x      = (const float*)d_in[0];
    const float* state  = (const float*)d_in[1];
    const float* enc_w  = (const float*)d_in[2];
    const float* enc_b  = (const float*)d_in[3];
    const float* enc_g  = (const float*)d_in[4];
    const float* enc_bb = (const float*)d_in[5];
    const float* core_w = (const float*)d_in[6];
    const float* core_b = (const float*)d_in[7];
    const float* core_g = (const float*)d_in[8];
    const float* core_bb= (const float*)d_in[9];
    const float* ctx_w  = (const float*)d_in[10];
    const float* ctx_b  = (const float*)d_in[11];
    const float* ctx_g  = (const float*)d_in[12];
    const float* ctx_bb = (const float*)d_in[13];
    const float* att1_w = (const float*)d_in[14];
    const float* att1_b = (const float*)d_in[15];
    const float* att_g  = (const float*)d_in[16];
    const float* att_bb = (const float*)d_in[17];
    const float* att2_w = (const float*)d_in[18];
    const float* att2_b = (const float*)d_in[19];
    const float* out_w  = (const float*)d_in[20];
    const float* out_b  = (const float*)d_in[21];
    float* out = (float*)d_out;
    int dup = (out_size >= 2 * NR1 * FCN) ? 1 : 0;

    const int smem_enc = 2 * 4224 + 4 * 64 * 8;
    const int smem_uv  = 33792;
    const int smem_eff = 33792 + 33792 + 4 * 64 * 8 + 4 * 64 * 4 + 64 * 4 + 64 * 8;
    const int smem_out = 2 * 4224;

    static int attr_done = 0;
    if (!attr_done) {
        cudaFuncSetAttribute(k_enc, cudaFuncAttributeMaxDynamicSharedMemorySize, smem_enc);
        cudaFuncSetAttribute(k_uv,  cudaFuncAttributeMaxDynamicSharedMemorySize, smem_uv);
        cudaFuncSetAttribute(k_eff, cudaFuncAttributeMaxDynamicSharedMemorySize, smem_eff);
        cudaFuncSetAttribute(k_out, cudaFuncAttributeMaxDynamicSharedMemorySize, smem_out);
        attr_done = 1;
    }

    k_cvtw<<<256, 256>>>(enc_w, core_w, ctx_w, att1_w, out_w);
    k_enc<<<NR1 / 64, 256, smem_enc>>>(state, enc_b, enc_g, enc_bb);
    k_uv <<<NR1 / 64, 256, smem_uv >>>();
    k_eff<<<NR2 / 56, 256, smem_eff>>>(core_b, core_g, core_bb,
                                       ctx_b, ctx_g, ctx_bb,
                                       att1_b, att_g, att_bb,
                                       att2_w, att2_b);
    k_out<<<NR1 / 64, 256, smem_out>>>(x, out_b, out, dup);
}